// round 2
// baseline (speedup 1.0000x reference)
#include <cuda_runtime.h>
#include <math.h>

// Problem constants (fixed shapes)
#define B_   16
#define C_   256
#define H_   32
#define W_   32
#define N_   1024           // H*W
#define NH_  4
#define KD_  32             // head key dim
#define HD_  64             // head value dim
#define CQKV 512            // C + 2*kd*NH
#define HID  512            // 2*C / 2 ... hid = 2*C = 512
#define C2   1024           // 2*hid
#define P_   8

// ---------------- static scratch (no allocations allowed) ----------------
__device__ float g_qkv   [(size_t)B_*CQKV*N_];        // 32MB
__device__ float g_attn  [(size_t)B_*NH_*N_*N_];      // 256MB
__device__ float g_attout[(size_t)B_*C_*N_];          // 16MB (att out + pe)
__device__ float g_xnew  [(size_t)B_*C_*N_];          // 16MB
__device__ float g_pin   [(size_t)B_*C2*N_];          // 64MB
__device__ float g_dw    [(size_t)B_*C2*N_];          // 64MB
__device__ float g_hid   [(size_t)B_*HID*N_];         // 32MB
__device__ float g_yout  [(size_t)B_*C_*N_];          // 16MB
__device__ float g_g     [C_*64];                     // circ-conv kernels

// ---------------- generic conv1x1 GEMM: out[b,o,n] = sum_c W[o,c] in[b,c,n]
// optional per-o affine (scale,bias) and residual add.
// BM=BN=64, BK=16, 256 threads, 4x4 micro-tile
__global__ void gemm1x1_kernel(const float* __restrict__ in,
                               const float* __restrict__ w,
                               const float* __restrict__ scale,
                               const float* __restrict__ bias,
                               const float* __restrict__ residual,
                               float* __restrict__ out,
                               int Cin, int Cout, int N)
{
    __shared__ float Ws[16][65];   // [k][o]
    __shared__ float Is[16][64];   // [k][n]
    const int b  = blockIdx.z;
    const int o0 = blockIdx.y * 64;
    const int n0 = blockIdx.x * 64;
    const int tid = threadIdx.x;
    const int tx = tid & 15;
    const int ty = tid >> 4;

    const float* inb = in + (size_t)b * Cin * N;
    float acc[4][4];
#pragma unroll
    for (int i = 0; i < 4; i++)
#pragma unroll
        for (int j = 0; j < 4; j++) acc[i][j] = 0.f;

    for (int k0 = 0; k0 < Cin; k0 += 16) {
        // load W tile (64 o x 16 c), coalesced along c
#pragma unroll
        for (int l = tid; l < 1024; l += 256) {
            int cc = l & 15, oo = l >> 4;
            Ws[cc][oo] = w[(size_t)(o0 + oo) * Cin + k0 + cc];
        }
        // load input tile (16 c x 64 n), coalesced along n
#pragma unroll
        for (int l = tid; l < 1024; l += 256) {
            int nn = l & 63, kk = l >> 6;
            Is[kk][nn] = inb[(size_t)(k0 + kk) * N + n0 + nn];
        }
        __syncthreads();
#pragma unroll
        for (int k = 0; k < 16; k++) {
            float ra[4], rb[4];
#pragma unroll
            for (int i = 0; i < 4; i++) ra[i] = Ws[k][ty * 4 + i];
#pragma unroll
            for (int j = 0; j < 4; j++) rb[j] = Is[k][tx * 4 + j];
#pragma unroll
            for (int i = 0; i < 4; i++)
#pragma unroll
                for (int j = 0; j < 4; j++) acc[i][j] += ra[i] * rb[j];
        }
        __syncthreads();
    }

#pragma unroll
    for (int i = 0; i < 4; i++) {
        int o = o0 + ty * 4 + i;
        float sc = scale ? scale[o] : 1.f;
        float bi = scale ? bias[o]  : 0.f;
#pragma unroll
        for (int j = 0; j < 4; j++) {
            int n = n0 + tx * 4 + j;
            float v = acc[i][j] * sc + bi;
            size_t oi = ((size_t)b * Cout + o) * N + n;
            if (residual) v += residual[oi];
            out[oi] = v;
        }
    }
}

// ---------------- attention S = Q^T K * scale --------------------------
__global__ void attn_qk_kernel(const float* __restrict__ qkv,
                               float* __restrict__ attn, float scale)
{
    __shared__ float Qs[16][64];
    __shared__ float Ks[16][64];
    const int bh = blockIdx.z;
    const int b = bh / NH_, h = bh % NH_;
    const int n0 = blockIdx.y * 64;
    const int m0 = blockIdx.x * 64;
    const int tid = threadIdx.x;
    const int tx = tid & 15, ty = tid >> 4;

    const float* qb = qkv + ((size_t)b * CQKV + h * 128) * N_;
    const float* kb = qb + (size_t)KD_ * N_;

    float acc[4][4];
#pragma unroll
    for (int i = 0; i < 4; i++)
#pragma unroll
        for (int j = 0; j < 4; j++) acc[i][j] = 0.f;

    for (int d0 = 0; d0 < KD_; d0 += 16) {
#pragma unroll
        for (int l = tid; l < 1024; l += 256) {
            int nn = l & 63, dd = l >> 6;
            Qs[dd][nn] = qb[(size_t)(d0 + dd) * N_ + n0 + nn];
            Ks[dd][nn] = kb[(size_t)(d0 + dd) * N_ + m0 + nn];
        }
        __syncthreads();
#pragma unroll
        for (int k = 0; k < 16; k++) {
            float ra[4], rb[4];
#pragma unroll
            for (int i = 0; i < 4; i++) ra[i] = Qs[k][ty * 4 + i];
#pragma unroll
            for (int j = 0; j < 4; j++) rb[j] = Ks[k][tx * 4 + j];
#pragma unroll
            for (int i = 0; i < 4; i++)
#pragma unroll
                for (int j = 0; j < 4; j++) acc[i][j] += ra[i] * rb[j];
        }
        __syncthreads();
    }
#pragma unroll
    for (int i = 0; i < 4; i++) {
        int n = n0 + ty * 4 + i;
#pragma unroll
        for (int j = 0; j < 4; j++) {
            int m = m0 + tx * 4 + j;
            attn[((size_t)bh * N_ + n) * N_ + m] = acc[i][j] * scale;
        }
    }
}

// ---------------- row softmax ------------------------------------------
__global__ void softmax_kernel(float* __restrict__ attn)
{
    __shared__ float red[256];
    const size_t row = blockIdx.x;
    float* p = attn + row * N_;
    const int tid = threadIdx.x;

    float m = -1e30f;
    for (int i = tid; i < N_; i += 256) m = fmaxf(m, p[i]);
    red[tid] = m; __syncthreads();
    for (int s = 128; s > 0; s >>= 1) { if (tid < s) red[tid] = fmaxf(red[tid], red[tid + s]); __syncthreads(); }
    m = red[0]; __syncthreads();

    float sum = 0.f;
    for (int i = tid; i < N_; i += 256) { float e = expf(p[i] - m); p[i] = e; sum += e; }
    red[tid] = sum; __syncthreads();
    for (int s = 128; s > 0; s >>= 1) { if (tid < s) red[tid] += red[tid + s]; __syncthreads(); }
    float inv = 1.f / red[0];
    for (int i = tid; i < N_; i += 256) p[i] *= inv;
}

// ---------------- out = V @ attn^T  -------------------------------------
__global__ void attn_pv_kernel(const float* __restrict__ qkv,
                               const float* __restrict__ attn,
                               float* __restrict__ out)
{
    __shared__ float Vs[16][65];
    __shared__ float Ss[16][65];
    const int bh = blockIdx.z;
    const int b = bh / NH_, h = bh % NH_;
    const int n0 = blockIdx.x * 64;
    const int tid = threadIdx.x;
    const int tx = tid & 15, ty = tid >> 4;

    const float* vb = qkv + ((size_t)b * CQKV + h * 128 + 2 * KD_) * N_;
    const float* sb = attn + (size_t)bh * N_ * N_;

    float acc[4][4];
#pragma unroll
    for (int i = 0; i < 4; i++)
#pragma unroll
        for (int j = 0; j < 4; j++) acc[i][j] = 0.f;

    for (int m0 = 0; m0 < N_; m0 += 16) {
#pragma unroll
        for (int l = tid; l < 1024; l += 256) {
            int mm = l & 15, rr = l >> 4;
            Vs[mm][rr] = vb[(size_t)rr * N_ + m0 + mm];         // d = rr
            Ss[mm][rr] = sb[(size_t)(n0 + rr) * N_ + m0 + mm];  // n = rr
        }
        __syncthreads();
#pragma unroll
        for (int k = 0; k < 16; k++) {
            float ra[4], rb[4];
#pragma unroll
            for (int i = 0; i < 4; i++) ra[i] = Vs[k][ty * 4 + i];
#pragma unroll
            for (int j = 0; j < 4; j++) rb[j] = Ss[k][tx * 4 + j];
#pragma unroll
            for (int i = 0; i < 4; i++)
#pragma unroll
                for (int j = 0; j < 4; j++) acc[i][j] += ra[i] * rb[j];
        }
        __syncthreads();
    }
#pragma unroll
    for (int i = 0; i < 4; i++) {
        int d = ty * 4 + i;
#pragma unroll
        for (int j = 0; j < 4; j++) {
            int n = n0 + tx * 4 + j;
            out[((size_t)b * C_ + h * HD_ + d) * N_ + n] = acc[i][j];
        }
    }
}

// ---------------- depthwise 3x3, SAME zero pad ---------------------------
// vmap: map logical channel c to qkv channel (c/64)*128 + 64 + (c%64)
__global__ void dwconv_kernel(const float* __restrict__ in,
                              const float* __restrict__ w,
                              const float* __restrict__ scale,
                              const float* __restrict__ bias,
                              float* __restrict__ out,
                              int C, int CinTotal, int vmap, int accum)
{
    int idx = blockIdx.x * blockDim.x + threadIdx.x;
    int total = B_ * C * H_ * W_;
    if (idx >= total) return;
    int xw = idx & (W_ - 1);
    int yh = (idx / W_) & (H_ - 1);
    int c  = (idx / (W_ * H_)) % C;
    int b  = idx / (W_ * H_ * C);
    int cin = vmap ? ((c >> 6) * 128 + 64 + (c & 63)) : c;
    const float* ip = in + ((size_t)b * CinTotal + cin) * (H_ * W_);
    const float* wp = w + c * 9;
    float s = 0.f;
#pragma unroll
    for (int dy = -1; dy <= 1; dy++) {
        int yy = yh + dy;
        if (yy < 0 || yy >= H_) continue;
#pragma unroll
        for (int dx = -1; dx <= 1; dx++) {
            int xx = xw + dx;
            if (xx < 0 || xx >= W_) continue;
            s += ip[yy * W_ + xx] * wp[(dy + 1) * 3 + (dx + 1)];
        }
    }
    if (scale) s = s * scale[c] + bias[c];
    if (accum) out[idx] += s; else out[idx] = s;
}

// ---------------- GELU(y1) * y2 gate -------------------------------------
__global__ void gate_kernel(const float* __restrict__ dw, float* __restrict__ hid)
{
    int idx = blockIdx.x * blockDim.x + threadIdx.x;
    int total = B_ * HID * N_;
    if (idx >= total) return;
    int n = idx % N_;
    int c = (idx / N_) % HID;
    int b = idx / (N_ * HID);
    float y1 = dw[((size_t)b * C2 + c) * N_ + n];
    float y2 = dw[((size_t)b * C2 + HID + c) * N_ + n];
    float g = 0.5f * y1 * (1.f + erff(y1 * 0.70710678118654752f));
    hid[idx] = g * y2;
}

// ---------------- FFT filter -> 8x8 circular-conv kernel ------------------
__global__ void fft_g_kernel(const float* __restrict__ filt, float* __restrict__ g)
{
    const float ct[8] = {1.f, 0.70710678118654752f, 0.f, -0.70710678118654752f,
                         -1.f, -0.70710678118654752f, 0.f, 0.70710678118654752f};
    int c = blockIdx.x;
    int t = threadIdx.x;           // 64
    int a = t >> 3, bb = t & 7;
    float s = 0.f;
    for (int k1 = 0; k1 < 8; k1++) {
        for (int k2 = 0; k2 < 8; k2++) {
            float F = (k2 <= 4) ? filt[c * 40 + k1 * 5 + k2]
                                : filt[c * 40 + ((8 - k1) & 7) * 5 + (8 - k2)];
            s += F * ct[(k1 * a + k2 * bb) & 7];
        }
    }
    g[c * 64 + t] = s * (1.f / 64.f);
}

// ---------------- per-8x8-block circular conv + final residual ----------
__global__ void fft_apply_kernel(const float* __restrict__ y,
                                 const float* __restrict__ g,
                                 const float* __restrict__ xnew,
                                 float* __restrict__ out)
{
    __shared__ float ys[32 * 32];
    __shared__ float gs[64];
    int bc = blockIdx.x;             // b*C + c
    int c = bc % C_;
    const float* yp = y + (size_t)bc * (H_ * W_);
    int tid = threadIdx.x;
    for (int i = tid; i < 1024; i += 256) ys[i] = yp[i];
    if (tid < 64) gs[tid] = g[c * 64 + tid];
    __syncthreads();
    for (int i = tid; i < 1024; i += 256) {
        int u = i >> 5, v = i & 31;
        int bu = u & ~7, bv = v & ~7;
        int uu = u & 7, vv = v & 7;
        float s = 0.f;
#pragma unroll
        for (int a = 0; a < 8; a++) {
            const float* yr = &ys[(bu + a) * 32 + bv];
            const float* gr = &gs[((uu - a) & 7) * 8];
#pragma unroll
            for (int b2 = 0; b2 < 8; b2++)
                s += gr[(vv - b2) & 7] * yr[b2];
        }
        size_t oi = (size_t)bc * 1024 + i;
        out[oi] = xnew[oi] + s;
    }
}

// =========================================================================
extern "C" void kernel_launch(void* const* d_in, const int* in_sizes, int n_in,
                              void* d_out, int out_size)
{
    const float* x        = (const float*)d_in[0];
    const float* qkv_w    = (const float*)d_in[1];
    const float* qkv_s    = (const float*)d_in[2];
    const float* qkv_b    = (const float*)d_in[3];
    const float* pe_w     = (const float*)d_in[4];
    const float* pe_s     = (const float*)d_in[5];
    const float* pe_b     = (const float*)d_in[6];
    const float* proj_w   = (const float*)d_in[7];
    const float* proj_s   = (const float*)d_in[8];
    const float* proj_b   = (const float*)d_in[9];
    const float* pin_w    = (const float*)d_in[10];
    const float* dw_w     = (const float*)d_in[11];
    const float* fft_filt = (const float*)d_in[12];
    const float* pout_w   = (const float*)d_in[13];
    float* out = (float*)d_out;

    float* qkv   ; cudaGetSymbolAddress((void**)&qkv,    g_qkv);
    float* attn  ; cudaGetSymbolAddress((void**)&attn,   g_attn);
    float* attout; cudaGetSymbolAddress((void**)&attout, g_attout);
    float* xnew  ; cudaGetSymbolAddress((void**)&xnew,   g_xnew);
    float* pin   ; cudaGetSymbolAddress((void**)&pin,    g_pin);
    float* dwbuf ; cudaGetSymbolAddress((void**)&dwbuf,  g_dw);
    float* hid   ; cudaGetSymbolAddress((void**)&hid,    g_hid);
    float* yout  ; cudaGetSymbolAddress((void**)&yout,   g_yout);
    float* gtab  ; cudaGetSymbolAddress((void**)&gtab,   g_g);

    // 1. qkv = affine(conv1x1(x, qkv_w))
    gemm1x1_kernel<<<dim3(N_/64, CQKV/64, B_), 256>>>(x, qkv_w, qkv_s, qkv_b, nullptr, qkv, C_, CQKV, N_);
    // 2. S = Q^T K * scale
    attn_qk_kernel<<<dim3(N_/64, N_/64, B_*NH_), 256>>>(qkv, attn, 0.176776695296636893f);
    // 3. softmax rows
    softmax_kernel<<<B_*NH_*N_, 256>>>(attn);
    // 4. out = V @ S^T
    attn_pv_kernel<<<dim3(N_/64, 1, B_*NH_), 256>>>(qkv, attn, attout);
    // 5. attout += affine(dwconv3x3(v_img, pe_w))
    dwconv_kernel<<<(B_*C_*H_*W_ + 255)/256, 256>>>(qkv, pe_w, pe_s, pe_b, attout, C_, CQKV, 1, 1);
    // 6. xnew = x + affine(conv1x1(attout, proj_w))
    gemm1x1_kernel<<<dim3(N_/64, C_/64, B_), 256>>>(attout, proj_w, proj_s, proj_b, x, xnew, C_, C_, N_);
    // 7. pin = conv1x1(xnew, pin_w)
    gemm1x1_kernel<<<dim3(N_/64, C2/64, B_), 256>>>(xnew, pin_w, nullptr, nullptr, nullptr, pin, C_, C2, N_);
    // 8. dw = dwconv3x3(pin, dw_w)
    dwconv_kernel<<<(B_*C2*H_*W_ + 255)/256, 256>>>(pin, dw_w, nullptr, nullptr, dwbuf, C2, C2, 0, 0);
    // 9. hid = gelu(y1) * y2
    gate_kernel<<<(B_*HID*N_ + 255)/256, 256>>>(dwbuf, hid);
    // 10. yout = conv1x1(hid, pout_w)
    gemm1x1_kernel<<<dim3(N_/64, C_/64, B_), 256>>>(hid, pout_w, nullptr, nullptr, nullptr, yout, HID, C_, N_);
    // 11. circular-conv kernels from fft filter
    fft_g_kernel<<<C_, 64>>>(fft_filt, gtab);
    // 12. out = xnew + blockwise circconv(yout)
    fft_apply_kernel<<<B_*C_, 256>>>(yout, gtab, xnew, out);
}

// round 4
// speedup vs baseline: 1.6285x; 1.6285x over previous
#include <cuda_runtime.h>
#include <math.h>
#include <stdint.h>

#define NB 16
#define C_ 256
#define N_ 1024
#define CQKV 512
#define C2 1024
#define HID 512

__device__ float g_qkv [(size_t)NB*CQKV*N_];
__device__ float g_attn[(size_t)NB*4*N_*N_];
__device__ float g_atto[(size_t)NB*C_*N_];
__device__ float g_xnew[(size_t)NB*C_*N_];
__device__ float g_pin [(size_t)NB*C2*N_];
__device__ float g_dw  [(size_t)NB*C2*N_];
__device__ float g_hid [(size_t)NB*HID*N_];
__device__ float g_yout[(size_t)NB*C_*N_];
__device__ float g_g   [C_*64];

__device__ __forceinline__ uint32_t tf32c(float f){
    uint32_t u; asm("cvt.rna.tf32.f32 %0, %1;" : "=r"(u) : "f"(f)); return u;
}
__device__ __forceinline__ void mma8(float* d, const uint32_t* a, uint32_t b0, uint32_t b1){
    asm volatile("mma.sync.aligned.m16n8k8.row.col.f32.tf32.tf32.f32 "
        "{%0,%1,%2,%3}, {%4,%5,%6,%7}, {%8,%9}, {%0,%1,%2,%3};"
        : "+f"(d[0]), "+f"(d[1]), "+f"(d[2]), "+f"(d[3])
        : "r"(a[0]), "r"(a[1]), "r"(a[2]), "r"(a[3]), "r"(b0), "r"(b1));
}

// D[m][n] = sum_k A[m][k]*B[n][k]; tile 128x128, BK=32, tf32 mma.sync.
// aT/bT: operand stored [k][m]/[k][n] in gmem. Epilogue: *cs, affine, +res.
__global__ void __launch_bounds__(256, 2) gemm_mma(
    const float* __restrict__ A, int aT, int lda, size_t aZs, int aRows,
    const float* __restrict__ B, int bT, int ldb, size_t bZs,
    float* __restrict__ O, size_t oZs, int K, float cs,
    const float* __restrict__ sc, const float* __restrict__ bi,
    const float* __restrict__ res)
{
    __shared__ uint32_t As[128*36];
    __shared__ uint32_t Bs[128*36];
    const int tid = threadIdx.x, wid = tid >> 5, lane = tid & 31;
    const int m0 = blockIdx.y*128, n0 = blockIdx.x*128, z = blockIdx.z;
    const float* Ap = A + (size_t)z * aZs;
    const float* Bp = B + (size_t)z * bZs;
    const int wm = (wid & 3) * 32, wn = (wid >> 2) * 64;
    const int grp = lane >> 2, qid = lane & 3;

    float acc[2][8][4];
    #pragma unroll
    for (int mt = 0; mt < 2; mt++)
    #pragma unroll
        for (int nt = 0; nt < 8; nt++)
        #pragma unroll
            for (int r = 0; r < 4; r++) acc[mt][nt][r] = 0.f;

    for (int k0 = 0; k0 < K; k0 += 32) {
        // ---- fill A tile (As[m][k], 36-stride) ----
        if (!aT) {
            #pragma unroll
            for (int idx = tid; idx < 1024; idx += 256) {
                int r = idx >> 3, c4 = (idx & 7) * 4;
                if (r < aRows) {
                    float4 v = *(const float4*)(Ap + (size_t)(m0+r)*lda + k0 + c4);
                    uint32_t* d = &As[r*36 + c4];
                    d[0]=tf32c(v.x); d[1]=tf32c(v.y); d[2]=tf32c(v.z); d[3]=tf32c(v.w);
                }
            }
        } else {
            #pragma unroll
            for (int idx = tid; idx < 1024; idx += 256) {
                int k = idx >> 5, m4 = (idx & 31) * 4;
                float4 v = *(const float4*)(Ap + (size_t)(k0+k)*lda + m0 + m4);
                As[(m4+0)*36+k]=tf32c(v.x); As[(m4+1)*36+k]=tf32c(v.y);
                As[(m4+2)*36+k]=tf32c(v.z); As[(m4+3)*36+k]=tf32c(v.w);
            }
        }
        // ---- fill B tile (Bs[n][k]) ----
        if (!bT) {
            #pragma unroll
            for (int idx = tid; idx < 1024; idx += 256) {
                int r = idx >> 3, c4 = (idx & 7) * 4;
                float4 v = *(const float4*)(Bp + (size_t)(n0+r)*ldb + k0 + c4);
                uint32_t* d = &Bs[r*36 + c4];
                d[0]=tf32c(v.x); d[1]=tf32c(v.y); d[2]=tf32c(v.z); d[3]=tf32c(v.w);
            }
        } else {
            #pragma unroll
            for (int idx = tid; idx < 1024; idx += 256) {
                int k = idx >> 5, n4 = (idx & 31) * 4;
                float4 v = *(const float4*)(Bp + (size_t)(k0+k)*ldb + n0 + n4);
                Bs[(n4+0)*36+k]=tf32c(v.x); Bs[(n4+1)*36+k]=tf32c(v.y);
                Bs[(n4+2)*36+k]=tf32c(v.z); Bs[(n4+3)*36+k]=tf32c(v.w);
            }
        }
        __syncthreads();
        // ---- compute 4 k8-steps ----
        #pragma unroll
        for (int ks = 0; ks < 4; ks++) {
            int kk = ks * 8;
            uint32_t a[2][4];
            #pragma unroll
            for (int mt = 0; mt < 2; mt++) {
                int r = wm + mt*16 + grp;
                a[mt][0] = As[r*36 + kk + qid];
                a[mt][1] = As[(r+8)*36 + kk + qid];
                a[mt][2] = As[r*36 + kk + qid + 4];
                a[mt][3] = As[(r+8)*36 + kk + qid + 4];
            }
            #pragma unroll
            for (int nt = 0; nt < 8; nt++) {
                int n = wn + nt*8 + grp;
                uint32_t b0 = Bs[n*36 + kk + qid];
                uint32_t b1 = Bs[n*36 + kk + qid + 4];
                mma8(acc[0][nt], a[0], b0, b1);
                mma8(acc[1][nt], a[1], b0, b1);
            }
        }
        __syncthreads();
    }

    // ---- epilogue ----
    #pragma unroll
    for (int mt = 0; mt < 2; mt++) {
        #pragma unroll
        for (int half = 0; half < 2; half++) {
            int mrow = wm + mt*16 + grp + half*8;
            if (mrow >= aRows) continue;
            int mg = m0 + mrow;
            float s1 = sc ? sc[mg] * cs : cs;
            float b1 = sc ? bi[mg] : 0.f;
            float* ob = O + (size_t)z*oZs + (size_t)mg*1024 + n0 + wn;
            const float* rb = res ? res + (size_t)z*oZs + (size_t)mg*1024 + n0 + wn : nullptr;
            #pragma unroll
            for (int nt = 0; nt < 8; nt++) {
                int c = nt*8 + 2*qid;
                float2 v;
                v.x = acc[mt][nt][half*2]   * s1 + b1;
                v.y = acc[mt][nt][half*2+1] * s1 + b1;
                if (rb) { float2 rv = *(const float2*)(rb + c); v.x += rv.x; v.y += rv.y; }
                *(float2*)(ob + c) = v;
            }
        }
    }
}

// single-pass softmax, row resident in smem
__global__ void softmax_kernel(float* __restrict__ attn)
{
    __shared__ float row[1024];
    __shared__ float red[256];
    float* p = attn + (size_t)blockIdx.x * 1024;
    const int tid = threadIdx.x;
    float4 v = *(float4*)(p + tid*4);
    *(float4*)(row + tid*4) = v;
    float m = fmaxf(fmaxf(v.x, v.y), fmaxf(v.z, v.w));
    red[tid] = m; __syncthreads();
    for (int s = 128; s > 0; s >>= 1) { if (tid < s) red[tid] = fmaxf(red[tid], red[tid+s]); __syncthreads(); }
    m = red[0]; __syncthreads();
    float sum = 0.f;
    #pragma unroll
    for (int j = 0; j < 4; j++) { float e = __expf(row[tid*4+j] - m); row[tid*4+j] = e; sum += e; }
    red[tid] = sum; __syncthreads();
    for (int s = 128; s > 0; s >>= 1) { if (tid < s) red[tid] += red[tid+s]; __syncthreads(); }
    float inv = 1.f / red[0];
    float4 o; o.x = row[tid*4]*inv; o.y = row[tid*4+1]*inv; o.z = row[tid*4+2]*inv; o.w = row[tid*4+3]*inv;
    *(float4*)(p + tid*4) = o;
}

__global__ void dwconv_kernel(const float* __restrict__ in, const float* __restrict__ w,
                              const float* __restrict__ scale, const float* __restrict__ bias,
                              float* __restrict__ out, int C, int CinTotal, int vmap, int accum)
{
    int idx = blockIdx.x * blockDim.x + threadIdx.x;
    if (idx >= NB * C * 1024) return;
    int xw = idx & 31, yh = (idx >> 5) & 31;
    int c = (idx >> 10) % C, b = idx / (1024 * C);
    int cin = vmap ? ((c >> 6) * 128 + 64 + (c & 63)) : c;
    const float* ip = in + ((size_t)b * CinTotal + cin) * 1024;
    const float* wp = w + c * 9;
    float s = 0.f;
    #pragma unroll
    for (int dy = -1; dy <= 1; dy++) {
        int yy = yh + dy; if ((unsigned)yy >= 32u) continue;
        #pragma unroll
        for (int dx = -1; dx <= 1; dx++) {
            int xx = xw + dx; if ((unsigned)xx >= 32u) continue;
            s += ip[yy*32 + xx] * wp[(dy+1)*3 + dx + 1];
        }
    }
    if (scale) s = s * scale[c] + bias[c];
    if (accum) out[idx] += s; else out[idx] = s;
}

__global__ void gate_kernel(const float* __restrict__ dw, float* __restrict__ hid)
{
    int idx = blockIdx.x * blockDim.x + threadIdx.x;
    if (idx >= NB * HID * 1024) return;
    int n = idx & 1023, c = (idx >> 10) & 511, b = idx >> 19;
    float y1 = dw[((size_t)b * C2 + c) * 1024 + n];
    float y2 = dw[((size_t)b * C2 + 512 + c) * 1024 + n];
    float g = 0.5f * y1 * (1.f + erff(y1 * 0.70710678118654752f));
    hid[idx] = g * y2;
}

__global__ void fft_g_kernel(const float* __restrict__ filt, float* __restrict__ g)
{
    const float ct[8] = {1.f, 0.70710678118654752f, 0.f, -0.70710678118654752f,
                         -1.f, -0.70710678118654752f, 0.f, 0.70710678118654752f};
    int c = blockIdx.x, t = threadIdx.x;
    int a = t >> 3, bb = t & 7;
    float s = 0.f;
    for (int k1 = 0; k1 < 8; k1++)
        for (int k2 = 0; k2 < 8; k2++) {
            float F = (k2 <= 4) ? filt[c*40 + k1*5 + k2]
                                : filt[c*40 + ((8-k1)&7)*5 + (8-k2)];
            s += F * ct[(k1*a + k2*bb) & 7];
        }
    g[c*64 + t] = s * (1.f/64.f);
}

__global__ void fft_apply_kernel(const float* __restrict__ y, const float* __restrict__ g,
                                 const float* __restrict__ xnew, float* __restrict__ out)
{
    __shared__ float ys[1024];
    __shared__ float gs[64];
    int bc = blockIdx.x, c = bc % 256;
    const float* yp = y + (size_t)bc * 1024;
    int tid = threadIdx.x;
    for (int i = tid; i < 1024; i += 256) ys[i] = yp[i];
    if (tid < 64) gs[tid] = g[c*64 + tid];
    __syncthreads();
    for (int i = tid; i < 1024; i += 256) {
        int u = i >> 5, v = i & 31;
        int bu = u & ~7, bv = v & ~7, uu = u & 7, vv = v & 7;
        float s = 0.f;
        #pragma unroll
        for (int a = 0; a < 8; a++) {
            const float* yr = &ys[(bu + a)*32 + bv];
            const float* gr = &gs[((uu - a) & 7) * 8];
            #pragma unroll
            for (int b2 = 0; b2 < 8; b2++)
                s += gr[(vv - b2) & 7] * yr[b2];
        }
        size_t oi = (size_t)bc * 1024 + i;
        out[oi] = xnew[oi] + s;
    }
}

extern "C" void kernel_launch(void* const* d_in, const int* in_sizes, int n_in,
                              void* d_out, int out_size)
{
    const float* x      = (const float*)d_in[0];
    const float* qkv_w  = (const float*)d_in[1];
    const float* qkv_s  = (const float*)d_in[2];
    const float* qkv_b  = (const float*)d_in[3];
    const float* pe_w   = (const float*)d_in[4];
    const float* pe_s   = (const float*)d_in[5];
    const float* pe_b   = (const float*)d_in[6];
    const float* proj_w = (const float*)d_in[7];
    const float* proj_s = (const float*)d_in[8];
    const float* proj_b = (const float*)d_in[9];
    const float* pin_w  = (const float*)d_in[10];
    const float* dw_w   = (const float*)d_in[11];
    const float* ff     = (const float*)d_in[12];
    const float* pout_w = (const float*)d_in[13];
    float* out = (float*)d_out;

    float *qkv, *attn, *atto, *xnew, *pin, *dwb, *hid, *yout, *gtab;
    cudaGetSymbolAddress((void**)&qkv,  g_qkv);
    cudaGetSymbolAddress((void**)&attn, g_attn);
    cudaGetSymbolAddress((void**)&atto, g_atto);
    cudaGetSymbolAddress((void**)&xnew, g_xnew);
    cudaGetSymbolAddress((void**)&pin,  g_pin);
    cudaGetSymbolAddress((void**)&dwb,  g_dw);
    cudaGetSymbolAddress((void**)&hid,  g_hid);
    cudaGetSymbolAddress((void**)&yout, g_yout);
    cudaGetSymbolAddress((void**)&gtab, g_g);

    // 1. qkv = affine(W_qkv @ x)
    gemm_mma<<<dim3(8,4,16), 256>>>(qkv_w,0,256,0,128, x,1,1024,(size_t)262144,
                                    qkv,(size_t)524288, 256, 1.f, qkv_s, qkv_b, nullptr);
    // 2. S = (Q^T K) * scale
    gemm_mma<<<dim3(8,8,64), 256>>>(qkv,1,1024,(size_t)131072,128, qkv+32768,1,1024,(size_t)131072,
                                    attn,(size_t)1048576, 32, 0.17677669529663687f, nullptr, nullptr, nullptr);
    // 3. softmax
    softmax_kernel<<<NB*4*1024, 256>>>(attn);
    // 4. out = V @ S^T (64 valid rows)
    gemm_mma<<<dim3(8,1,64), 256>>>(qkv+65536,0,1024,(size_t)131072,64, attn,0,1024,(size_t)1048576,
                                    atto,(size_t)65536, 1024, 1.f, nullptr, nullptr, nullptr);
    // 5. atto += affine(dwconv3x3(v_img))
    dwconv_kernel<<<(NB*C_*1024+255)/256, 256>>>(qkv, pe_w, pe_s, pe_b, atto, C_, CQKV, 1, 1);
    // 6. xnew = x + affine(W_proj @ atto)
    gemm_mma<<<dim3(8,2,16), 256>>>(proj_w,0,256,0,128, atto,1,1024,(size_t)262144,
                                    xnew,(size_t)262144, 256, 1.f, proj_s, proj_b, x);
    // 7. pin = W_pin @ xnew
    gemm_mma<<<dim3(8,8,16), 256>>>(pin_w,0,256,0,128, xnew,1,1024,(size_t)262144,
                                    pin,(size_t)1048576, 256, 1.f, nullptr, nullptr, nullptr);
    // 8. dw = dwconv3x3(pin)
    dwconv_kernel<<<(NB*C2*1024+255)/256, 256>>>(pin, dw_w, nullptr, nullptr, dwb, C2, C2, 0, 0);
    // 9. hid = gelu(y1)*y2
    gate_kernel<<<(NB*HID*1024+255)/256, 256>>>(dwb, hid);
    // 10. yout = W_pout @ hid
    gemm_mma<<<dim3(8,2,16), 256>>>(pout_w,0,512,0,128, hid,1,1024,(size_t)524288,
                                    yout,(size_t)262144, 512, 1.f, nullptr, nullptr, nullptr);
    // 11-12. fft filter -> circular conv, add residual
    fft_g_kernel<<<C_, 64>>>(ff, gtab);
    fft_apply_kernel<<<NB*C_, 256>>>(yout, gtab, xnew, out);
}

// round 5
// speedup vs baseline: 3.1826x; 1.9544x over previous
#include <cuda_runtime.h>
#include <math.h>
#include <stdint.h>

#define NB 16
#define C_ 256
#define N_ 1024
#define C2 1024
#define HID 512

__device__ float g_qkv  [(size_t)NB*512*1024];
__device__ float g_qkT  [(size_t)64*1024*64];
__device__ float g_xT   [(size_t)NB*1024*256];
__device__ float g_atto [(size_t)NB*256*1024];
__device__ float g_attoT[(size_t)NB*1024*256];
__device__ float g_xnew [(size_t)NB*256*1024];
__device__ float g_xnewT[(size_t)NB*1024*256];
__device__ float g_pin  [(size_t)NB*1024*1024];
__device__ float g_dw   [(size_t)NB*1024*1024];
__device__ float g_hid  [(size_t)NB*512*1024];
__device__ float g_hidT [(size_t)NB*1024*512];
__device__ float g_yout [(size_t)NB*256*1024];
__device__ float g_g    [C_*64];

__device__ __forceinline__ uint32_t tf32c(float f){
    uint32_t u; asm("cvt.rna.tf32.f32 %0, %1;" : "=r"(u) : "f"(f)); return u;
}
__device__ __forceinline__ void mma8(float* d, const uint32_t* a, uint32_t b0, uint32_t b1){
    asm volatile("mma.sync.aligned.m16n8k8.row.col.f32.tf32.tf32.f32 "
        "{%0,%1,%2,%3}, {%4,%5,%6,%7}, {%8,%9}, {%0,%1,%2,%3};"
        : "+f"(d[0]), "+f"(d[1]), "+f"(d[2]), "+f"(d[3])
        : "r"(a[0]), "r"(a[1]), "r"(a[2]), "r"(a[3]), "r"(b0), "r"(b1));
}

// ======================= generic conv1x1 GEMM (tf32 mma) =======================
// D[m][n] = sum_k A[m][k]*B[n][k]; tile 128x128, BK=32. Both operands K-major.
__global__ void __launch_bounds__(256, 2) gemm_mma(
    const float* __restrict__ A, int lda, int aRows,
    const float* __restrict__ B, int ldb, size_t bZs,
    float* __restrict__ O, size_t oZs, int K, float cs,
    const float* __restrict__ sc, const float* __restrict__ bi,
    const float* __restrict__ res)
{
    __shared__ uint32_t As[128*36];
    __shared__ uint32_t Bs[128*36];
    const int tid = threadIdx.x, wid = tid >> 5, lane = tid & 31;
    const int m0 = blockIdx.y*128, n0 = blockIdx.x*128, z = blockIdx.z;
    const float* Bp = B + (size_t)z * bZs;
    const int wm = (wid & 3) * 32, wn = (wid >> 2) * 64;
    const int grp = lane >> 2, qid = lane & 3;

    float acc[2][8][4];
    #pragma unroll
    for (int mt = 0; mt < 2; mt++)
    #pragma unroll
        for (int nt = 0; nt < 8; nt++)
        #pragma unroll
            for (int r = 0; r < 4; r++) acc[mt][nt][r] = 0.f;

    for (int k0 = 0; k0 < K; k0 += 32) {
        #pragma unroll
        for (int idx = tid; idx < 1024; idx += 256) {
            int r = idx >> 3, c4 = (idx & 7) * 4;
            if (r < aRows) {
                float4 v = *(const float4*)(A + (size_t)(m0+r)*lda + k0 + c4);
                uint32_t* d = &As[r*36 + c4];
                d[0]=tf32c(v.x); d[1]=tf32c(v.y); d[2]=tf32c(v.z); d[3]=tf32c(v.w);
            }
        }
        #pragma unroll
        for (int idx = tid; idx < 1024; idx += 256) {
            int r = idx >> 3, c4 = (idx & 7) * 4;
            float4 v = *(const float4*)(Bp + (size_t)(n0+r)*ldb + k0 + c4);
            uint32_t* d = &Bs[r*36 + c4];
            d[0]=tf32c(v.x); d[1]=tf32c(v.y); d[2]=tf32c(v.z); d[3]=tf32c(v.w);
        }
        __syncthreads();
        #pragma unroll
        for (int ks = 0; ks < 4; ks++) {
            int kk = ks * 8;
            uint32_t a[2][4];
            #pragma unroll
            for (int mt = 0; mt < 2; mt++) {
                int r = wm + mt*16 + grp;
                a[mt][0] = As[r*36 + kk + qid];
                a[mt][1] = As[(r+8)*36 + kk + qid];
                a[mt][2] = As[r*36 + kk + qid + 4];
                a[mt][3] = As[(r+8)*36 + kk + qid + 4];
            }
            #pragma unroll
            for (int nt = 0; nt < 8; nt++) {
                int n = wn + nt*8 + grp;
                uint32_t b0 = Bs[n*36 + kk + qid];
                uint32_t b1 = Bs[n*36 + kk + qid + 4];
                mma8(acc[0][nt], a[0], b0, b1);
                mma8(acc[1][nt], a[1], b0, b1);
            }
        }
        __syncthreads();
    }
    #pragma unroll
    for (int mt = 0; mt < 2; mt++) {
        #pragma unroll
        for (int half = 0; half < 2; half++) {
            int mrow = wm + mt*16 + grp + half*8;
            if (mrow >= aRows) continue;
            int mg = m0 + mrow;
            float s1 = sc ? sc[mg] * cs : cs;
            float b1 = sc ? bi[mg] : 0.f;
            float* ob = O + (size_t)z*oZs + (size_t)mg*1024 + n0 + wn;
            const float* rb = res ? res + (size_t)z*oZs + (size_t)mg*1024 + n0 + wn : nullptr;
            #pragma unroll
            for (int nt = 0; nt < 8; nt++) {
                int c = nt*8 + 2*qid;
                float2 v;
                v.x = acc[mt][nt][half*2]   * s1 + b1;
                v.y = acc[mt][nt][half*2+1] * s1 + b1;
                if (rb) { float2 rv = *(const float2*)(rb + c); v.x += rv.x; v.y += rv.y; }
                *(float2*)(ob + c) = v;
            }
        }
    }
}

// ======================= 32x32 tiled transpose =======================
// dst[z][c][r] = src[z][r][c], R rows x C cols
__global__ void transpose_kernel(const float* __restrict__ src, float* __restrict__ dst,
                                 size_t sStr, size_t dStr, int R, int C)
{
    __shared__ float t[32][33];
    const float* s = src + (size_t)blockIdx.z * sStr;
    float* d = dst + (size_t)blockIdx.z * dStr;
    int c0 = blockIdx.x*32, r0 = blockIdx.y*32;
    int tx = threadIdx.x, ty = threadIdx.y;
    #pragma unroll
    for (int k = 0; k < 32; k += 8)
        t[ty+k][tx] = s[(size_t)(r0+ty+k)*C + c0+tx];
    __syncthreads();
    #pragma unroll
    for (int k = 0; k < 32; k += 8)
        d[(size_t)(c0+ty+k)*R + r0+tx] = t[tx][ty+k];
}

// ======================= flash attention =======================
// grid (8 qblocks, 64 bh), 256 threads. qkT: [bh][n][64] (Q 0-31, K 32-63).
// V read channel-major from qkv. Output: atto channel-major.
#define FA_SMEM 138240
__global__ void __launch_bounds__(256, 1) flash_kernel(
    const float* __restrict__ qkT, const float* __restrict__ qkv,
    float* __restrict__ atto)
{
    extern __shared__ float sm[];
    float* Qs = sm;             // [128][36]
    float* Ks = sm + 4608;      // [128][36]
    float* Vs = sm + 9216;      // [64][132]
    float* Ps = sm + 17664;     // [128][132]
    const int tid = threadIdx.x, wid = tid >> 5, lane = tid & 31;
    const int grp = lane >> 2, qid = lane & 3;
    const int m0 = blockIdx.x * 128, bh = blockIdx.y;
    const int b = bh >> 2, h = bh & 3;
    const int wq = wid * 16;
    const float* qbase = qkT + ((size_t)bh*1024 + m0)*64;
    const float* vbase = qkv + (size_t)b*524288 + (size_t)(h*128+64)*1024;

    // load Q (pre-scaled by 1/sqrt(kd))
    #pragma unroll
    for (int idx = tid; idx < 1024; idx += 256) {
        int r = idx >> 3, c4 = (idx & 7) * 4;
        float4 v = *(const float4*)(qbase + r*64 + c4);
        uint32_t* d = (uint32_t*)&Qs[r*36 + c4];
        const float s = 0.17677669529663687f;
        d[0]=tf32c(v.x*s); d[1]=tf32c(v.y*s); d[2]=tf32c(v.z*s); d[3]=tf32c(v.w*s);
    }

    float m_i[2] = {-1e30f, -1e30f};
    float l_i[2] = {0.f, 0.f};
    float ao[8][4];
    #pragma unroll
    for (int dt = 0; dt < 8; dt++) { ao[dt][0]=0; ao[dt][1]=0; ao[dt][2]=0; ao[dt][3]=0; }

    for (int kc = 0; kc < 8; kc++) {
        const float* kb = qkT + ((size_t)bh*1024 + kc*128)*64 + 32;
        #pragma unroll
        for (int idx = tid; idx < 1024; idx += 256) {
            int r = idx >> 3, c4 = (idx & 7) * 4;
            float4 v = *(const float4*)(kb + r*64 + c4);
            uint32_t* d = (uint32_t*)&Ks[r*36 + c4];
            d[0]=tf32c(v.x); d[1]=tf32c(v.y); d[2]=tf32c(v.z); d[3]=tf32c(v.w);
        }
        const float* vb = vbase + kc*128;
        #pragma unroll
        for (int idx = tid; idx < 2048; idx += 256) {
            int dd = idx >> 5, c4 = (idx & 31) * 4;
            float4 v = *(const float4*)(vb + (size_t)dd*1024 + c4);
            uint32_t* dp = (uint32_t*)&Vs[dd*132 + c4];
            dp[0]=tf32c(v.x); dp[1]=tf32c(v.y); dp[2]=tf32c(v.z); dp[3]=tf32c(v.w);
        }
        __syncthreads();

        // S = Q K^T (16 q rows per warp x 128 keys)
        float sacc[16][4];
        #pragma unroll
        for (int nt = 0; nt < 16; nt++) { sacc[nt][0]=0; sacc[nt][1]=0; sacc[nt][2]=0; sacc[nt][3]=0; }
        const uint32_t* Qu = (const uint32_t*)Qs;
        const uint32_t* Ku = (const uint32_t*)Ks;
        #pragma unroll
        for (int ks = 0; ks < 4; ks++) {
            int kk = ks * 8;
            uint32_t a[4];
            a[0] = Qu[(wq+grp)*36 + kk + qid];
            a[1] = Qu[(wq+grp+8)*36 + kk + qid];
            a[2] = Qu[(wq+grp)*36 + kk + qid + 4];
            a[3] = Qu[(wq+grp+8)*36 + kk + qid + 4];
            #pragma unroll
            for (int nt = 0; nt < 16; nt++) {
                uint32_t b0 = Ku[(nt*8+grp)*36 + kk + qid];
                uint32_t b1 = Ku[(nt*8+grp)*36 + kk + qid + 4];
                mma8(sacc[nt], a, b0, b1);
            }
        }
        // online softmax (rows grp, grp+8; quad-shuffle reductions)
        float mx0 = -1e30f, mx1 = -1e30f;
        #pragma unroll
        for (int nt = 0; nt < 16; nt++) {
            mx0 = fmaxf(mx0, fmaxf(sacc[nt][0], sacc[nt][1]));
            mx1 = fmaxf(mx1, fmaxf(sacc[nt][2], sacc[nt][3]));
        }
        mx0 = fmaxf(mx0, __shfl_xor_sync(0xffffffffu, mx0, 1));
        mx0 = fmaxf(mx0, __shfl_xor_sync(0xffffffffu, mx0, 2));
        mx1 = fmaxf(mx1, __shfl_xor_sync(0xffffffffu, mx1, 1));
        mx1 = fmaxf(mx1, __shfl_xor_sync(0xffffffffu, mx1, 2));
        float mn0 = fmaxf(m_i[0], mx0), mn1 = fmaxf(m_i[1], mx1);
        float s0 = 0.f, s1 = 0.f;
        #pragma unroll
        for (int nt = 0; nt < 16; nt++) {
            sacc[nt][0] = __expf(sacc[nt][0] - mn0);
            sacc[nt][1] = __expf(sacc[nt][1] - mn0);
            sacc[nt][2] = __expf(sacc[nt][2] - mn1);
            sacc[nt][3] = __expf(sacc[nt][3] - mn1);
            s0 += sacc[nt][0] + sacc[nt][1];
            s1 += sacc[nt][2] + sacc[nt][3];
        }
        s0 += __shfl_xor_sync(0xffffffffu, s0, 1);
        s0 += __shfl_xor_sync(0xffffffffu, s0, 2);
        s1 += __shfl_xor_sync(0xffffffffu, s1, 1);
        s1 += __shfl_xor_sync(0xffffffffu, s1, 2);
        float al0 = __expf(m_i[0] - mn0), al1 = __expf(m_i[1] - mn1);
        l_i[0] = l_i[0]*al0 + s0; l_i[1] = l_i[1]*al1 + s1;
        m_i[0] = mn0; m_i[1] = mn1;
        #pragma unroll
        for (int dt = 0; dt < 8; dt++) {
            ao[dt][0] *= al0; ao[dt][1] *= al0;
            ao[dt][2] *= al1; ao[dt][3] *= al1;
        }
        // stage P (warp-private rows)
        #pragma unroll
        for (int nt = 0; nt < 16; nt++) {
            Ps[(wq+grp)*132 + nt*8 + 2*qid]     = sacc[nt][0];
            Ps[(wq+grp)*132 + nt*8 + 2*qid+1]   = sacc[nt][1];
            Ps[(wq+grp+8)*132 + nt*8 + 2*qid]   = sacc[nt][2];
            Ps[(wq+grp+8)*132 + nt*8 + 2*qid+1] = sacc[nt][3];
        }
        __syncwarp();
        // O += P V
        const uint32_t* Pu = (const uint32_t*)Ps;
        const uint32_t* Vu = (const uint32_t*)Vs;
        #pragma unroll
        for (int ks = 0; ks < 16; ks++) {
            int kk = ks * 8;
            uint32_t a[4];
            a[0] = Pu[(wq+grp)*132 + kk + qid];
            a[1] = Pu[(wq+grp+8)*132 + kk + qid];
            a[2] = Pu[(wq+grp)*132 + kk + qid + 4];
            a[3] = Pu[(wq+grp+8)*132 + kk + qid + 4];
            #pragma unroll
            for (int dt = 0; dt < 8; dt++) {
                uint32_t b0 = Vu[(dt*8+grp)*132 + kk + qid];
                uint32_t b1 = Vu[(dt*8+grp)*132 + kk + qid + 4];
                mma8(ao[dt], a, b0, b1);
            }
        }
        __syncthreads();
    }
    // epilogue: normalize, stage [d][q] in smem, coalesced channel-major write
    float inv0 = 1.f / l_i[0], inv1 = 1.f / l_i[1];
    #pragma unroll
    for (int dt = 0; dt < 8; dt++) {
        int d0 = dt*8 + 2*qid;
        Ps[d0*132 + wq+grp]       = ao[dt][0]*inv0;
        Ps[(d0+1)*132 + wq+grp]   = ao[dt][1]*inv0;
        Ps[d0*132 + wq+grp+8]     = ao[dt][2]*inv1;
        Ps[(d0+1)*132 + wq+grp+8] = ao[dt][3]*inv1;
    }
    __syncthreads();
    #pragma unroll
    for (int idx = tid; idx < 2048; idx += 256) {
        int dd = idx >> 5, q4 = (idx & 31) * 4;
        float4 v = *(float4*)&Ps[dd*132 + q4];
        *(float4*)(atto + ((size_t)(b*256 + h*64 + dd))*1024 + m0 + q4) = v;
    }
}

// ======================= elementwise kernels (from R4) =======================
__global__ void dwconv_kernel(const float* __restrict__ in, const float* __restrict__ w,
                              const float* __restrict__ scale, const float* __restrict__ bias,
                              float* __restrict__ out, int C, int CinTotal, int vmap, int accum)
{
    int idx = blockIdx.x * blockDim.x + threadIdx.x;
    if (idx >= NB * C * 1024) return;
    int xw = idx & 31, yh = (idx >> 5) & 31;
    int c = (idx >> 10) % C, b = idx / (1024 * C);
    int cin = vmap ? ((c >> 6) * 128 + 64 + (c & 63)) : c;
    const float* ip = in + ((size_t)b * CinTotal + cin) * 1024;
    const float* wp = w + c * 9;
    float s = 0.f;
    #pragma unroll
    for (int dy = -1; dy <= 1; dy++) {
        int yy = yh + dy; if ((unsigned)yy >= 32u) continue;
        #pragma unroll
        for (int dx = -1; dx <= 1; dx++) {
            int xx = xw + dx; if ((unsigned)xx >= 32u) continue;
            s += ip[yy*32 + xx] * wp[(dy+1)*3 + dx + 1];
        }
    }
    if (scale) s = s * scale[c] + bias[c];
    if (accum) out[idx] += s; else out[idx] = s;
}

__global__ void gate_kernel(const float* __restrict__ dw, float* __restrict__ hid)
{
    int idx = blockIdx.x * blockDim.x + threadIdx.x;
    if (idx >= NB * HID * 1024) return;
    int n = idx & 1023, c = (idx >> 10) & 511, b = idx >> 19;
    float y1 = dw[((size_t)b * C2 + c) * 1024 + n];
    float y2 = dw[((size_t)b * C2 + 512 + c) * 1024 + n];
    float g = 0.5f * y1 * (1.f + erff(y1 * 0.70710678118654752f));
    hid[idx] = g * y2;
}

__global__ void fft_g_kernel(const float* __restrict__ filt, float* __restrict__ g)
{
    const float ct[8] = {1.f, 0.70710678118654752f, 0.f, -0.70710678118654752f,
                         -1.f, -0.70710678118654752f, 0.f, 0.70710678118654752f};
    int c = blockIdx.x, t = threadIdx.x;
    int a = t >> 3, bb = t & 7;
    float s = 0.f;
    for (int k1 = 0; k1 < 8; k1++)
        for (int k2 = 0; k2 < 8; k2++) {
            float F = (k2 <= 4) ? filt[c*40 + k1*5 + k2]
                                : filt[c*40 + ((8-k1)&7)*5 + (8-k2)];
            s += F * ct[(k1*a + k2*bb) & 7];
        }
    g[c*64 + t] = s * (1.f/64.f);
}

__global__ void fft_apply_kernel(const float* __restrict__ y, const float* __restrict__ g,
                                 const float* __restrict__ xnew, float* __restrict__ out)
{
    __shared__ float ys[1024];
    __shared__ float gs[64];
    int bc = blockIdx.x, c = bc % 256;
    const float* yp = y + (size_t)bc * 1024;
    int tid = threadIdx.x;
    for (int i = tid; i < 1024; i += 256) ys[i] = yp[i];
    if (tid < 64) gs[tid] = g[c*64 + tid];
    __syncthreads();
    for (int i = tid; i < 1024; i += 256) {
        int u = i >> 5, v = i & 31;
        int bu = u & ~7, bv = v & ~7, uu = u & 7, vv = v & 7;
        float s = 0.f;
        #pragma unroll
        for (int a = 0; a < 8; a++) {
            const float* yr = &ys[(bu + a)*32 + bv];
            const float* gr = &gs[((uu - a) & 7) * 8];
            #pragma unroll
            for (int b2 = 0; b2 < 8; b2++)
                s += gr[(vv - b2) & 7] * yr[b2];
        }
        size_t oi = (size_t)bc * 1024 + i;
        out[oi] = xnew[oi] + s;
    }
}

// =========================================================================
extern "C" void kernel_launch(void* const* d_in, const int* in_sizes, int n_in,
                              void* d_out, int out_size)
{
    const float* x      = (const float*)d_in[0];
    const float* qkv_w  = (const float*)d_in[1];
    const float* qkv_s  = (const float*)d_in[2];
    const float* qkv_b  = (const float*)d_in[3];
    const float* pe_w   = (const float*)d_in[4];
    const float* pe_s   = (const float*)d_in[5];
    const float* pe_b   = (const float*)d_in[6];
    const float* proj_w = (const float*)d_in[7];
    const float* proj_s = (const float*)d_in[8];
    const float* proj_b = (const float*)d_in[9];
    const float* pin_w  = (const float*)d_in[10];
    const float* dw_w   = (const float*)d_in[11];
    const float* ff     = (const float*)d_in[12];
    const float* pout_w = (const float*)d_in[13];
    float* out = (float*)d_out;

    float *qkv, *qkT, *xT, *atto, *attoT, *xnew, *xnewT, *pin, *dwb, *hid, *hidT, *yout, *gtab;
    cudaGetSymbolAddress((void**)&qkv,   g_qkv);
    cudaGetSymbolAddress((void**)&qkT,   g_qkT);
    cudaGetSymbolAddress((void**)&xT,    g_xT);
    cudaGetSymbolAddress((void**)&atto,  g_atto);
    cudaGetSymbolAddress((void**)&attoT, g_attoT);
    cudaGetSymbolAddress((void**)&xnew,  g_xnew);
    cudaGetSymbolAddress((void**)&xnewT, g_xnewT);
    cudaGetSymbolAddress((void**)&pin,   g_pin);
    cudaGetSymbolAddress((void**)&dwb,   g_dw);
    cudaGetSymbolAddress((void**)&hid,   g_hid);
    cudaGetSymbolAddress((void**)&hidT,  g_hidT);
    cudaGetSymbolAddress((void**)&yout,  g_yout);
    cudaGetSymbolAddress((void**)&gtab,  g_g);

    cudaFuncSetAttribute(flash_kernel, cudaFuncAttributeMaxDynamicSharedMemorySize, FA_SMEM);
    dim3 tb(32, 8);

    // 1. xT = transpose(x)   [b][256][1024] -> [b][1024][256]
    transpose_kernel<<<dim3(32, 8, 16), tb>>>(x, xT, 262144, 262144, 256, 1024);
    // 2. qkv = affine(W_qkv @ x)  (channel-major out)
    gemm_mma<<<dim3(8,4,16), 256>>>(qkv_w, 256, 128, xT, 256, (size_t)262144,
                                    qkv, (size_t)524288, 256, 1.f, qkv_s, qkv_b, nullptr);
    // 3. qkT = transpose(Q,K channels)  per (b,h): 64ch x 1024 -> 1024 x 64
    transpose_kernel<<<dim3(32, 2, 64), tb>>>(qkv, qkT, 131072, 65536, 64, 1024);
    // 4. flash attention -> atto channel-major
    flash_kernel<<<dim3(8, 64), 256, FA_SMEM>>>(qkT, qkv, atto);
    // 5. atto += affine(dwconv3x3(v_img))
    dwconv_kernel<<<(NB*C_*1024+255)/256, 256>>>(qkv, pe_w, pe_s, pe_b, atto, C_, 512, 1, 1);
    // 6. attoT
    transpose_kernel<<<dim3(32, 8, 16), tb>>>(atto, attoT, 262144, 262144, 256, 1024);
    // 7. xnew = x + affine(W_proj @ atto)
    gemm_mma<<<dim3(8,2,16), 256>>>(proj_w, 256, 128, attoT, 256, (size_t)262144,
                                    xnew, (size_t)262144, 256, 1.f, proj_s, proj_b, x);
    // 8. xnewT
    transpose_kernel<<<dim3(32, 8, 16), tb>>>(xnew, xnewT, 262144, 262144, 256, 1024);
    // 9. pin = W_pin @ xnew
    gemm_mma<<<dim3(8,8,16), 256>>>(pin_w, 256, 128, xnewT, 256, (size_t)262144,
                                    pin, (size_t)1048576, 256, 1.f, nullptr, nullptr, nullptr);
    // 10. dw = dwconv3x3(pin)
    dwconv_kernel<<<(NB*C2*1024+255)/256, 256>>>(pin, dw_w, nullptr, nullptr, dwb, C2, C2, 0, 0);
    // 11. hid = gelu(y1)*y2
    gate_kernel<<<(NB*HID*1024+255)/256, 256>>>(dwb, hid);
    // 12. hidT  [b][512][1024] -> [b][1024][512]
    transpose_kernel<<<dim3(32, 16, 16), tb>>>(hid, hidT, 524288, 524288, 512, 1024);
    // 13. yout = W_pout @ hid
    gemm_mma<<<dim3(8,2,16), 256>>>(pout_w, 512, 128, hidT, 512, (size_t)524288,
                                    yout, (size_t)262144, 512, 1.f, nullptr, nullptr, nullptr);
    // 14. fft filter -> circular conv + residual
    fft_g_kernel<<<C_, 64>>>(ff, gtab);
    fft_apply_kernel<<<NB*C_, 256>>>(yout, gtab, xnew, out);
}

// round 6
// speedup vs baseline: 3.7564x; 1.1803x over previous
#include <cuda_runtime.h>
#include <math.h>
#include <stdint.h>

#define NB 16
#define C_ 256
#define N_ 1024
#define C2 1024
#define HID 512

__device__ float g_qkv  [(size_t)NB*512*1024];   // channel-major qkv (V used)
__device__ float g_qkT  [(size_t)64*1024*64];    // [bh][n][64] Q(0-31),K(32-63)
__device__ float g_xT   [(size_t)NB*1024*256];
__device__ float g_attoT[(size_t)NB*1024*256];   // token-major attn+pe
__device__ float g_xnew [(size_t)NB*256*1024];   // channel-major (fft residual)
__device__ float g_xnewT[(size_t)NB*1024*256];
__device__ float g_pin  [(size_t)NB*1024*1024];
__device__ float g_dw   [(size_t)NB*1024*1024];
__device__ float g_hidT [(size_t)NB*1024*512];
__device__ float g_yout [(size_t)NB*256*1024];
__device__ float g_g    [C_*64];

__device__ __forceinline__ uint32_t tf32c(float f){
    uint32_t u; asm("cvt.rna.tf32.f32 %0, %1;" : "=r"(u) : "f"(f)); return u;
}
__device__ __forceinline__ uint32_t smem_u32(const void* p){
    uint32_t a;
    asm("{ .reg .u64 t; cvta.to.shared.u64 t, %1; cvt.u32.u64 %0, t; }" : "=r"(a) : "l"(p));
    return a;
}
__device__ __forceinline__ void cpasync16(uint32_t s, const void* g){
    asm volatile("cp.async.ca.shared.global [%0], [%1], 16;" :: "r"(s), "l"(g));
}
__device__ __forceinline__ void mma8(float* d, const uint32_t* a, uint32_t b0, uint32_t b1){
    asm volatile("mma.sync.aligned.m16n8k8.row.col.f32.tf32.tf32.f32 "
        "{%0,%1,%2,%3}, {%4,%5,%6,%7}, {%8,%9}, {%0,%1,%2,%3};"
        : "+f"(d[0]), "+f"(d[1]), "+f"(d[2]), "+f"(d[3])
        : "r"(a[0]), "r"(a[1]), "r"(a[2]), "r"(a[3]), "r"(b0), "r"(b1));
}

// ============ conv1x1 GEMM, cp.async 2-stage, optional token-major dual write
// D[m][n] = sum_k A[m][k]*B[n][k]; tile 128x128, BK=32. Raw fp32 -> tf32 mma.
// tokMode: 0 none; 1 full token write tokO[z][n][ (m0+m) ] tld=256;
//          2 qk write: cols (m&127)<64 to tokO[(z*4+(m0>>7))][n][m&127]
#define GEMM_SMEM 73728
__global__ void __launch_bounds__(256, 2) gemm_mma(
    const float* __restrict__ A, int lda,
    const float* __restrict__ B, int ldb, size_t bZs,
    float* __restrict__ O, size_t oZs, int K,
    const float* __restrict__ sc, const float* __restrict__ bi,
    const float* __restrict__ res,
    float* __restrict__ tokO, int tokMode, size_t tZs)
{
    extern __shared__ float smem[];
    const int tid = threadIdx.x, wid = tid >> 5, lane = tid & 31;
    const int m0 = blockIdx.y*128, n0 = blockIdx.x*128, z = blockIdx.z;
    const float* Bp = B + (size_t)z * bZs;
    const int wm = (wid & 3) * 32, wn = (wid >> 2) * 64;
    const int grp = lane >> 2, qid = lane & 3;
    const uint32_t sb = smem_u32(smem);

    float acc[2][8][4];
    #pragma unroll
    for (int mt = 0; mt < 2; mt++)
    #pragma unroll
        for (int nt = 0; nt < 8; nt++)
        #pragma unroll
            for (int r = 0; r < 4; r++) acc[mt][nt][r] = 0.f;

    const int nkc = K >> 5;
    // issue stage: 1024 float4 per operand tile (128 rows x 8)
    auto issue = [&](int i, int st){
        int k0 = i << 5;
        uint32_t abase = sb + st*36864u;
        uint32_t bbase = abase + 18432u;
        #pragma unroll
        for (int idx = tid; idx < 1024; idx += 256) {
            int r = idx >> 3, c4 = (idx & 7) * 4;
            cpasync16(abase + (uint32_t)(r*36 + c4)*4u, A + (size_t)(m0+r)*lda + k0 + c4);
            cpasync16(bbase + (uint32_t)(r*36 + c4)*4u, Bp + (size_t)(n0+r)*ldb + k0 + c4);
        }
        asm volatile("cp.async.commit_group;" ::: "memory");
    };

    issue(0, 0);
    for (int i = 0; i < nkc; i++) {
        if (i + 1 < nkc) { issue(i+1, (i+1)&1); }
        if (i + 1 < nkc) asm volatile("cp.async.wait_group 1;" ::: "memory");
        else             asm volatile("cp.async.wait_group 0;" ::: "memory");
        __syncthreads();
        const uint32_t* As = (const uint32_t*)(smem + (i&1)*9216);
        const uint32_t* Bs = As + 4608;
        #pragma unroll
        for (int ks = 0; ks < 4; ks++) {
            int kk = ks * 8;
            uint32_t a[2][4];
            #pragma unroll
            for (int mt = 0; mt < 2; mt++) {
                int r = wm + mt*16 + grp;
                a[mt][0] = As[r*36 + kk + qid];
                a[mt][1] = As[(r+8)*36 + kk + qid];
                a[mt][2] = As[r*36 + kk + qid + 4];
                a[mt][3] = As[(r+8)*36 + kk + qid + 4];
            }
            #pragma unroll
            for (int nt = 0; nt < 8; nt++) {
                int n = wn + nt*8 + grp;
                uint32_t b0 = Bs[n*36 + kk + qid];
                uint32_t b1 = Bs[n*36 + kk + qid + 4];
                mma8(acc[0][nt], a[0], b0, b1);
                mma8(acc[1][nt], a[1], b0, b1);
            }
        }
        __syncthreads();
    }

    // ---- finalize acc in place (affine + residual) ----
    #pragma unroll
    for (int mt = 0; mt < 2; mt++) {
        #pragma unroll
        for (int half = 0; half < 2; half++) {
            int mg = m0 + wm + mt*16 + grp + half*8;
            float s1 = sc ? sc[mg] : 1.f;
            float b1 = sc ? bi[mg] : 0.f;
            const float* rb = res ? res + (size_t)z*oZs + (size_t)mg*1024 + n0 + wn : nullptr;
            #pragma unroll
            for (int nt = 0; nt < 8; nt++) {
                int c = nt*8 + 2*qid;
                float vx = acc[mt][nt][half*2]   * s1 + b1;
                float vy = acc[mt][nt][half*2+1] * s1 + b1;
                if (rb) { float2 rv = *(const float2*)(rb + c); vx += rv.x; vy += rv.y; }
                acc[mt][nt][half*2]   = vx;
                acc[mt][nt][half*2+1] = vy;
            }
        }
    }
    // ---- channel-major write ----
    #pragma unroll
    for (int mt = 0; mt < 2; mt++) {
        #pragma unroll
        for (int half = 0; half < 2; half++) {
            int mg = m0 + wm + mt*16 + grp + half*8;
            float* ob = O + (size_t)z*oZs + (size_t)mg*1024 + n0 + wn;
            #pragma unroll
            for (int nt = 0; nt < 8; nt++) {
                int c = nt*8 + 2*qid;
                float2 v; v.x = acc[mt][nt][half*2]; v.y = acc[mt][nt][half*2+1];
                *(float2*)(ob + c) = v;
            }
        }
    }
    // ---- optional token-major dual write via smem stage ----
    if (tokMode) {
        const int tS = (tokMode == 2) ? 68 : 132;
        float* Ts = smem;
        for (int nh = 0; nh < 2; nh++) {
            if ((wid >> 2) == nh && (tokMode == 1 || wm < 64)) {
                #pragma unroll
                for (int mt = 0; mt < 2; mt++)
                #pragma unroll
                    for (int hh = 0; hh < 2; hh++) {
                        int ml = wm + mt*16 + grp + hh*8;
                        #pragma unroll
                        for (int nt = 0; nt < 8; nt++) {
                            int r = nt*8 + 2*qid;
                            Ts[r*tS + ml]     = acc[mt][nt][hh*2];
                            Ts[(r+1)*tS + ml] = acc[mt][nt][hh*2+1];
                        }
                    }
            }
            __syncthreads();
            if (tokMode == 1) {
                float* dst = tokO + (size_t)z*tZs + (size_t)(n0 + nh*64)*256 + m0;
                #pragma unroll
                for (int idx = tid; idx < 2048; idx += 256) {
                    int r = idx >> 5, c4 = (idx & 31) * 4;
                    float4 v = *(float4*)&Ts[r*tS + c4];
                    *(float4*)(dst + (size_t)r*256 + c4) = v;
                }
            } else {
                float* dst = tokO + ((size_t)(z*4 + (m0 >> 7))*1024 + n0 + nh*64)*64;
                #pragma unroll
                for (int idx = tid; idx < 1024; idx += 256) {
                    int r = idx >> 4, c4 = (idx & 15) * 4;
                    float4 v = *(float4*)&Ts[r*tS + c4];
                    *(float4*)(dst + r*64 + c4) = v;
                }
            }
            __syncthreads();
        }
    }
}

// ============ 32x32 tiled transpose (only for input x) ============
__global__ void transpose_kernel(const float* __restrict__ src, float* __restrict__ dst,
                                 size_t sStr, size_t dStr, int R, int C)
{
    __shared__ float t[32][33];
    const float* s = src + (size_t)blockIdx.z * sStr;
    float* d = dst + (size_t)blockIdx.z * dStr;
    int c0 = blockIdx.x*32, r0 = blockIdx.y*32;
    int tx = threadIdx.x, ty = threadIdx.y;
    #pragma unroll
    for (int k = 0; k < 32; k += 8)
        t[ty+k][tx] = s[(size_t)(r0+ty+k)*C + c0+tx];
    __syncthreads();
    #pragma unroll
    for (int k = 0; k < 32; k += 8)
        d[(size_t)(c0+ty+k)*R + r0+tx] = t[tx][ty+k];
}

// ============ flash attention -> token-major out ============
#define FA_SMEM 138240
__global__ void __launch_bounds__(256, 1) flash_kernel(
    const float* __restrict__ qkT, const float* __restrict__ qkv,
    float* __restrict__ attoT)
{
    extern __shared__ float sm[];
    float* Qs = sm;             // [128][36]
    float* Ks = sm + 4608;      // [128][36]
    float* Vs = sm + 9216;      // [64][132]
    float* Ps = sm + 17664;     // [128][132] (also epilogue stage [128][68])
    const int tid = threadIdx.x, wid = tid >> 5, lane = tid & 31;
    const int grp = lane >> 2, qid = lane & 3;
    const int m0 = blockIdx.x * 128, bh = blockIdx.y;
    const int b = bh >> 2, h = bh & 3;
    const int wq = wid * 16;
    const float* qbase = qkT + ((size_t)bh*1024 + m0)*64;
    const float* vbase = qkv + (size_t)b*524288 + (size_t)(h*128+64)*1024;

    #pragma unroll
    for (int idx = tid; idx < 1024; idx += 256) {
        int r = idx >> 3, c4 = (idx & 7) * 4;
        float4 v = *(const float4*)(qbase + r*64 + c4);
        uint32_t* d = (uint32_t*)&Qs[r*36 + c4];
        const float s = 0.17677669529663687f;
        d[0]=tf32c(v.x*s); d[1]=tf32c(v.y*s); d[2]=tf32c(v.z*s); d[3]=tf32c(v.w*s);
    }

    float m_i[2] = {-1e30f, -1e30f};
    float l_i[2] = {0.f, 0.f};
    float ao[8][4];
    #pragma unroll
    for (int dt = 0; dt < 8; dt++) { ao[dt][0]=0; ao[dt][1]=0; ao[dt][2]=0; ao[dt][3]=0; }

    for (int kc = 0; kc < 8; kc++) {
        const float* kb = qkT + ((size_t)bh*1024 + kc*128)*64 + 32;
        #pragma unroll
        for (int idx = tid; idx < 1024; idx += 256) {
            int r = idx >> 3, c4 = (idx & 7) * 4;
            float4 v = *(const float4*)(kb + r*64 + c4);
            uint32_t* d = (uint32_t*)&Ks[r*36 + c4];
            d[0]=tf32c(v.x); d[1]=tf32c(v.y); d[2]=tf32c(v.z); d[3]=tf32c(v.w);
        }
        const float* vb = vbase + kc*128;
        #pragma unroll
        for (int idx = tid; idx < 2048; idx += 256) {
            int dd = idx >> 5, c4 = (idx & 31) * 4;
            float4 v = *(const float4*)(vb + (size_t)dd*1024 + c4);
            uint32_t* dp = (uint32_t*)&Vs[dd*132 + c4];
            dp[0]=tf32c(v.x); dp[1]=tf32c(v.y); dp[2]=tf32c(v.z); dp[3]=tf32c(v.w);
        }
        __syncthreads();

        float sacc[16][4];
        #pragma unroll
        for (int nt = 0; nt < 16; nt++) { sacc[nt][0]=0; sacc[nt][1]=0; sacc[nt][2]=0; sacc[nt][3]=0; }
        const uint32_t* Qu = (const uint32_t*)Qs;
        const uint32_t* Ku = (const uint32_t*)Ks;
        #pragma unroll
        for (int ks = 0; ks < 4; ks++) {
            int kk = ks * 8;
            uint32_t a[4];
            a[0] = Qu[(wq+grp)*36 + kk + qid];
            a[1] = Qu[(wq+grp+8)*36 + kk + qid];
            a[2] = Qu[(wq+grp)*36 + kk + qid + 4];
            a[3] = Qu[(wq+grp+8)*36 + kk + qid + 4];
            #pragma unroll
            for (int nt = 0; nt < 16; nt++) {
                uint32_t b0 = Ku[(nt*8+grp)*36 + kk + qid];
                uint32_t b1 = Ku[(nt*8+grp)*36 + kk + qid + 4];
                mma8(sacc[nt], a, b0, b1);
            }
        }
        float mx0 = -1e30f, mx1 = -1e30f;
        #pragma unroll
        for (int nt = 0; nt < 16; nt++) {
            mx0 = fmaxf(mx0, fmaxf(sacc[nt][0], sacc[nt][1]));
            mx1 = fmaxf(mx1, fmaxf(sacc[nt][2], sacc[nt][3]));
        }
        mx0 = fmaxf(mx0, __shfl_xor_sync(0xffffffffu, mx0, 1));
        mx0 = fmaxf(mx0, __shfl_xor_sync(0xffffffffu, mx0, 2));
        mx1 = fmaxf(mx1, __shfl_xor_sync(0xffffffffu, mx1, 1));
        mx1 = fmaxf(mx1, __shfl_xor_sync(0xffffffffu, mx1, 2));
        float mn0 = fmaxf(m_i[0], mx0), mn1 = fmaxf(m_i[1], mx1);
        float s0 = 0.f, s1 = 0.f;
        #pragma unroll
        for (int nt = 0; nt < 16; nt++) {
            sacc[nt][0] = __expf(sacc[nt][0] - mn0);
            sacc[nt][1] = __expf(sacc[nt][1] - mn0);
            sacc[nt][2] = __expf(sacc[nt][2] - mn1);
            sacc[nt][3] = __expf(sacc[nt][3] - mn1);
            s0 += sacc[nt][0] + sacc[nt][1];
            s1 += sacc[nt][2] + sacc[nt][3];
        }
        s0 += __shfl_xor_sync(0xffffffffu, s0, 1);
        s0 += __shfl_xor_sync(0xffffffffu, s0, 2);
        s1 += __shfl_xor_sync(0xffffffffu, s1, 1);
        s1 += __shfl_xor_sync(0xffffffffu, s1, 2);
        float al0 = __expf(m_i[0] - mn0), al1 = __expf(m_i[1] - mn1);
        l_i[0] = l_i[0]*al0 + s0; l_i[1] = l_i[1]*al1 + s1;
        m_i[0] = mn0; m_i[1] = mn1;
        #pragma unroll
        for (int dt = 0; dt < 8; dt++) {
            ao[dt][0] *= al0; ao[dt][1] *= al0;
            ao[dt][2] *= al1; ao[dt][3] *= al1;
        }
        #pragma unroll
        for (int nt = 0; nt < 16; nt++) {
            Ps[(wq+grp)*132 + nt*8 + 2*qid]     = sacc[nt][0];
            Ps[(wq+grp)*132 + nt*8 + 2*qid+1]   = sacc[nt][1];
            Ps[(wq+grp+8)*132 + nt*8 + 2*qid]   = sacc[nt][2];
            Ps[(wq+grp+8)*132 + nt*8 + 2*qid+1] = sacc[nt][3];
        }
        __syncwarp();
        const uint32_t* Pu = (const uint32_t*)Ps;
        const uint32_t* Vu = (const uint32_t*)Vs;
        #pragma unroll
        for (int ks = 0; ks < 16; ks++) {
            int kk = ks * 8;
            uint32_t a[4];
            a[0] = Pu[(wq+grp)*132 + kk + qid];
            a[1] = Pu[(wq+grp+8)*132 + kk + qid];
            a[2] = Pu[(wq+grp)*132 + kk + qid + 4];
            a[3] = Pu[(wq+grp+8)*132 + kk + qid + 4];
            #pragma unroll
            for (int dt = 0; dt < 8; dt++) {
                uint32_t b0 = Vu[(dt*8+grp)*132 + kk + qid];
                uint32_t b1 = Vu[(dt*8+grp)*132 + kk + qid + 4];
                mma8(ao[dt], a, b0, b1);
            }
        }
        __syncthreads();
    }
    // epilogue: normalize, stage [q][68], token-major write
    float inv0 = 1.f / l_i[0], inv1 = 1.f / l_i[1];
    #pragma unroll
    for (int dt = 0; dt < 8; dt++) {
        int d0 = dt*8 + 2*qid;
        Ps[(wq+grp)*68 + d0]       = ao[dt][0]*inv0;
        Ps[(wq+grp)*68 + d0+1]     = ao[dt][1]*inv0;
        Ps[(wq+grp+8)*68 + d0]     = ao[dt][2]*inv1;
        Ps[(wq+grp+8)*68 + d0+1]   = ao[dt][3]*inv1;
    }
    __syncthreads();
    #pragma unroll
    for (int idx = tid; idx < 2048; idx += 256) {
        int q = idx >> 4, c4 = (idx & 15) * 4;
        float4 v = *(float4*)&Ps[q*68 + c4];
        *(float4*)(attoT + ((size_t)(b*1024 + m0 + q))*256 + h*64 + c4) = v;
    }
}

// ============ PE depthwise conv, accumulate token-major ============
__global__ void pe_tok(const float* __restrict__ qkv, const float* __restrict__ w,
                       const float* __restrict__ s, const float* __restrict__ bb,
                       float* __restrict__ attoT)
{
    __shared__ float sv[3][32][33];
    int row = blockIdx.x, ct = blockIdx.y, b = blockIdx.z, tid = threadIdx.x;
    for (int idx = tid; idx < 3072; idx += 256) {
        int rr = idx >> 10, c = (idx >> 5) & 31, w2 = idx & 31;
        int r = row + rr - 1;
        int cg = ct*32 + c;
        int cin = (cg >> 6)*128 + 64 + (cg & 63);
        float v = 0.f;
        if ((unsigned)r < 32u) v = qkv[((size_t)b*512 + cin)*1024 + r*32 + w2];
        sv[rr][c][w2] = v;
    }
    __syncthreads();
    int w2 = tid >> 3, cb = (tid & 7) * 4;
    float o[4];
    #pragma unroll
    for (int j = 0; j < 4; j++) {
        int c = cb + j, cg = ct*32 + c;
        const float* wp = w + cg*9;
        float acc = 0.f;
        #pragma unroll
        for (int rr = 0; rr < 3; rr++)
        #pragma unroll
            for (int dx = -1; dx <= 1; dx++) {
                int ww = w2 + dx;
                if ((unsigned)ww < 32u) acc += sv[rr][c][ww] * wp[rr*3 + dx + 1];
            }
        o[j] = acc * s[cg] + bb[cg];
    }
    size_t base = ((size_t)b*1024 + row*32 + w2)*256 + ct*32 + cb;
    float4 old = *(float4*)(attoT + base);
    old.x += o[0]; old.y += o[1]; old.z += o[2]; old.w += o[3];
    *(float4*)(attoT + base) = old;
}

// ============ fused GELU-gate + transpose -> token-major hid ============
__global__ void gatetrans(const float* __restrict__ dwb, float* __restrict__ hidT)
{
    __shared__ float t[32][33];
    int nt = blockIdx.x, ct = blockIdx.y, b = blockIdx.z, tid = threadIdx.x;
    int cl = tid >> 5, nl = tid & 31;
    #pragma unroll
    for (int k = 0; k < 32; k += 8) {
        int cc = cl + k;
        size_t i1 = ((size_t)b*1024 + ct*32 + cc)*1024 + nt*32 + nl;
        float y1 = dwb[i1];
        float y2 = dwb[i1 + (size_t)512*1024];
        float g = 0.5f * y1 * (1.f + erff(y1 * 0.70710678118654752f));
        t[nl][cc] = g * y2;
    }
    __syncthreads();
    #pragma unroll
    for (int k = 0; k < 32; k += 8) {
        int n2 = cl + k;
        hidT[((size_t)b*1024 + nt*32 + n2)*512 + ct*32 + nl] = t[n2][nl];
    }
}

// ============ dwconv3x3 (pin -> dwb, channel-major) ============
__global__ void dwconv_kernel(const float* __restrict__ in, const float* __restrict__ w,
                              float* __restrict__ out)
{
    int idx = blockIdx.x * blockDim.x + threadIdx.x;
    if (idx >= NB * C2 * 1024) return;
    int xw = idx & 31, yh = (idx >> 5) & 31;
    int c = (idx >> 10) % C2;
    const float* ip = in + ((size_t)(idx >> 10)) * 1024;
    const float* wp = w + c * 9;
    float s = 0.f;
    #pragma unroll
    for (int dy = -1; dy <= 1; dy++) {
        int yy = yh + dy; if ((unsigned)yy >= 32u) continue;
        #pragma unroll
        for (int dx = -1; dx <= 1; dx++) {
            int xx = xw + dx; if ((unsigned)xx >= 32u) continue;
            s += ip[yy*32 + xx] * wp[(dy+1)*3 + dx + 1];
        }
    }
    out[idx] = s;
}

// ============ FFT filter -> 8x8 circular-conv kernel ============
__global__ void fft_g_kernel(const float* __restrict__ filt, float* __restrict__ g)
{
    const float ct[8] = {1.f, 0.70710678118654752f, 0.f, -0.70710678118654752f,
                         -1.f, -0.70710678118654752f, 0.f, 0.70710678118654752f};
    int c = blockIdx.x, t = threadIdx.x;
    int a = t >> 3, bb = t & 7;
    float s = 0.f;
    for (int k1 = 0; k1 < 8; k1++)
        for (int k2 = 0; k2 < 8; k2++) {
            float F = (k2 <= 4) ? filt[c*40 + k1*5 + k2]
                                : filt[c*40 + ((8-k1)&7)*5 + (8-k2)];
            s += F * ct[(k1*a + k2*bb) & 7];
        }
    g[c*64 + t] = s * (1.f/64.f);
}

__global__ void fft_apply_kernel(const float* __restrict__ y, const float* __restrict__ g,
                                 const float* __restrict__ xnew, float* __restrict__ out)
{
    __shared__ float ys[1024];
    __shared__ float gs[64];
    int bc = blockIdx.x, c = bc % 256;
    const float* yp = y + (size_t)bc * 1024;
    int tid = threadIdx.x;
    for (int i = tid; i < 1024; i += 256) ys[i] = yp[i];
    if (tid < 64) gs[tid] = g[c*64 + tid];
    __syncthreads();
    for (int i = tid; i < 1024; i += 256) {
        int u = i >> 5, v = i & 31;
        int bu = u & ~7, bv = v & ~7, uu = u & 7, vv = v & 7;
        float s = 0.f;
        #pragma unroll
        for (int a = 0; a < 8; a++) {
            const float* yr = &ys[(bu + a)*32 + bv];
            const float* gr = &gs[((uu - a) & 7) * 8];
            #pragma unroll
            for (int b2 = 0; b2 < 8; b2++)
                s += gr[(vv - b2) & 7] * yr[b2];
        }
        size_t oi = (size_t)bc * 1024 + i;
        out[oi] = xnew[oi] + s;
    }
}

// =========================================================================
extern "C" void kernel_launch(void* const* d_in, const int* in_sizes, int n_in,
                              void* d_out, int out_size)
{
    const float* x      = (const float*)d_in[0];
    const float* qkv_w  = (const float*)d_in[1];
    const float* qkv_s  = (const float*)d_in[2];
    const float* qkv_b  = (const float*)d_in[3];
    const float* pe_w   = (const float*)d_in[4];
    const float* pe_s   = (const float*)d_in[5];
    const float* pe_b   = (const float*)d_in[6];
    const float* proj_w = (const float*)d_in[7];
    const float* proj_s = (const float*)d_in[8];
    const float* proj_b = (const float*)d_in[9];
    const float* pin_w  = (const float*)d_in[10];
    const float* dw_w   = (const float*)d_in[11];
    const float* ff     = (const float*)d_in[12];
    const float* pout_w = (const float*)d_in[13];
    float* out = (float*)d_out;

    float *qkv, *qkT, *xT, *attoT, *xnew, *xnewT, *pin, *dwb, *hidT, *yout, *gtab;
    cudaGetSymbolAddress((void**)&qkv,   g_qkv);
    cudaGetSymbolAddress((void**)&qkT,   g_qkT);
    cudaGetSymbolAddress((void**)&xT,    g_xT);
    cudaGetSymbolAddress((void**)&attoT, g_attoT);
    cudaGetSymbolAddress((void**)&xnew,  g_xnew);
    cudaGetSymbolAddress((void**)&xnewT, g_xnewT);
    cudaGetSymbolAddress((void**)&pin,   g_pin);
    cudaGetSymbolAddress((void**)&dwb,   g_dw);
    cudaGetSymbolAddress((void**)&hidT,  g_hidT);
    cudaGetSymbolAddress((void**)&yout,  g_yout);
    cudaGetSymbolAddress((void**)&gtab,  g_g);

    cudaFuncSetAttribute(flash_kernel, cudaFuncAttributeMaxDynamicSharedMemorySize, FA_SMEM);
    cudaFuncSetAttribute(gemm_mma, cudaFuncAttributeMaxDynamicSharedMemorySize, GEMM_SMEM);
    dim3 tb(32, 8);

    // 1. xT = transpose(x)
    transpose_kernel<<<dim3(32, 8, 16), tb>>>(x, xT, 262144, 262144, 256, 1024);
    // 2. qkv gemm -> qkv cm + qkT token (mode 2)
    gemm_mma<<<dim3(8,4,16), 256, GEMM_SMEM>>>(qkv_w, 256, xT, 256, (size_t)262144,
        qkv, (size_t)524288, 256, qkv_s, qkv_b, nullptr, qkT, 2, 0);
    // 3. flash attention -> attoT token-major
    flash_kernel<<<dim3(8, 64), 256, FA_SMEM>>>(qkT, qkv, attoT);
    // 4. PE conv accumulate into attoT
    pe_tok<<<dim3(32, 8, 16), 256>>>(qkv, pe_w, pe_s, pe_b, attoT);
    // 5. proj gemm -> xnew cm (+x residual) + xnewT token (mode 1)
    gemm_mma<<<dim3(8,2,16), 256, GEMM_SMEM>>>(proj_w, 256, attoT, 256, (size_t)262144,
        xnew, (size_t)262144, 256, proj_s, proj_b, x, xnewT, 1, (size_t)262144);
    // 6. pin gemm -> pin cm
    gemm_mma<<<dim3(8,8,16), 256, GEMM_SMEM>>>(pin_w, 256, xnewT, 256, (size_t)262144,
        pin, (size_t)1048576, 256, nullptr, nullptr, nullptr, nullptr, 0, 0);
    // 7. dwconv
    dwconv_kernel<<<(NB*C2*1024+255)/256, 256>>>(pin, dw_w, dwb);
    // 8. gate + transpose -> hidT
    gatetrans<<<dim3(32, 16, 16), 256>>>(dwb, hidT);
    // 9. pout gemm -> yout cm
    gemm_mma<<<dim3(8,2,16), 256, GEMM_SMEM>>>(pout_w, 512, hidT, 512, (size_t)524288,
        yout, (size_t)262144, 512, nullptr, nullptr, nullptr, nullptr, 0, 0);
    // 10. fft
    fft_g_kernel<<<C_, 64>>>(ff, gtab);
    fft_apply_kernel<<<NB*C_, 256>>>(yout, gtab, xnew, out);
}

// round 7
// speedup vs baseline: 3.8688x; 1.0299x over previous
#include <cuda_runtime.h>
#include <math.h>
#include <stdint.h>

#define NB 16
#define C_ 256
#define N_ 1024
#define C2 1024
#define HID 512

__device__ float g_qkv  [(size_t)NB*512*1024];   // channel-major qkv (V used)
__device__ float g_qkT  [(size_t)64*1024*64];    // [bh][n][64] Q(0-31),K(32-63)
__device__ float g_xT   [(size_t)NB*1024*256];
__device__ float g_attoT[(size_t)NB*1024*256];   // token-major attn+pe
__device__ float g_xnew [(size_t)NB*256*1024];   // channel-major (fft residual)
__device__ float g_xnewT[(size_t)NB*1024*256];
__device__ float g_pin  [(size_t)NB*1024*1024];
__device__ float g_dw   [(size_t)NB*1024*1024];
__device__ float g_hidT [(size_t)NB*1024*512];
__device__ float g_yout [(size_t)NB*256*1024];
__device__ float g_g    [C_*64];

__device__ __forceinline__ uint32_t tf32c(float f){
    uint32_t u; asm("cvt.rna.tf32.f32 %0, %1;" : "=r"(u) : "f"(f)); return u;
}
__device__ __forceinline__ uint32_t smem_u32(const void* p){
    uint32_t a;
    asm("{ .reg .u64 t; cvta.to.shared.u64 t, %1; cvt.u32.u64 %0, t; }" : "=r"(a) : "l"(p));
    return a;
}
__device__ __forceinline__ void cpasync16(uint32_t s, const void* g){
    asm volatile("cp.async.ca.shared.global [%0], [%1], 16;" :: "r"(s), "l"(g));
}
__device__ __forceinline__ void mma8(float* d, const uint32_t* a, uint32_t b0, uint32_t b1){
    asm volatile("mma.sync.aligned.m16n8k8.row.col.f32.tf32.tf32.f32 "
        "{%0,%1,%2,%3}, {%4,%5,%6,%7}, {%8,%9}, {%0,%1,%2,%3};"
        : "+f"(d[0]), "+f"(d[1]), "+f"(d[2]), "+f"(d[3])
        : "r"(a[0]), "r"(a[1]), "r"(a[2]), "r"(a[3]), "r"(b0), "r"(b1));
}

// ============ conv1x1 GEMM, cp.async 2-stage, optional token-major dual write
#define GEMM_SMEM 73728
__global__ void __launch_bounds__(256, 2) gemm_mma(
    const float* __restrict__ A, int lda,
    const float* __restrict__ B, int ldb, size_t bZs,
    float* __restrict__ O, size_t oZs, int K,
    const float* __restrict__ sc, const float* __restrict__ bi,
    const float* __restrict__ res,
    float* __restrict__ tokO, int tokMode, size_t tZs)
{
    extern __shared__ float smem[];
    const int tid = threadIdx.x, wid = tid >> 5, lane = tid & 31;
    const int m0 = blockIdx.y*128, n0 = blockIdx.x*128, z = blockIdx.z;
    const float* Bp = B + (size_t)z * bZs;
    const int wm = (wid & 3) * 32, wn = (wid >> 2) * 64;
    const int grp = lane >> 2, qid = lane & 3;
    const uint32_t sb = smem_u32(smem);

    float acc[2][8][4];
    #pragma unroll
    for (int mt = 0; mt < 2; mt++)
    #pragma unroll
        for (int nt = 0; nt < 8; nt++)
        #pragma unroll
            for (int r = 0; r < 4; r++) acc[mt][nt][r] = 0.f;

    const int nkc = K >> 5;
    auto issue = [&](int i, int st){
        int k0 = i << 5;
        uint32_t abase = sb + st*36864u;
        uint32_t bbase = abase + 18432u;
        #pragma unroll
        for (int idx = tid; idx < 1024; idx += 256) {
            int r = idx >> 3, c4 = (idx & 7) * 4;
            cpasync16(abase + (uint32_t)(r*36 + c4)*4u, A + (size_t)(m0+r)*lda + k0 + c4);
            cpasync16(bbase + (uint32_t)(r*36 + c4)*4u, Bp + (size_t)(n0+r)*ldb + k0 + c4);
        }
        asm volatile("cp.async.commit_group;" ::: "memory");
    };

    issue(0, 0);
    for (int i = 0; i < nkc; i++) {
        if (i + 1 < nkc) { issue(i+1, (i+1)&1); }
        if (i + 1 < nkc) asm volatile("cp.async.wait_group 1;" ::: "memory");
        else             asm volatile("cp.async.wait_group 0;" ::: "memory");
        __syncthreads();
        const uint32_t* As = (const uint32_t*)(smem + (i&1)*9216);
        const uint32_t* Bs = As + 4608;
        #pragma unroll
        for (int ks = 0; ks < 4; ks++) {
            int kk = ks * 8;
            uint32_t a[2][4];
            #pragma unroll
            for (int mt = 0; mt < 2; mt++) {
                int r = wm + mt*16 + grp;
                a[mt][0] = As[r*36 + kk + qid];
                a[mt][1] = As[(r+8)*36 + kk + qid];
                a[mt][2] = As[r*36 + kk + qid + 4];
                a[mt][3] = As[(r+8)*36 + kk + qid + 4];
            }
            #pragma unroll
            for (int nt = 0; nt < 8; nt++) {
                int n = wn + nt*8 + grp;
                uint32_t b0 = Bs[n*36 + kk + qid];
                uint32_t b1 = Bs[n*36 + kk + qid + 4];
                mma8(acc[0][nt], a[0], b0, b1);
                mma8(acc[1][nt], a[1], b0, b1);
            }
        }
        __syncthreads();
    }

    #pragma unroll
    for (int mt = 0; mt < 2; mt++) {
        #pragma unroll
        for (int half = 0; half < 2; half++) {
            int mg = m0 + wm + mt*16 + grp + half*8;
            float s1 = sc ? sc[mg] : 1.f;
            float b1 = sc ? bi[mg] : 0.f;
            const float* rb = res ? res + (size_t)z*oZs + (size_t)mg*1024 + n0 + wn : nullptr;
            #pragma unroll
            for (int nt = 0; nt < 8; nt++) {
                int c = nt*8 + 2*qid;
                float vx = acc[mt][nt][half*2]   * s1 + b1;
                float vy = acc[mt][nt][half*2+1] * s1 + b1;
                if (rb) { float2 rv = *(const float2*)(rb + c); vx += rv.x; vy += rv.y; }
                acc[mt][nt][half*2]   = vx;
                acc[mt][nt][half*2+1] = vy;
            }
        }
    }
    #pragma unroll
    for (int mt = 0; mt < 2; mt++) {
        #pragma unroll
        for (int half = 0; half < 2; half++) {
            int mg = m0 + wm + mt*16 + grp + half*8;
            float* ob = O + (size_t)z*oZs + (size_t)mg*1024 + n0 + wn;
            #pragma unroll
            for (int nt = 0; nt < 8; nt++) {
                int c = nt*8 + 2*qid;
                float2 v; v.x = acc[mt][nt][half*2]; v.y = acc[mt][nt][half*2+1];
                *(float2*)(ob + c) = v;
            }
        }
    }
    if (tokMode) {
        const int tS = (tokMode == 2) ? 68 : 132;
        float* Ts = smem;
        for (int nh = 0; nh < 2; nh++) {
            if ((wid >> 2) == nh && (tokMode == 1 || wm < 64)) {
                #pragma unroll
                for (int mt = 0; mt < 2; mt++)
                #pragma unroll
                    for (int hh = 0; hh < 2; hh++) {
                        int ml = wm + mt*16 + grp + hh*8;
                        #pragma unroll
                        for (int nt = 0; nt < 8; nt++) {
                            int r = nt*8 + 2*qid;
                            Ts[r*tS + ml]     = acc[mt][nt][hh*2];
                            Ts[(r+1)*tS + ml] = acc[mt][nt][hh*2+1];
                        }
                    }
            }
            __syncthreads();
            if (tokMode == 1) {
                float* dst = tokO + (size_t)z*tZs + (size_t)(n0 + nh*64)*256 + m0;
                #pragma unroll
                for (int idx = tid; idx < 2048; idx += 256) {
                    int r = idx >> 5, c4 = (idx & 31) * 4;
                    float4 v = *(float4*)&Ts[r*tS + c4];
                    *(float4*)(dst + (size_t)r*256 + c4) = v;
                }
            } else {
                float* dst = tokO + ((size_t)(z*4 + (m0 >> 7))*1024 + n0 + nh*64)*64;
                #pragma unroll
                for (int idx = tid; idx < 1024; idx += 256) {
                    int r = idx >> 4, c4 = (idx & 15) * 4;
                    float4 v = *(float4*)&Ts[r*tS + c4];
                    *(float4*)(dst + r*64 + c4) = v;
                }
            }
            __syncthreads();
        }
    }
}

// ============ 32x32 tiled transpose (input x only) ============
__global__ void transpose_kernel(const float* __restrict__ src, float* __restrict__ dst,
                                 size_t sStr, size_t dStr, int R, int C)
{
    __shared__ float t[32][33];
    const float* s = src + (size_t)blockIdx.z * sStr;
    float* d = dst + (size_t)blockIdx.z * dStr;
    int c0 = blockIdx.x*32, r0 = blockIdx.y*32;
    int tx = threadIdx.x, ty = threadIdx.y;
    #pragma unroll
    for (int k = 0; k < 32; k += 8)
        t[ty+k][tx] = s[(size_t)(r0+ty+k)*C + c0+tx];
    __syncthreads();
    #pragma unroll
    for (int k = 0; k < 32; k += 8)
        d[(size_t)(c0+ty+k)*R + r0+tx] = t[tx][ty+k];
}

// ============ flash attention v2: no P smem, 2 CTAs/SM ============
#define FA_SMEM 70656
__global__ void __launch_bounds__(256, 2) flash_kernel(
    const float* __restrict__ qkT, const float* __restrict__ qkv,
    float* __restrict__ attoT)
{
    extern __shared__ float sm[];
    float* Qs = sm;             // [128][36]
    float* Ks = sm + 4608;      // [128][36]
    float* Vs = sm + 9216;      // [64][132]
    const int tid = threadIdx.x, wid = tid >> 5, lane = tid & 31;
    const int grp = lane >> 2, qid = lane & 3;
    const int lanebase = lane & ~3, odd = qid & 1;
    const int src1 = lanebase + (qid >> 1), src2 = src1 + 2;
    const int m0 = blockIdx.x * 128, bh = blockIdx.y;
    const int b = bh >> 2, h = bh & 3;
    const int wq = wid * 16;
    const float* qbase = qkT + ((size_t)bh*1024 + m0)*64;
    const float* vbase = qkv + (size_t)b*524288 + (size_t)(h*128+64)*1024;

    #pragma unroll
    for (int idx = tid; idx < 1024; idx += 256) {
        int r = idx >> 3, c4 = (idx & 7) * 4;
        float4 v = *(const float4*)(qbase + r*64 + c4);
        uint32_t* d = (uint32_t*)&Qs[r*36 + c4];
        const float s = 0.17677669529663687f;
        d[0]=tf32c(v.x*s); d[1]=tf32c(v.y*s); d[2]=tf32c(v.z*s); d[3]=tf32c(v.w*s);
    }

    float m_i[2] = {-1e30f, -1e30f};
    float l_i[2] = {0.f, 0.f};
    float ao[8][4];
    #pragma unroll
    for (int dt = 0; dt < 8; dt++) { ao[dt][0]=0; ao[dt][1]=0; ao[dt][2]=0; ao[dt][3]=0; }

    for (int kc = 0; kc < 8; kc++) {
        const float* kb = qkT + ((size_t)bh*1024 + kc*128)*64 + 32;
        #pragma unroll
        for (int idx = tid; idx < 1024; idx += 256) {
            int r = idx >> 3, c4 = (idx & 7) * 4;
            float4 v = *(const float4*)(kb + r*64 + c4);
            uint32_t* d = (uint32_t*)&Ks[r*36 + c4];
            d[0]=tf32c(v.x); d[1]=tf32c(v.y); d[2]=tf32c(v.z); d[3]=tf32c(v.w);
        }
        const float* vb = vbase + kc*128;
        #pragma unroll
        for (int idx = tid; idx < 2048; idx += 256) {
            int dd = idx >> 5, c4 = (idx & 31) * 4;
            float4 v = *(const float4*)(vb + (size_t)dd*1024 + c4);
            uint32_t* dp = (uint32_t*)&Vs[dd*132 + c4];
            dp[0]=tf32c(v.x); dp[1]=tf32c(v.y); dp[2]=tf32c(v.z); dp[3]=tf32c(v.w);
        }
        __syncthreads();

        const uint32_t* Qu = (const uint32_t*)Qs;
        const uint32_t* Ku = (const uint32_t*)Ks;
        const uint32_t* Vu = (const uint32_t*)Vs;

        #pragma unroll
        for (int half = 0; half < 2; half++) {
            float sacc[8][4];
            #pragma unroll
            for (int nt = 0; nt < 8; nt++) { sacc[nt][0]=0; sacc[nt][1]=0; sacc[nt][2]=0; sacc[nt][3]=0; }
            #pragma unroll
            for (int ks = 0; ks < 4; ks++) {
                int kk = ks * 8;
                uint32_t a[4];
                a[0] = Qu[(wq+grp)*36 + kk + qid];
                a[1] = Qu[(wq+grp+8)*36 + kk + qid];
                a[2] = Qu[(wq+grp)*36 + kk + qid + 4];
                a[3] = Qu[(wq+grp+8)*36 + kk + qid + 4];
                #pragma unroll
                for (int nt = 0; nt < 8; nt++) {
                    int n = half*64 + nt*8 + grp;
                    uint32_t b0 = Ku[n*36 + kk + qid];
                    uint32_t b1 = Ku[n*36 + kk + qid + 4];
                    mma8(sacc[nt], a, b0, b1);
                }
            }
            // online softmax over this 64-key half
            float mx0 = -1e30f, mx1 = -1e30f;
            #pragma unroll
            for (int nt = 0; nt < 8; nt++) {
                mx0 = fmaxf(mx0, fmaxf(sacc[nt][0], sacc[nt][1]));
                mx1 = fmaxf(mx1, fmaxf(sacc[nt][2], sacc[nt][3]));
            }
            mx0 = fmaxf(mx0, __shfl_xor_sync(0xffffffffu, mx0, 1));
            mx0 = fmaxf(mx0, __shfl_xor_sync(0xffffffffu, mx0, 2));
            mx1 = fmaxf(mx1, __shfl_xor_sync(0xffffffffu, mx1, 1));
            mx1 = fmaxf(mx1, __shfl_xor_sync(0xffffffffu, mx1, 2));
            float mn0 = fmaxf(m_i[0], mx0), mn1 = fmaxf(m_i[1], mx1);
            float s0 = 0.f, s1 = 0.f;
            #pragma unroll
            for (int nt = 0; nt < 8; nt++) {
                sacc[nt][0] = __expf(sacc[nt][0] - mn0);
                sacc[nt][1] = __expf(sacc[nt][1] - mn0);
                sacc[nt][2] = __expf(sacc[nt][2] - mn1);
                sacc[nt][3] = __expf(sacc[nt][3] - mn1);
                s0 += sacc[nt][0] + sacc[nt][1];
                s1 += sacc[nt][2] + sacc[nt][3];
            }
            s0 += __shfl_xor_sync(0xffffffffu, s0, 1);
            s0 += __shfl_xor_sync(0xffffffffu, s0, 2);
            s1 += __shfl_xor_sync(0xffffffffu, s1, 1);
            s1 += __shfl_xor_sync(0xffffffffu, s1, 2);
            float al0 = __expf(m_i[0] - mn0), al1 = __expf(m_i[1] - mn1);
            l_i[0] = l_i[0]*al0 + s0; l_i[1] = l_i[1]*al1 + s1;
            m_i[0] = mn0; m_i[1] = mn1;
            #pragma unroll
            for (int dt = 0; dt < 8; dt++) {
                ao[dt][0] *= al0; ao[dt][1] *= al0;
                ao[dt][2] *= al1; ao[dt][3] *= al1;
            }
            // PV with in-register P fragment conversion (quad butterfly)
            #pragma unroll
            for (int ks2 = 0; ks2 < 8; ks2++) {
                float p00 = __shfl_sync(0xffffffffu, sacc[ks2][0], src1);
                float p01 = __shfl_sync(0xffffffffu, sacc[ks2][1], src1);
                float p10 = __shfl_sync(0xffffffffu, sacc[ks2][2], src1);
                float p11 = __shfl_sync(0xffffffffu, sacc[ks2][3], src1);
                float q00 = __shfl_sync(0xffffffffu, sacc[ks2][0], src2);
                float q01 = __shfl_sync(0xffffffffu, sacc[ks2][1], src2);
                float q10 = __shfl_sync(0xffffffffu, sacc[ks2][2], src2);
                float q11 = __shfl_sync(0xffffffffu, sacc[ks2][3], src2);
                uint32_t a[4];
                a[0] = tf32c(odd ? p01 : p00);
                a[1] = tf32c(odd ? p11 : p10);
                a[2] = tf32c(odd ? q01 : q00);
                a[3] = tf32c(odd ? q11 : q10);
                int kk = half*64 + ks2*8;
                #pragma unroll
                for (int dt = 0; dt < 8; dt++) {
                    uint32_t b0 = Vu[(dt*8+grp)*132 + kk + qid];
                    uint32_t b1 = Vu[(dt*8+grp)*132 + kk + qid + 4];
                    mma8(ao[dt], a, b0, b1);
                }
            }
        }
        __syncthreads();
    }
    // epilogue: normalize + direct token-major fragment stores
    float inv0 = 1.f / l_i[0], inv1 = 1.f / l_i[1];
    float* ob0 = attoT + ((size_t)(b*1024 + m0 + wq + grp))*256 + h*64;
    float* ob1 = attoT + ((size_t)(b*1024 + m0 + wq + grp + 8))*256 + h*64;
    #pragma unroll
    for (int dt = 0; dt < 8; dt++) {
        int d0 = dt*8 + 2*qid;
        float2 v0; v0.x = ao[dt][0]*inv0; v0.y = ao[dt][1]*inv0;
        float2 v1; v1.x = ao[dt][2]*inv1; v1.y = ao[dt][3]*inv1;
        *(float2*)(ob0 + d0) = v0;
        *(float2*)(ob1 + d0) = v1;
    }
}

// ============ PE depthwise conv, accumulate token-major ============
__global__ void pe_tok(const float* __restrict__ qkv, const float* __restrict__ w,
                       const float* __restrict__ s, const float* __restrict__ bb,
                       float* __restrict__ attoT)
{
    __shared__ float sv[3][32][33];
    int row = blockIdx.x, ct = blockIdx.y, b = blockIdx.z, tid = threadIdx.x;
    for (int idx = tid; idx < 3072; idx += 256) {
        int rr = idx >> 10, c = (idx >> 5) & 31, w2 = idx & 31;
        int r = row + rr - 1;
        int cg = ct*32 + c;
        int cin = (cg >> 6)*128 + 64 + (cg & 63);
        float v = 0.f;
        if ((unsigned)r < 32u) v = qkv[((size_t)b*512 + cin)*1024 + r*32 + w2];
        sv[rr][c][w2] = v;
    }
    __syncthreads();
    int w2 = tid >> 3, cb = (tid & 7) * 4;
    float o[4];
    #pragma unroll
    for (int j = 0; j < 4; j++) {
        int c = cb + j, cg = ct*32 + c;
        const float* wp = w + cg*9;
        float acc = 0.f;
        #pragma unroll
        for (int rr = 0; rr < 3; rr++)
        #pragma unroll
            for (int dx = -1; dx <= 1; dx++) {
                int ww = w2 + dx;
                if ((unsigned)ww < 32u) acc += sv[rr][c][ww] * wp[rr*3 + dx + 1];
            }
        o[j] = acc * s[cg] + bb[cg];
    }
    size_t base = ((size_t)b*1024 + row*32 + w2)*256 + ct*32 + cb;
    float4 old = *(float4*)(attoT + base);
    old.x += o[0]; old.y += o[1]; old.z += o[2]; old.w += o[3];
    *(float4*)(attoT + base) = old;
}

// ============ fused GELU-gate + transpose ============
__global__ void gatetrans(const float* __restrict__ dwb, float* __restrict__ hidT)
{
    __shared__ float t[32][33];
    int nt = blockIdx.x, ct = blockIdx.y, b = blockIdx.z, tid = threadIdx.x;
    int cl = tid >> 5, nl = tid & 31;
    #pragma unroll
    for (int k = 0; k < 32; k += 8) {
        int cc = cl + k;
        size_t i1 = ((size_t)b*1024 + ct*32 + cc)*1024 + nt*32 + nl;
        float y1 = dwb[i1];
        float y2 = dwb[i1 + (size_t)512*1024];
        float g = 0.5f * y1 * (1.f + erff(y1 * 0.70710678118654752f));
        t[nl][cc] = g * y2;
    }
    __syncthreads();
    #pragma unroll
    for (int k = 0; k < 32; k += 8) {
        int n2 = cl + k;
        hidT[((size_t)b*1024 + nt*32 + n2)*512 + ct*32 + nl] = t[n2][nl];
    }
}

// ============ dwconv3x3 ============
__global__ void dwconv_kernel(const float* __restrict__ in, const float* __restrict__ w,
                              float* __restrict__ out)
{
    int idx = blockIdx.x * blockDim.x + threadIdx.x;
    if (idx >= NB * C2 * 1024) return;
    int xw = idx & 31, yh = (idx >> 5) & 31;
    int c = (idx >> 10) % C2;
    const float* ip = in + ((size_t)(idx >> 10)) * 1024;
    const float* wp = w + c * 9;
    float s = 0.f;
    #pragma unroll
    for (int dy = -1; dy <= 1; dy++) {
        int yy = yh + dy; if ((unsigned)yy >= 32u) continue;
        #pragma unroll
        for (int dx = -1; dx <= 1; dx++) {
            int xx = xw + dx; if ((unsigned)xx >= 32u) continue;
            s += ip[yy*32 + xx] * wp[(dy+1)*3 + dx + 1];
        }
    }
    out[idx] = s;
}

// ============ FFT filter -> circular conv ============
__global__ void fft_g_kernel(const float* __restrict__ filt, float* __restrict__ g)
{
    const float ct[8] = {1.f, 0.70710678118654752f, 0.f, -0.70710678118654752f,
                         -1.f, -0.70710678118654752f, 0.f, 0.70710678118654752f};
    int c = blockIdx.x, t = threadIdx.x;
    int a = t >> 3, bb = t & 7;
    float s = 0.f;
    for (int k1 = 0; k1 < 8; k1++)
        for (int k2 = 0; k2 < 8; k2++) {
            float F = (k2 <= 4) ? filt[c*40 + k1*5 + k2]
                                : filt[c*40 + ((8-k1)&7)*5 + (8-k2)];
            s += F * ct[(k1*a + k2*bb) & 7];
        }
    g[c*64 + t] = s * (1.f/64.f);
}

__global__ void fft_apply_kernel(const float* __restrict__ y, const float* __restrict__ g,
                                 const float* __restrict__ xnew, float* __restrict__ out)
{
    __shared__ float ys[1024];
    __shared__ float gs[64];
    int bc = blockIdx.x, c = bc % 256;
    const float* yp = y + (size_t)bc * 1024;
    int tid = threadIdx.x;
    for (int i = tid; i < 1024; i += 256) ys[i] = yp[i];
    if (tid < 64) gs[tid] = g[c*64 + tid];
    __syncthreads();
    for (int i = tid; i < 1024; i += 256) {
        int u = i >> 5, v = i & 31;
        int bu = u & ~7, bv = v & ~7, uu = u & 7, vv = v & 7;
        float s = 0.f;
        #pragma unroll
        for (int a = 0; a < 8; a++) {
            const float* yr = &ys[(bu + a)*32 + bv];
            const float* gr = &gs[((uu - a) & 7) * 8];
            #pragma unroll
            for (int b2 = 0; b2 < 8; b2++)
                s += gr[(vv - b2) & 7] * yr[b2];
        }
        size_t oi = (size_t)bc * 1024 + i;
        out[oi] = xnew[oi] + s;
    }
}

// =========================================================================
extern "C" void kernel_launch(void* const* d_in, const int* in_sizes, int n_in,
                              void* d_out, int out_size)
{
    const float* x      = (const float*)d_in[0];
    const float* qkv_w  = (const float*)d_in[1];
    const float* qkv_s  = (const float*)d_in[2];
    const float* qkv_b  = (const float*)d_in[3];
    const float* pe_w   = (const float*)d_in[4];
    const float* pe_s   = (const float*)d_in[5];
    const float* pe_b   = (const float*)d_in[6];
    const float* proj_w = (const float*)d_in[7];
    const float* proj_s = (const float*)d_in[8];
    const float* proj_b = (const float*)d_in[9];
    const float* pin_w  = (const float*)d_in[10];
    const float* dw_w   = (const float*)d_in[11];
    const float* ff     = (const float*)d_in[12];
    const float* pout_w = (const float*)d_in[13];
    float* out = (float*)d_out;

    float *qkv, *qkT, *xT, *attoT, *xnew, *xnewT, *pin, *dwb, *hidT, *yout, *gtab;
    cudaGetSymbolAddress((void**)&qkv,   g_qkv);
    cudaGetSymbolAddress((void**)&qkT,   g_qkT);
    cudaGetSymbolAddress((void**)&xT,    g_xT);
    cudaGetSymbolAddress((void**)&attoT, g_attoT);
    cudaGetSymbolAddress((void**)&xnew,  g_xnew);
    cudaGetSymbolAddress((void**)&xnewT, g_xnewT);
    cudaGetSymbolAddress((void**)&pin,   g_pin);
    cudaGetSymbolAddress((void**)&dwb,   g_dw);
    cudaGetSymbolAddress((void**)&hidT,  g_hidT);
    cudaGetSymbolAddress((void**)&yout,  g_yout);
    cudaGetSymbolAddress((void**)&gtab,  g_g);

    cudaFuncSetAttribute(flash_kernel, cudaFuncAttributeMaxDynamicSharedMemorySize, FA_SMEM);
    cudaFuncSetAttribute(gemm_mma, cudaFuncAttributeMaxDynamicSharedMemorySize, GEMM_SMEM);
    dim3 tb(32, 8);

    // 1. xT = transpose(x)
    transpose_kernel<<<dim3(32, 8, 16), tb>>>(x, xT, 262144, 262144, 256, 1024);
    // 2. qkv gemm -> qkv cm + qkT token (mode 2)
    gemm_mma<<<dim3(8,4,16), 256, GEMM_SMEM>>>(qkv_w, 256, xT, 256, (size_t)262144,
        qkv, (size_t)524288, 256, qkv_s, qkv_b, nullptr, qkT, 2, 0);
    // 3. flash attention -> attoT token-major
    flash_kernel<<<dim3(8, 64), 256, FA_SMEM>>>(qkT, qkv, attoT);
    // 4. PE conv accumulate into attoT
    pe_tok<<<dim3(32, 8, 16), 256>>>(qkv, pe_w, pe_s, pe_b, attoT);
    // 5. proj gemm -> xnew cm (+x residual) + xnewT token (mode 1)
    gemm_mma<<<dim3(8,2,16), 256, GEMM_SMEM>>>(proj_w, 256, attoT, 256, (size_t)262144,
        xnew, (size_t)262144, 256, proj_s, proj_b, x, xnewT, 1, (size_t)262144);
    // 6. pin gemm -> pin cm
    gemm_mma<<<dim3(8,8,16), 256, GEMM_SMEM>>>(pin_w, 256, xnewT, 256, (size_t)262144,
        pin, (size_t)1048576, 256, nullptr, nullptr, nullptr, nullptr, 0, 0);
    // 7. dwconv
    dwconv_kernel<<<(NB*C2*1024+255)/256, 256>>>(pin, dw_w, dwb);
    // 8. gate + transpose -> hidT
    gatetrans<<<dim3(32, 16, 16), 256>>>(dwb, hidT);
    // 9. pout gemm -> yout cm
    gemm_mma<<<dim3(8,2,16), 256, GEMM_SMEM>>>(pout_w, 512, hidT, 512, (size_t)524288,
        yout, (size_t)262144, 512, nullptr, nullptr, nullptr, nullptr, 0, 0);
    // 10. fft
    fft_g_kernel<<<C_, 64>>>(ff, gtab);
    fft_apply_kernel<<<NB*C_, 256>>>(yout, gtab, xnew, out);
}

// round 8
// speedup vs baseline: 4.1817x; 1.0809x over previous
#include <cuda_runtime.h>
#include <math.h>
#include <stdint.h>

#define NB 16
#define C_ 256
#define N_ 1024
#define C2 1024
#define HID 512

__device__ float g_qkv  [(size_t)NB*512*1024];
__device__ float g_qkT  [(size_t)64*1024*64];
__device__ float g_xT   [(size_t)NB*1024*256];
__device__ float g_attoT[(size_t)NB*1024*256];
__device__ float g_xnew [(size_t)NB*256*1024];
__device__ float g_xnewT[(size_t)NB*1024*256];
__device__ float g_pin  [(size_t)NB*1024*1024];
__device__ float g_hidT [(size_t)NB*1024*512];
__device__ float g_yout [(size_t)NB*256*1024];
__device__ float g_g    [C_*64];

__device__ __forceinline__ uint32_t tf32c(float f){
    uint32_t u; asm("cvt.rna.tf32.f32 %0, %1;" : "=r"(u) : "f"(f)); return u;
}
__device__ __forceinline__ uint32_t smem_u32(const void* p){
    uint32_t a;
    asm("{ .reg .u64 t; cvta.to.shared.u64 t, %1; cvt.u32.u64 %0, t; }" : "=r"(a) : "l"(p));
    return a;
}
__device__ __forceinline__ void cpasync16(uint32_t s, const void* g){
    asm volatile("cp.async.ca.shared.global [%0], [%1], 16;" :: "r"(s), "l"(g));
}
__device__ __forceinline__ void mma8(float* d, const uint32_t* a, uint32_t b0, uint32_t b1){
    asm volatile("mma.sync.aligned.m16n8k8.row.col.f32.tf32.tf32.f32 "
        "{%0,%1,%2,%3}, {%4,%5,%6,%7}, {%8,%9}, {%0,%1,%2,%3};"
        : "+f"(d[0]), "+f"(d[1]), "+f"(d[2]), "+f"(d[3])
        : "r"(a[0]), "r"(a[1]), "r"(a[2]), "r"(a[3]), "r"(b0), "r"(b1));
}

// ============ conv1x1 GEMM, cp.async 2-stage, optional token-major dual write
#define GEMM_SMEM 73728
__global__ void __launch_bounds__(256, 2) gemm_mma(
    const float* __restrict__ A, int lda,
    const float* __restrict__ B, int ldb, size_t bZs,
    float* __restrict__ O, size_t oZs, int K,
    const float* __restrict__ sc, const float* __restrict__ bi,
    const float* __restrict__ res,
    float* __restrict__ tokO, int tokMode, size_t tZs)
{
    extern __shared__ float smem[];
    const int tid = threadIdx.x, wid = tid >> 5, lane = tid & 31;
    const int m0 = blockIdx.y*128, n0 = blockIdx.x*128, z = blockIdx.z;
    const float* Bp = B + (size_t)z * bZs;
    const int wm = (wid & 3) * 32, wn = (wid >> 2) * 64;
    const int grp = lane >> 2, qid = lane & 3;
    const uint32_t sb = smem_u32(smem);

    float acc[2][8][4];
    #pragma unroll
    for (int mt = 0; mt < 2; mt++)
    #pragma unroll
        for (int nt = 0; nt < 8; nt++)
        #pragma unroll
            for (int r = 0; r < 4; r++) acc[mt][nt][r] = 0.f;

    const int nkc = K >> 5;
    auto issue = [&](int i, int st){
        int k0 = i << 5;
        uint32_t abase = sb + st*36864u;
        uint32_t bbase = abase + 18432u;
        #pragma unroll
        for (int idx = tid; idx < 1024; idx += 256) {
            int r = idx >> 3, c4 = (idx & 7) * 4;
            cpasync16(abase + (uint32_t)(r*36 + c4)*4u, A + (size_t)(m0+r)*lda + k0 + c4);
            cpasync16(bbase + (uint32_t)(r*36 + c4)*4u, Bp + (size_t)(n0+r)*ldb + k0 + c4);
        }
        asm volatile("cp.async.commit_group;" ::: "memory");
    };

    issue(0, 0);
    for (int i = 0; i < nkc; i++) {
        if (i + 1 < nkc) { issue(i+1, (i+1)&1); }
        if (i + 1 < nkc) asm volatile("cp.async.wait_group 1;" ::: "memory");
        else             asm volatile("cp.async.wait_group 0;" ::: "memory");
        __syncthreads();
        const uint32_t* As = (const uint32_t*)(smem + (i&1)*9216);
        const uint32_t* Bs = As + 4608;
        #pragma unroll
        for (int ks = 0; ks < 4; ks++) {
            int kk = ks * 8;
            uint32_t a[2][4];
            #pragma unroll
            for (int mt = 0; mt < 2; mt++) {
                int r = wm + mt*16 + grp;
                a[mt][0] = As[r*36 + kk + qid];
                a[mt][1] = As[(r+8)*36 + kk + qid];
                a[mt][2] = As[r*36 + kk + qid + 4];
                a[mt][3] = As[(r+8)*36 + kk + qid + 4];
            }
            #pragma unroll
            for (int nt = 0; nt < 8; nt++) {
                int n = wn + nt*8 + grp;
                uint32_t b0 = Bs[n*36 + kk + qid];
                uint32_t b1 = Bs[n*36 + kk + qid + 4];
                mma8(acc[0][nt], a[0], b0, b1);
                mma8(acc[1][nt], a[1], b0, b1);
            }
        }
        __syncthreads();
    }

    #pragma unroll
    for (int mt = 0; mt < 2; mt++) {
        #pragma unroll
        for (int half = 0; half < 2; half++) {
            int mg = m0 + wm + mt*16 + grp + half*8;
            float s1 = sc ? sc[mg] : 1.f;
            float b1 = sc ? bi[mg] : 0.f;
            const float* rb = res ? res + (size_t)z*oZs + (size_t)mg*1024 + n0 + wn : nullptr;
            #pragma unroll
            for (int nt = 0; nt < 8; nt++) {
                int c = nt*8 + 2*qid;
                float vx = acc[mt][nt][half*2]   * s1 + b1;
                float vy = acc[mt][nt][half*2+1] * s1 + b1;
                if (rb) { float2 rv = *(const float2*)(rb + c); vx += rv.x; vy += rv.y; }
                acc[mt][nt][half*2]   = vx;
                acc[mt][nt][half*2+1] = vy;
            }
        }
    }
    #pragma unroll
    for (int mt = 0; mt < 2; mt++) {
        #pragma unroll
        for (int half = 0; half < 2; half++) {
            int mg = m0 + wm + mt*16 + grp + half*8;
            float* ob = O + (size_t)z*oZs + (size_t)mg*1024 + n0 + wn;
            #pragma unroll
            for (int nt = 0; nt < 8; nt++) {
                int c = nt*8 + 2*qid;
                float2 v; v.x = acc[mt][nt][half*2]; v.y = acc[mt][nt][half*2+1];
                *(float2*)(ob + c) = v;
            }
        }
    }
    if (tokMode) {
        const int tS = (tokMode == 2) ? 68 : 132;
        float* Ts = smem;
        for (int nh = 0; nh < 2; nh++) {
            if ((wid >> 2) == nh && (tokMode == 1 || wm < 64)) {
                #pragma unroll
                for (int mt = 0; mt < 2; mt++)
                #pragma unroll
                    for (int hh = 0; hh < 2; hh++) {
                        int ml = wm + mt*16 + grp + hh*8;
                        #pragma unroll
                        for (int nt = 0; nt < 8; nt++) {
                            int r = nt*8 + 2*qid;
                            Ts[r*tS + ml]     = acc[mt][nt][hh*2];
                            Ts[(r+1)*tS + ml] = acc[mt][nt][hh*2+1];
                        }
                    }
            }
            __syncthreads();
            if (tokMode == 1) {
                float* dst = tokO + (size_t)z*tZs + (size_t)(n0 + nh*64)*256 + m0;
                #pragma unroll
                for (int idx = tid; idx < 2048; idx += 256) {
                    int r = idx >> 5, c4 = (idx & 31) * 4;
                    float4 v = *(float4*)&Ts[r*tS + c4];
                    *(float4*)(dst + (size_t)r*256 + c4) = v;
                }
            } else {
                float* dst = tokO + ((size_t)(z*4 + (m0 >> 7))*1024 + n0 + nh*64)*64;
                #pragma unroll
                for (int idx = tid; idx < 1024; idx += 256) {
                    int r = idx >> 4, c4 = (idx & 15) * 4;
                    float4 v = *(float4*)&Ts[r*tS + c4];
                    *(float4*)(dst + r*64 + c4) = v;
                }
            }
            __syncthreads();
        }
    }
}

// ============ 32x32 tiled transpose (input x only) ============
__global__ void transpose_kernel(const float* __restrict__ src, float* __restrict__ dst,
                                 size_t sStr, size_t dStr, int R, int C)
{
    __shared__ float t[32][33];
    const float* s = src + (size_t)blockIdx.z * sStr;
    float* d = dst + (size_t)blockIdx.z * dStr;
    int c0 = blockIdx.x*32, r0 = blockIdx.y*32;
    int tx = threadIdx.x, ty = threadIdx.y;
    #pragma unroll
    for (int k = 0; k < 32; k += 8)
        t[ty+k][tx] = s[(size_t)(r0+ty+k)*C + c0+tx];
    __syncthreads();
    #pragma unroll
    for (int k = 0; k < 32; k += 8)
        d[(size_t)(c0+ty+k)*R + r0+tx] = t[tx][ty+k];
}

// ============ flash attention (R7 version) ============
#define FA_SMEM 70656
__global__ void __launch_bounds__(256, 2) flash_kernel(
    const float* __restrict__ qkT, const float* __restrict__ qkv,
    float* __restrict__ attoT)
{
    extern __shared__ float sm[];
    float* Qs = sm;
    float* Ks = sm + 4608;
    float* Vs = sm + 9216;
    const int tid = threadIdx.x, wid = tid >> 5, lane = tid & 31;
    const int grp = lane >> 2, qid = lane & 3;
    const int lanebase = lane & ~3, odd = qid & 1;
    const int src1 = lanebase + (qid >> 1), src2 = src1 + 2;
    const int m0 = blockIdx.x * 128, bh = blockIdx.y;
    const int b = bh >> 2, h = bh & 3;
    const int wq = wid * 16;
    const float* qbase = qkT + ((size_t)bh*1024 + m0)*64;
    const float* vbase = qkv + (size_t)b*524288 + (size_t)(h*128+64)*1024;

    #pragma unroll
    for (int idx = tid; idx < 1024; idx += 256) {
        int r = idx >> 3, c4 = (idx & 7) * 4;
        float4 v = *(const float4*)(qbase + r*64 + c4);
        uint32_t* d = (uint32_t*)&Qs[r*36 + c4];
        const float s = 0.17677669529663687f;
        d[0]=tf32c(v.x*s); d[1]=tf32c(v.y*s); d[2]=tf32c(v.z*s); d[3]=tf32c(v.w*s);
    }

    float m_i[2] = {-1e30f, -1e30f};
    float l_i[2] = {0.f, 0.f};
    float ao[8][4];
    #pragma unroll
    for (int dt = 0; dt < 8; dt++) { ao[dt][0]=0; ao[dt][1]=0; ao[dt][2]=0; ao[dt][3]=0; }

    for (int kc = 0; kc < 8; kc++) {
        const float* kb = qkT + ((size_t)bh*1024 + kc*128)*64 + 32;
        #pragma unroll
        for (int idx = tid; idx < 1024; idx += 256) {
            int r = idx >> 3, c4 = (idx & 7) * 4;
            float4 v = *(const float4*)(kb + r*64 + c4);
            uint32_t* d = (uint32_t*)&Ks[r*36 + c4];
            d[0]=tf32c(v.x); d[1]=tf32c(v.y); d[2]=tf32c(v.z); d[3]=tf32c(v.w);
        }
        const float* vb = vbase + kc*128;
        #pragma unroll
        for (int idx = tid; idx < 2048; idx += 256) {
            int dd = idx >> 5, c4 = (idx & 31) * 4;
            float4 v = *(const float4*)(vb + (size_t)dd*1024 + c4);
            uint32_t* dp = (uint32_t*)&Vs[dd*132 + c4];
            dp[0]=tf32c(v.x); dp[1]=tf32c(v.y); dp[2]=tf32c(v.z); dp[3]=tf32c(v.w);
        }
        __syncthreads();

        const uint32_t* Qu = (const uint32_t*)Qs;
        const uint32_t* Ku = (const uint32_t*)Ks;
        const uint32_t* Vu = (const uint32_t*)Vs;

        #pragma unroll
        for (int half = 0; half < 2; half++) {
            float sacc[8][4];
            #pragma unroll
            for (int nt = 0; nt < 8; nt++) { sacc[nt][0]=0; sacc[nt][1]=0; sacc[nt][2]=0; sacc[nt][3]=0; }
            #pragma unroll
            for (int ks = 0; ks < 4; ks++) {
                int kk = ks * 8;
                uint32_t a[4];
                a[0] = Qu[(wq+grp)*36 + kk + qid];
                a[1] = Qu[(wq+grp+8)*36 + kk + qid];
                a[2] = Qu[(wq+grp)*36 + kk + qid + 4];
                a[3] = Qu[(wq+grp+8)*36 + kk + qid + 4];
                #pragma unroll
                for (int nt = 0; nt < 8; nt++) {
                    int n = half*64 + nt*8 + grp;
                    uint32_t b0 = Ku[n*36 + kk + qid];
                    uint32_t b1 = Ku[n*36 + kk + qid + 4];
                    mma8(sacc[nt], a, b0, b1);
                }
            }
            float mx0 = -1e30f, mx1 = -1e30f;
            #pragma unroll
            for (int nt = 0; nt < 8; nt++) {
                mx0 = fmaxf(mx0, fmaxf(sacc[nt][0], sacc[nt][1]));
                mx1 = fmaxf(mx1, fmaxf(sacc[nt][2], sacc[nt][3]));
            }
            mx0 = fmaxf(mx0, __shfl_xor_sync(0xffffffffu, mx0, 1));
            mx0 = fmaxf(mx0, __shfl_xor_sync(0xffffffffu, mx0, 2));
            mx1 = fmaxf(mx1, __shfl_xor_sync(0xffffffffu, mx1, 1));
            mx1 = fmaxf(mx1, __shfl_xor_sync(0xffffffffu, mx1, 2));
            float mn0 = fmaxf(m_i[0], mx0), mn1 = fmaxf(m_i[1], mx1);
            float s0 = 0.f, s1 = 0.f;
            #pragma unroll
            for (int nt = 0; nt < 8; nt++) {
                sacc[nt][0] = __expf(sacc[nt][0] - mn0);
                sacc[nt][1] = __expf(sacc[nt][1] - mn0);
                sacc[nt][2] = __expf(sacc[nt][2] - mn1);
                sacc[nt][3] = __expf(sacc[nt][3] - mn1);
                s0 += sacc[nt][0] + sacc[nt][1];
                s1 += sacc[nt][2] + sacc[nt][3];
            }
            s0 += __shfl_xor_sync(0xffffffffu, s0, 1);
            s0 += __shfl_xor_sync(0xffffffffu, s0, 2);
            s1 += __shfl_xor_sync(0xffffffffu, s1, 1);
            s1 += __shfl_xor_sync(0xffffffffu, s1, 2);
            float al0 = __expf(m_i[0] - mn0), al1 = __expf(m_i[1] - mn1);
            l_i[0] = l_i[0]*al0 + s0; l_i[1] = l_i[1]*al1 + s1;
            m_i[0] = mn0; m_i[1] = mn1;
            #pragma unroll
            for (int dt = 0; dt < 8; dt++) {
                ao[dt][0] *= al0; ao[dt][1] *= al0;
                ao[dt][2] *= al1; ao[dt][3] *= al1;
            }
            #pragma unroll
            for (int ks2 = 0; ks2 < 8; ks2++) {
                float p00 = __shfl_sync(0xffffffffu, sacc[ks2][0], src1);
                float p01 = __shfl_sync(0xffffffffu, sacc[ks2][1], src1);
                float p10 = __shfl_sync(0xffffffffu, sacc[ks2][2], src1);
                float p11 = __shfl_sync(0xffffffffu, sacc[ks2][3], src1);
                float q00 = __shfl_sync(0xffffffffu, sacc[ks2][0], src2);
                float q01 = __shfl_sync(0xffffffffu, sacc[ks2][1], src2);
                float q10 = __shfl_sync(0xffffffffu, sacc[ks2][2], src2);
                float q11 = __shfl_sync(0xffffffffu, sacc[ks2][3], src2);
                uint32_t a[4];
                a[0] = tf32c(odd ? p01 : p00);
                a[1] = tf32c(odd ? p11 : p10);
                a[2] = tf32c(odd ? q01 : q00);
                a[3] = tf32c(odd ? q11 : q10);
                int kk = half*64 + ks2*8;
                #pragma unroll
                for (int dt = 0; dt < 8; dt++) {
                    uint32_t b0 = Vu[(dt*8+grp)*132 + kk + qid];
                    uint32_t b1 = Vu[(dt*8+grp)*132 + kk + qid + 4];
                    mma8(ao[dt], a, b0, b1);
                }
            }
        }
        __syncthreads();
    }
    float inv0 = 1.f / l_i[0], inv1 = 1.f / l_i[1];
    float* ob0 = attoT + ((size_t)(b*1024 + m0 + wq + grp))*256 + h*64;
    float* ob1 = attoT + ((size_t)(b*1024 + m0 + wq + grp + 8))*256 + h*64;
    #pragma unroll
    for (int dt = 0; dt < 8; dt++) {
        int d0 = dt*8 + 2*qid;
        float2 v0; v0.x = ao[dt][0]*inv0; v0.y = ao[dt][1]*inv0;
        float2 v1; v1.x = ao[dt][2]*inv1; v1.y = ao[dt][3]*inv1;
        *(float2*)(ob0 + d0) = v0;
        *(float2*)(ob1 + d0) = v1;
    }
}

// ============ PE depthwise conv, accumulate token-major ============
__global__ void pe_tok(const float* __restrict__ qkv, const float* __restrict__ w,
                       const float* __restrict__ s, const float* __restrict__ bb,
                       float* __restrict__ attoT)
{
    __shared__ float sv[3][32][33];
    int row = blockIdx.x, ct = blockIdx.y, b = blockIdx.z, tid = threadIdx.x;
    for (int idx = tid; idx < 3072; idx += 256) {
        int rr = idx >> 10, c = (idx >> 5) & 31, w2 = idx & 31;
        int r = row + rr - 1;
        int cg = ct*32 + c;
        int cin = (cg >> 6)*128 + 64 + (cg & 63);
        float v = 0.f;
        if ((unsigned)r < 32u) v = qkv[((size_t)b*512 + cin)*1024 + r*32 + w2];
        sv[rr][c][w2] = v;
    }
    __syncthreads();
    int w2 = tid >> 3, cb = (tid & 7) * 4;
    float o[4];
    #pragma unroll
    for (int j = 0; j < 4; j++) {
        int c = cb + j, cg = ct*32 + c;
        const float* wp = w + cg*9;
        float acc = 0.f;
        #pragma unroll
        for (int rr = 0; rr < 3; rr++)
        #pragma unroll
            for (int dx = -1; dx <= 1; dx++) {
                int ww = w2 + dx;
                if ((unsigned)ww < 32u) acc += sv[rr][c][ww] * wp[rr*3 + dx + 1];
            }
        o[j] = acc * s[cg] + bb[cg];
    }
    size_t base = ((size_t)b*1024 + row*32 + w2)*256 + ct*32 + cb;
    float4 old = *(float4*)(attoT + base);
    old.x += o[0]; old.y += o[1]; old.z += o[2]; old.w += o[3];
    *(float4*)(attoT + base) = old;
}

// ============ fused dwconv3x3 + GELU-gate + transpose ============
// block: 32 channels (ct) x 4 image rows (rg), both planes. out: hidT token-major.
#define DG_SMEM 72192
__global__ void __launch_bounds__(256) dwgate(
    const float* __restrict__ pin, const float* __restrict__ w,
    float* __restrict__ hidT)
{
    extern __shared__ float sm[];
    float* s1 = sm;            // [32ch][6rows*36]
    float* s2 = sm + 6912;     // same
    float* t  = sm + 13824;    // [128 tok][33]
    const int rg = blockIdx.x, ct = blockIdx.y, b = blockIdx.z;
    const int tid = threadIdx.x;

    // load both planes, 6-row halo slab, 32 channels
    for (int idx = tid; idx < 3072; idx += 256) {
        int px4 = idx & 7;
        int rowp = idx >> 3;           // 0..383
        int ch = rowp & 31;
        int rp = rowp >> 5;            // 0..11
        int row = rp % 6, plane = rp / 6;
        int grow = rg*4 + row - 1;
        float4 v = make_float4(0.f, 0.f, 0.f, 0.f);
        if ((unsigned)grow < 32u) {
            const float* gp = pin + ((size_t)b*1024 + ct*32 + ch + plane*512)*1024
                            + grow*32 + px4*4;
            v = *(const float4*)gp;
        }
        float* dst = (plane ? s2 : s1) + ch*216 + row*36 + px4*4;
        *(float4*)dst = v;
    }
    __syncthreads();

    // compute: warp w handles channels w*4..w*4+3, lane = pixel column
    const int wl = tid >> 5, lane = tid & 31;
    #pragma unroll
    for (int cc = 0; cc < 4; cc++) {
        int ch = wl*4 + cc;
        int cg = ct*32 + ch;
        float w1[9], w2[9];
        #pragma unroll
        for (int i = 0; i < 9; i++) { w1[i] = w[cg*9 + i]; w2[i] = w[(cg+512)*9 + i]; }
        const float* p1 = s1 + ch*216;
        const float* p2 = s2 + ch*216;
        #pragma unroll
        for (int r = 0; r < 4; r++) {
            float y1 = 0.f, y2 = 0.f;
            #pragma unroll
            for (int rr = 0; rr < 3; rr++) {
                const float* q1 = p1 + (r+rr)*36;
                const float* q2 = p2 + (r+rr)*36;
                #pragma unroll
                for (int dx = -1; dx <= 1; dx++) {
                    int px = lane + dx;
                    if ((unsigned)px < 32u) {
                        float wa = w1[rr*3 + dx + 1], wb = w2[rr*3 + dx + 1];
                        y1 += q1[px] * wa;
                        y2 += q2[px] * wb;
                    }
                }
            }
            float g = 0.5f * y1 * (1.f + erff(y1 * 0.70710678118654752f));
            t[(r*32 + lane)*33 + ch] = g * y2;
        }
    }
    __syncthreads();

    // write token-major: 128 tokens x 32 channels
    for (int idx = tid; idx < 1024; idx += 256) {
        int tok = idx >> 3, c4 = (idx & 7) * 4;
        const float* tp = &t[tok*33 + c4];
        float4 v; v.x = tp[0]; v.y = tp[1]; v.z = tp[2]; v.w = tp[3];
        *(float4*)(hidT + ((size_t)b*1024 + rg*128 + tok)*512 + ct*32 + c4) = v;
    }
}

// ============ FFT filter -> circular conv ============
__global__ void fft_g_kernel(const float* __restrict__ filt, float* __restrict__ g)
{
    const float ct[8] = {1.f, 0.70710678118654752f, 0.f, -0.70710678118654752f,
                         -1.f, -0.70710678118654752f, 0.f, 0.70710678118654752f};
    int c = blockIdx.x, t = threadIdx.x;
    int a = t >> 3, bb = t & 7;
    float s = 0.f;
    for (int k1 = 0; k1 < 8; k1++)
        for (int k2 = 0; k2 < 8; k2++) {
            float F = (k2 <= 4) ? filt[c*40 + k1*5 + k2]
                                : filt[c*40 + ((8-k1)&7)*5 + (8-k2)];
            s += F * ct[(k1*a + k2*bb) & 7];
        }
    g[c*64 + t] = s * (1.f/64.f);
}

__global__ void fft_apply_kernel(const float* __restrict__ y, const float* __restrict__ g,
                                 const float* __restrict__ xnew, float* __restrict__ out)
{
    __shared__ float ys[1024];
    __shared__ float gs[64];
    int bc = blockIdx.x, c = bc % 256;
    const float* yp = y + (size_t)bc * 1024;
    int tid = threadIdx.x;
    for (int i = tid; i < 1024; i += 256) ys[i] = yp[i];
    if (tid < 64) gs[tid] = g[c*64 + tid];
    __syncthreads();
    for (int i = tid; i < 1024; i += 256) {
        int u = i >> 5, v = i & 31;
        int bu = u & ~7, bv = v & ~7, uu = u & 7, vv = v & 7;
        float s = 0.f;
        #pragma unroll
        for (int a = 0; a < 8; a++) {
            const float* yr = &ys[(bu + a)*32 + bv];
            const float* gr = &gs[((uu - a) & 7) * 8];
            #pragma unroll
            for (int b2 = 0; b2 < 8; b2++)
                s += gr[(vv - b2) & 7] * yr[b2];
        }
        size_t oi = (size_t)bc * 1024 + i;
        out[oi] = xnew[oi] + s;
    }
}

// =========================================================================
extern "C" void kernel_launch(void* const* d_in, const int* in_sizes, int n_in,
                              void* d_out, int out_size)
{
    const float* x      = (const float*)d_in[0];
    const float* qkv_w  = (const float*)d_in[1];
    const float* qkv_s  = (const float*)d_in[2];
    const float* qkv_b  = (const float*)d_in[3];
    const float* pe_w   = (const float*)d_in[4];
    const float* pe_s   = (const float*)d_in[5];
    const float* pe_b   = (const float*)d_in[6];
    const float* proj_w = (const float*)d_in[7];
    const float* proj_s = (const float*)d_in[8];
    const float* proj_b = (const float*)d_in[9];
    const float* pin_w  = (const float*)d_in[10];
    const float* dw_w   = (const float*)d_in[11];
    const float* ff     = (const float*)d_in[12];
    const float* pout_w = (const float*)d_in[13];
    float* out = (float*)d_out;

    float *qkv, *qkT, *xT, *attoT, *xnew, *xnewT, *pin, *hidT, *yout, *gtab;
    cudaGetSymbolAddress((void**)&qkv,   g_qkv);
    cudaGetSymbolAddress((void**)&qkT,   g_qkT);
    cudaGetSymbolAddress((void**)&xT,    g_xT);
    cudaGetSymbolAddress((void**)&attoT, g_attoT);
    cudaGetSymbolAddress((void**)&xnew,  g_xnew);
    cudaGetSymbolAddress((void**)&xnewT, g_xnewT);
    cudaGetSymbolAddress((void**)&pin,   g_pin);
    cudaGetSymbolAddress((void**)&hidT,  g_hidT);
    cudaGetSymbolAddress((void**)&yout,  g_yout);
    cudaGetSymbolAddress((void**)&gtab,  g_g);

    cudaFuncSetAttribute(flash_kernel, cudaFuncAttributeMaxDynamicSharedMemorySize, FA_SMEM);
    cudaFuncSetAttribute(gemm_mma, cudaFuncAttributeMaxDynamicSharedMemorySize, GEMM_SMEM);
    cudaFuncSetAttribute(dwgate, cudaFuncAttributeMaxDynamicSharedMemorySize, DG_SMEM);
    dim3 tb(32, 8);

    // 1. xT = transpose(x)
    transpose_kernel<<<dim3(32, 8, 16), tb>>>(x, xT, 262144, 262144, 256, 1024);
    // 2. qkv gemm -> qkv cm + qkT token (mode 2)
    gemm_mma<<<dim3(8,4,16), 256, GEMM_SMEM>>>(qkv_w, 256, xT, 256, (size_t)262144,
        qkv, (size_t)524288, 256, qkv_s, qkv_b, nullptr, qkT, 2, 0);
    // 3. flash attention -> attoT token-major
    flash_kernel<<<dim3(8, 64), 256, FA_SMEM>>>(qkT, qkv, attoT);
    // 4. PE conv accumulate into attoT
    pe_tok<<<dim3(32, 8, 16), 256>>>(qkv, pe_w, pe_s, pe_b, attoT);
    // 5. proj gemm -> xnew cm (+x residual) + xnewT token (mode 1)
    gemm_mma<<<dim3(8,2,16), 256, GEMM_SMEM>>>(proj_w, 256, attoT, 256, (size_t)262144,
        xnew, (size_t)262144, 256, proj_s, proj_b, x, xnewT, 1, (size_t)262144);
    // 6. pin gemm -> pin cm
    gemm_mma<<<dim3(8,8,16), 256, GEMM_SMEM>>>(pin_w, 256, xnewT, 256, (size_t)262144,
        pin, (size_t)1048576, 256, nullptr, nullptr, nullptr, nullptr, 0, 0);
    // 7. fused dwconv + gate + transpose -> hidT
    dwgate<<<dim3(8, 16, 16), 256, DG_SMEM>>>(pin, dw_w, hidT);
    // 8. pout gemm -> yout cm
    gemm_mma<<<dim3(8,2,16), 256, GEMM_SMEM>>>(pout_w, 512, hidT, 512, (size_t)524288,
        yout, (size_t)262144, 512, nullptr, nullptr, nullptr, nullptr, 0, 0);
    // 9. fft
    fft_g_kernel<<<C_, 64>>>(ff, gtab);
    fft_apply_kernel<<<NB*C_, 256>>>(yout, gtab, xnew, out);
}

// round 9
// speedup vs baseline: 4.2621x; 1.0192x over previous
#include <cuda_runtime.h>
#include <math.h>
#include <stdint.h>

#define NB 16
#define C_ 256
#define N_ 1024
#define C2 1024
#define HID 512

__device__ float g_qkv  [(size_t)NB*512*1024];
__device__ float g_qkT  [(size_t)64*1024*64];
__device__ float g_xT   [(size_t)NB*1024*256];
__device__ float g_attoT[(size_t)NB*1024*256];
__device__ float g_xnew [(size_t)NB*256*1024];
__device__ float g_xnewT[(size_t)NB*1024*256];
__device__ float g_pin  [(size_t)NB*1024*1024];
__device__ float g_hidT [(size_t)NB*1024*512];
__device__ float g_yout [(size_t)NB*256*1024];
__device__ float g_g    [C_*64];

__device__ __forceinline__ uint32_t tf32c(float f){
    uint32_t u; asm("cvt.rna.tf32.f32 %0, %1;" : "=r"(u) : "f"(f)); return u;
}
__device__ __forceinline__ uint32_t smem_u32(const void* p){
    uint32_t a;
    asm("{ .reg .u64 t; cvta.to.shared.u64 t, %1; cvt.u32.u64 %0, t; }" : "=r"(a) : "l"(p));
    return a;
}
__device__ __forceinline__ void cpasync16(uint32_t s, const void* g){
    asm volatile("cp.async.ca.shared.global [%0], [%1], 16;" :: "r"(s), "l"(g));
}
__device__ __forceinline__ void mma8(float* d, const uint32_t* a, uint32_t b0, uint32_t b1){
    asm volatile("mma.sync.aligned.m16n8k8.row.col.f32.tf32.tf32.f32 "
        "{%0,%1,%2,%3}, {%4,%5,%6,%7}, {%8,%9}, {%0,%1,%2,%3};"
        : "+f"(d[0]), "+f"(d[1]), "+f"(d[2]), "+f"(d[3])
        : "r"(a[0]), "r"(a[1]), "r"(a[2]), "r"(a[3]), "r"(b0), "r"(b1));
}

// ============ conv1x1 GEMM, cp.async 2-stage, optional token-major dual write
#define GEMM_SMEM 73728
__global__ void __launch_bounds__(256, 2) gemm_mma(
    const float* __restrict__ A, int lda,
    const float* __restrict__ B, int ldb, size_t bZs,
    float* __restrict__ O, size_t oZs, int K,
    const float* __restrict__ sc, const float* __restrict__ bi,
    const float* __restrict__ res,
    float* __restrict__ tokO, int tokMode, size_t tZs)
{
    extern __shared__ float smem[];
    const int tid = threadIdx.x, wid = tid >> 5, lane = tid & 31;
    const int m0 = blockIdx.y*128, n0 = blockIdx.x*128, z = blockIdx.z;
    const float* Bp = B + (size_t)z * bZs;
    const int wm = (wid & 3) * 32, wn = (wid >> 2) * 64;
    const int grp = lane >> 2, qid = lane & 3;
    const uint32_t sb = smem_u32(smem);

    float acc[2][8][4];
    #pragma unroll
    for (int mt = 0; mt < 2; mt++)
    #pragma unroll
        for (int nt = 0; nt < 8; nt++)
        #pragma unroll
            for (int r = 0; r < 4; r++) acc[mt][nt][r] = 0.f;

    const int nkc = K >> 5;
    auto issue = [&](int i, int st){
        int k0 = i << 5;
        uint32_t abase = sb + st*36864u;
        uint32_t bbase = abase + 18432u;
        #pragma unroll
        for (int idx = tid; idx < 1024; idx += 256) {
            int r = idx >> 3, c4 = (idx & 7) * 4;
            cpasync16(abase + (uint32_t)(r*36 + c4)*4u, A + (size_t)(m0+r)*lda + k0 + c4);
            cpasync16(bbase + (uint32_t)(r*36 + c4)*4u, Bp + (size_t)(n0+r)*ldb + k0 + c4);
        }
        asm volatile("cp.async.commit_group;" ::: "memory");
    };

    issue(0, 0);
    for (int i = 0; i < nkc; i++) {
        if (i + 1 < nkc) { issue(i+1, (i+1)&1); }
        if (i + 1 < nkc) asm volatile("cp.async.wait_group 1;" ::: "memory");
        else             asm volatile("cp.async.wait_group 0;" ::: "memory");
        __syncthreads();
        const uint32_t* As = (const uint32_t*)(smem + (i&1)*9216);
        const uint32_t* Bs = As + 4608;
        #pragma unroll
        for (int ks = 0; ks < 4; ks++) {
            int kk = ks * 8;
            uint32_t a[2][4];
            #pragma unroll
            for (int mt = 0; mt < 2; mt++) {
                int r = wm + mt*16 + grp;
                a[mt][0] = As[r*36 + kk + qid];
                a[mt][1] = As[(r+8)*36 + kk + qid];
                a[mt][2] = As[r*36 + kk + qid + 4];
                a[mt][3] = As[(r+8)*36 + kk + qid + 4];
            }
            #pragma unroll
            for (int nt = 0; nt < 8; nt++) {
                int n = wn + nt*8 + grp;
                uint32_t b0 = Bs[n*36 + kk + qid];
                uint32_t b1 = Bs[n*36 + kk + qid + 4];
                mma8(acc[0][nt], a[0], b0, b1);
                mma8(acc[1][nt], a[1], b0, b1);
            }
        }
        __syncthreads();
    }

    #pragma unroll
    for (int mt = 0; mt < 2; mt++) {
        #pragma unroll
        for (int half = 0; half < 2; half++) {
            int mg = m0 + wm + mt*16 + grp + half*8;
            float s1 = sc ? sc[mg] : 1.f;
            float b1 = sc ? bi[mg] : 0.f;
            const float* rb = res ? res + (size_t)z*oZs + (size_t)mg*1024 + n0 + wn : nullptr;
            #pragma unroll
            for (int nt = 0; nt < 8; nt++) {
                int c = nt*8 + 2*qid;
                float vx = acc[mt][nt][half*2]   * s1 + b1;
                float vy = acc[mt][nt][half*2+1] * s1 + b1;
                if (rb) { float2 rv = *(const float2*)(rb + c); vx += rv.x; vy += rv.y; }
                acc[mt][nt][half*2]   = vx;
                acc[mt][nt][half*2+1] = vy;
            }
        }
    }
    #pragma unroll
    for (int mt = 0; mt < 2; mt++) {
        #pragma unroll
        for (int half = 0; half < 2; half++) {
            int mg = m0 + wm + mt*16 + grp + half*8;
            float* ob = O + (size_t)z*oZs + (size_t)mg*1024 + n0 + wn;
            #pragma unroll
            for (int nt = 0; nt < 8; nt++) {
                int c = nt*8 + 2*qid;
                float2 v; v.x = acc[mt][nt][half*2]; v.y = acc[mt][nt][half*2+1];
                *(float2*)(ob + c) = v;
            }
        }
    }
    if (tokMode) {
        const int tS = (tokMode == 2) ? 68 : 132;
        float* Ts = smem;
        for (int nh = 0; nh < 2; nh++) {
            if ((wid >> 2) == nh && (tokMode == 1 || wm < 64)) {
                #pragma unroll
                for (int mt = 0; mt < 2; mt++)
                #pragma unroll
                    for (int hh = 0; hh < 2; hh++) {
                        int ml = wm + mt*16 + grp + hh*8;
                        #pragma unroll
                        for (int nt = 0; nt < 8; nt++) {
                            int r = nt*8 + 2*qid;
                            Ts[r*tS + ml]     = acc[mt][nt][hh*2];
                            Ts[(r+1)*tS + ml] = acc[mt][nt][hh*2+1];
                        }
                    }
            }
            __syncthreads();
            if (tokMode == 1) {
                float* dst = tokO + (size_t)z*tZs + (size_t)(n0 + nh*64)*256 + m0;
                #pragma unroll
                for (int idx = tid; idx < 2048; idx += 256) {
                    int r = idx >> 5, c4 = (idx & 31) * 4;
                    float4 v = *(float4*)&Ts[r*tS + c4];
                    *(float4*)(dst + (size_t)r*256 + c4) = v;
                }
            } else {
                float* dst = tokO + ((size_t)(z*4 + (m0 >> 7))*1024 + n0 + nh*64)*64;
                #pragma unroll
                for (int idx = tid; idx < 1024; idx += 256) {
                    int r = idx >> 4, c4 = (idx & 15) * 4;
                    float4 v = *(float4*)&Ts[r*tS + c4];
                    *(float4*)(dst + r*64 + c4) = v;
                }
            }
            __syncthreads();
        }
    }
}

// ============ 32x32 tiled transpose (input x only) ============
__global__ void transpose_kernel(const float* __restrict__ src, float* __restrict__ dst,
                                 size_t sStr, size_t dStr, int R, int C)
{
    __shared__ float t[32][33];
    const float* s = src + (size_t)blockIdx.z * sStr;
    float* d = dst + (size_t)blockIdx.z * dStr;
    int c0 = blockIdx.x*32, r0 = blockIdx.y*32;
    int tx = threadIdx.x, ty = threadIdx.y;
    #pragma unroll
    for (int k = 0; k < 32; k += 8)
        t[ty+k][tx] = s[(size_t)(r0+ty+k)*C + c0+tx];
    __syncthreads();
    #pragma unroll
    for (int k = 0; k < 32; k += 8)
        d[(size_t)(c0+ty+k)*R + r0+tx] = t[tx][ty+k];
}

// ============ flash attention + fused PE depthwise conv ============
#define FA_SMEM 70656
__global__ void __launch_bounds__(256, 2) flash_kernel(
    const float* __restrict__ qkT, const float* __restrict__ qkv,
    const float* __restrict__ pe_w, const float* __restrict__ pe_s,
    const float* __restrict__ pe_b,
    float* __restrict__ attoT)
{
    extern __shared__ float sm[];
    float* Qs = sm;
    float* Ks = sm + 4608;
    float* Vs = sm + 9216;
    const int tid = threadIdx.x, wid = tid >> 5, lane = tid & 31;
    const int grp = lane >> 2, qid = lane & 3;
    const int lanebase = lane & ~3, odd = qid & 1;
    const int src1 = lanebase + (qid >> 1), src2 = src1 + 2;
    const int m0 = blockIdx.x * 128, bh = blockIdx.y;
    const int b = bh >> 2, h = bh & 3;
    const int wq = wid * 16;
    const float* qbase = qkT + ((size_t)bh*1024 + m0)*64;
    const float* vbase = qkv + (size_t)b*524288 + (size_t)(h*128+64)*1024;

    #pragma unroll
    for (int idx = tid; idx < 1024; idx += 256) {
        int r = idx >> 3, c4 = (idx & 7) * 4;
        float4 v = *(const float4*)(qbase + r*64 + c4);
        uint32_t* d = (uint32_t*)&Qs[r*36 + c4];
        const float s = 0.17677669529663687f;
        d[0]=tf32c(v.x*s); d[1]=tf32c(v.y*s); d[2]=tf32c(v.z*s); d[3]=tf32c(v.w*s);
    }

    float m_i[2] = {-1e30f, -1e30f};
    float l_i[2] = {0.f, 0.f};
    float ao[8][4];
    #pragma unroll
    for (int dt = 0; dt < 8; dt++) { ao[dt][0]=0; ao[dt][1]=0; ao[dt][2]=0; ao[dt][3]=0; }

    for (int kc = 0; kc < 8; kc++) {
        const float* kb = qkT + ((size_t)bh*1024 + kc*128)*64 + 32;
        #pragma unroll
        for (int idx = tid; idx < 1024; idx += 256) {
            int r = idx >> 3, c4 = (idx & 7) * 4;
            float4 v = *(const float4*)(kb + r*64 + c4);
            uint32_t* d = (uint32_t*)&Ks[r*36 + c4];
            d[0]=tf32c(v.x); d[1]=tf32c(v.y); d[2]=tf32c(v.z); d[3]=tf32c(v.w);
        }
        const float* vb = vbase + kc*128;
        #pragma unroll
        for (int idx = tid; idx < 2048; idx += 256) {
            int dd = idx >> 5, c4 = (idx & 31) * 4;
            float4 v = *(const float4*)(vb + (size_t)dd*1024 + c4);
            uint32_t* dp = (uint32_t*)&Vs[dd*132 + c4];
            dp[0]=tf32c(v.x); dp[1]=tf32c(v.y); dp[2]=tf32c(v.z); dp[3]=tf32c(v.w);
        }
        __syncthreads();

        const uint32_t* Qu = (const uint32_t*)Qs;
        const uint32_t* Ku = (const uint32_t*)Ks;
        const uint32_t* Vu = (const uint32_t*)Vs;

        #pragma unroll
        for (int half = 0; half < 2; half++) {
            float sacc[8][4];
            #pragma unroll
            for (int nt = 0; nt < 8; nt++) { sacc[nt][0]=0; sacc[nt][1]=0; sacc[nt][2]=0; sacc[nt][3]=0; }
            #pragma unroll
            for (int ks = 0; ks < 4; ks++) {
                int kk = ks * 8;
                uint32_t a[4];
                a[0] = Qu[(wq+grp)*36 + kk + qid];
                a[1] = Qu[(wq+grp+8)*36 + kk + qid];
                a[2] = Qu[(wq+grp)*36 + kk + qid + 4];
                a[3] = Qu[(wq+grp+8)*36 + kk + qid + 4];
                #pragma unroll
                for (int nt = 0; nt < 8; nt++) {
                    int n = half*64 + nt*8 + grp;
                    uint32_t b0 = Ku[n*36 + kk + qid];
                    uint32_t b1 = Ku[n*36 + kk + qid + 4];
                    mma8(sacc[nt], a, b0, b1);
                }
            }
            float mx0 = -1e30f, mx1 = -1e30f;
            #pragma unroll
            for (int nt = 0; nt < 8; nt++) {
                mx0 = fmaxf(mx0, fmaxf(sacc[nt][0], sacc[nt][1]));
                mx1 = fmaxf(mx1, fmaxf(sacc[nt][2], sacc[nt][3]));
            }
            mx0 = fmaxf(mx0, __shfl_xor_sync(0xffffffffu, mx0, 1));
            mx0 = fmaxf(mx0, __shfl_xor_sync(0xffffffffu, mx0, 2));
            mx1 = fmaxf(mx1, __shfl_xor_sync(0xffffffffu, mx1, 1));
            mx1 = fmaxf(mx1, __shfl_xor_sync(0xffffffffu, mx1, 2));
            float mn0 = fmaxf(m_i[0], mx0), mn1 = fmaxf(m_i[1], mx1);
            float s0 = 0.f, s1 = 0.f;
            #pragma unroll
            for (int nt = 0; nt < 8; nt++) {
                sacc[nt][0] = __expf(sacc[nt][0] - mn0);
                sacc[nt][1] = __expf(sacc[nt][1] - mn0);
                sacc[nt][2] = __expf(sacc[nt][2] - mn1);
                sacc[nt][3] = __expf(sacc[nt][3] - mn1);
                s0 += sacc[nt][0] + sacc[nt][1];
                s1 += sacc[nt][2] + sacc[nt][3];
            }
            s0 += __shfl_xor_sync(0xffffffffu, s0, 1);
            s0 += __shfl_xor_sync(0xffffffffu, s0, 2);
            s1 += __shfl_xor_sync(0xffffffffu, s1, 1);
            s1 += __shfl_xor_sync(0xffffffffu, s1, 2);
            float al0 = __expf(m_i[0] - mn0), al1 = __expf(m_i[1] - mn1);
            l_i[0] = l_i[0]*al0 + s0; l_i[1] = l_i[1]*al1 + s1;
            m_i[0] = mn0; m_i[1] = mn1;
            #pragma unroll
            for (int dt = 0; dt < 8; dt++) {
                ao[dt][0] *= al0; ao[dt][1] *= al0;
                ao[dt][2] *= al1; ao[dt][3] *= al1;
            }
            #pragma unroll
            for (int ks2 = 0; ks2 < 8; ks2++) {
                float p00 = __shfl_sync(0xffffffffu, sacc[ks2][0], src1);
                float p01 = __shfl_sync(0xffffffffu, sacc[ks2][1], src1);
                float p10 = __shfl_sync(0xffffffffu, sacc[ks2][2], src1);
                float p11 = __shfl_sync(0xffffffffu, sacc[ks2][3], src1);
                float q00 = __shfl_sync(0xffffffffu, sacc[ks2][0], src2);
                float q01 = __shfl_sync(0xffffffffu, sacc[ks2][1], src2);
                float q10 = __shfl_sync(0xffffffffu, sacc[ks2][2], src2);
                float q11 = __shfl_sync(0xffffffffu, sacc[ks2][3], src2);
                uint32_t a[4];
                a[0] = tf32c(odd ? p01 : p00);
                a[1] = tf32c(odd ? p11 : p10);
                a[2] = tf32c(odd ? q01 : q00);
                a[3] = tf32c(odd ? q11 : q10);
                int kk = half*64 + ks2*8;
                #pragma unroll
                for (int dt = 0; dt < 8; dt++) {
                    uint32_t b0 = Vu[(dt*8+grp)*132 + kk + qid];
                    uint32_t b1 = Vu[(dt*8+grp)*132 + kk + qid + 4];
                    mma8(ao[dt], a, b0, b1);
                }
            }
        }
        __syncthreads();
    }

    // ---- PE slab: V rows (m0/32 -1 .. +4), 64 channels, padded [64][216] ----
    float* slab = sm;
    const int r0 = m0 >> 5;
    for (int idx = tid; idx < 3072; idx += 256) {
        int c4 = idx & 7;
        int t6 = idx >> 3;            // 0..383
        int srow = t6 % 6, ch = t6 / 6;
        int grow = r0 + srow - 1;
        float4 v = make_float4(0.f, 0.f, 0.f, 0.f);
        if ((unsigned)grow < 32u)
            v = *(const float4*)(vbase + (size_t)ch*1024 + grow*32 + c4*4);
        *(float4*)(slab + ch*216 + srow*36 + c4*4) = v;
    }
    __syncthreads();

    // ---- epilogue: normalize + PE add + token-major store ----
    float inv0 = 1.f / l_i[0], inv1 = 1.f / l_i[1];
    const int tl0 = wq + grp, tl1 = tl0 + 8;
    const int col0 = tl0 & 31, rl0 = tl0 >> 5;
    const int col1 = tl1 & 31, rl1 = tl1 >> 5;
    float* ob0 = attoT + ((size_t)(b*1024 + m0 + tl0))*256 + h*64;
    float* ob1 = attoT + ((size_t)(b*1024 + m0 + tl1))*256 + h*64;
    #pragma unroll
    for (int dt = 0; dt < 8; dt++) {
        int d0 = dt*8 + 2*qid;
        float pe[2][2];
        #pragma unroll
        for (int e = 0; e < 2; e++) {
            int ch = d0 + e, cg = h*64 + ch;
            const float* wp = pe_w + cg*9;
            float w9[9];
            #pragma unroll
            for (int i = 0; i < 9; i++) w9[i] = wp[i];
            float ss = pe_s[cg], bb2 = pe_b[cg];
            const float* sl = slab + ch*216;
            #pragma unroll
            for (int tk = 0; tk < 2; tk++) {
                int col = tk ? col1 : col0;
                int rl  = tk ? rl1  : rl0;
                float acc2 = 0.f;
                #pragma unroll
                for (int rr = 0; rr < 3; rr++) {
                    const float* q = sl + (rl + rr)*36;
                    #pragma unroll
                    for (int dx = -1; dx <= 1; dx++) {
                        int cx = col + dx;
                        if ((unsigned)cx < 32u) acc2 += q[cx] * w9[rr*3 + dx + 1];
                    }
                }
                pe[e][tk] = acc2 * ss + bb2;
            }
        }
        float2 v0, v1;
        v0.x = ao[dt][0]*inv0 + pe[0][0];
        v0.y = ao[dt][1]*inv0 + pe[1][0];
        v1.x = ao[dt][2]*inv1 + pe[0][1];
        v1.y = ao[dt][3]*inv1 + pe[1][1];
        *(float2*)(ob0 + d0) = v0;
        *(float2*)(ob1 + d0) = v1;
    }
}

// ============ fused dwconv3x3 + GELU-gate + transpose ============
#define DG_SMEM 72192
__global__ void __launch_bounds__(256) dwgate(
    const float* __restrict__ pin, const float* __restrict__ w,
    float* __restrict__ hidT)
{
    extern __shared__ float sm[];
    float* s1 = sm;
    float* s2 = sm + 6912;
    float* t  = sm + 13824;
    const int rg = blockIdx.x, ct = blockIdx.y, b = blockIdx.z;
    const int tid = threadIdx.x;

    for (int idx = tid; idx < 3072; idx += 256) {
        int px4 = idx & 7;
        int rowp = idx >> 3;
        int ch = rowp & 31;
        int rp = rowp >> 5;
        int row = rp % 6, plane = rp / 6;
        int grow = rg*4 + row - 1;
        float4 v = make_float4(0.f, 0.f, 0.f, 0.f);
        if ((unsigned)grow < 32u) {
            const float* gp = pin + ((size_t)b*1024 + ct*32 + ch + plane*512)*1024
                            + grow*32 + px4*4;
            v = *(const float4*)gp;
        }
        float* dst = (plane ? s2 : s1) + ch*216 + row*36 + px4*4;
        *(float4*)dst = v;
    }
    __syncthreads();

    const int wl = tid >> 5, lane = tid & 31;
    #pragma unroll
    for (int cc = 0; cc < 4; cc++) {
        int ch = wl*4 + cc;
        int cg = ct*32 + ch;
        float w1[9], w2[9];
        #pragma unroll
        for (int i = 0; i < 9; i++) { w1[i] = w[cg*9 + i]; w2[i] = w[(cg+512)*9 + i]; }
        const float* p1 = s1 + ch*216;
        const float* p2 = s2 + ch*216;
        #pragma unroll
        for (int r = 0; r < 4; r++) {
            float y1 = 0.f, y2 = 0.f;
            #pragma unroll
            for (int rr = 0; rr < 3; rr++) {
                const float* q1 = p1 + (r+rr)*36;
                const float* q2 = p2 + (r+rr)*36;
                #pragma unroll
                for (int dx = -1; dx <= 1; dx++) {
                    int px = lane + dx;
                    if ((unsigned)px < 32u) {
                        float wa = w1[rr*3 + dx + 1], wb = w2[rr*3 + dx + 1];
                        y1 += q1[px] * wa;
                        y2 += q2[px] * wb;
                    }
                }
            }
            float g = 0.5f * y1 * (1.f + erff(y1 * 0.70710678118654752f));
            t[(r*32 + lane)*33 + ch] = g * y2;
        }
    }
    __syncthreads();

    for (int idx = tid; idx < 1024; idx += 256) {
        int tok = idx >> 3, c4 = (idx & 7) * 4;
        const float* tp = &t[tok*33 + c4];
        float4 v; v.x = tp[0]; v.y = tp[1]; v.z = tp[2]; v.w = tp[3];
        *(float4*)(hidT + ((size_t)b*1024 + rg*128 + tok)*512 + ct*32 + c4) = v;
    }
}

// ============ FFT filter -> circular conv ============
__global__ void fft_g_kernel(const float* __restrict__ filt, float* __restrict__ g)
{
    const float ct[8] = {1.f, 0.70710678118654752f, 0.f, -0.70710678118654752f,
                         -1.f, -0.70710678118654752f, 0.f, 0.70710678118654752f};
    int c = blockIdx.x, t = threadIdx.x;
    int a = t >> 3, bb = t & 7;
    float s = 0.f;
    for (int k1 = 0; k1 < 8; k1++)
        for (int k2 = 0; k2 < 8; k2++) {
            float F = (k2 <= 4) ? filt[c*40 + k1*5 + k2]
                                : filt[c*40 + ((8-k1)&7)*5 + (8-k2)];
            s += F * ct[(k1*a + k2*bb) & 7];
        }
    g[c*64 + t] = s * (1.f/64.f);
}

__global__ void fft_apply_kernel(const float* __restrict__ y, const float* __restrict__ g,
                                 const float* __restrict__ xnew, float* __restrict__ out)
{
    __shared__ float ys[1024];
    __shared__ float gs[64];
    int bc = blockIdx.x, c = bc % 256;
    const float* yp = y + (size_t)bc * 1024;
    int tid = threadIdx.x;
    for (int i = tid; i < 1024; i += 256) ys[i] = yp[i];
    if (tid < 64) gs[tid] = g[c*64 + tid];
    __syncthreads();
    for (int i = tid; i < 1024; i += 256) {
        int u = i >> 5, v = i & 31;
        int bu = u & ~7, bv = v & ~7, uu = u & 7, vv = v & 7;
        float s = 0.f;
        #pragma unroll
        for (int a = 0; a < 8; a++) {
            const float* yr = &ys[(bu + a)*32 + bv];
            const float* gr = &gs[((uu - a) & 7) * 8];
            #pragma unroll
            for (int b2 = 0; b2 < 8; b2++)
                s += gr[(vv - b2) & 7] * yr[b2];
        }
        size_t oi = (size_t)bc * 1024 + i;
        out[oi] = xnew[oi] + s;
    }
}

// =========================================================================
extern "C" void kernel_launch(void* const* d_in, const int* in_sizes, int n_in,
                              void* d_out, int out_size)
{
    const float* x      = (const float*)d_in[0];
    const float* qkv_w  = (const float*)d_in[1];
    const float* qkv_s  = (const float*)d_in[2];
    const float* qkv_b  = (const float*)d_in[3];
    const float* pe_w   = (const float*)d_in[4];
    const float* pe_s   = (const float*)d_in[5];
    const float* pe_b   = (const float*)d_in[6];
    const float* proj_w = (const float*)d_in[7];
    const float* proj_s = (const float*)d_in[8];
    const float* proj_b = (const float*)d_in[9];
    const float* pin_w  = (const float*)d_in[10];
    const float* dw_w   = (const float*)d_in[11];
    const float* ff     = (const float*)d_in[12];
    const float* pout_w = (const float*)d_in[13];
    float* out = (float*)d_out;

    float *qkv, *qkT, *xT, *attoT, *xnew, *xnewT, *pin, *hidT, *yout, *gtab;
    cudaGetSymbolAddress((void**)&qkv,   g_qkv);
    cudaGetSymbolAddress((void**)&qkT,   g_qkT);
    cudaGetSymbolAddress((void**)&xT,    g_xT);
    cudaGetSymbolAddress((void**)&attoT, g_attoT);
    cudaGetSymbolAddress((void**)&xnew,  g_xnew);
    cudaGetSymbolAddress((void**)&xnewT, g_xnewT);
    cudaGetSymbolAddress((void**)&pin,   g_pin);
    cudaGetSymbolAddress((void**)&hidT,  g_hidT);
    cudaGetSymbolAddress((void**)&yout,  g_yout);
    cudaGetSymbolAddress((void**)&gtab,  g_g);

    cudaFuncSetAttribute(flash_kernel, cudaFuncAttributeMaxDynamicSharedMemorySize, FA_SMEM);
    cudaFuncSetAttribute(gemm_mma, cudaFuncAttributeMaxDynamicSharedMemorySize, GEMM_SMEM);
    cudaFuncSetAttribute(dwgate, cudaFuncAttributeMaxDynamicSharedMemorySize, DG_SMEM);
    dim3 tb(32, 8);

    // 1. xT = transpose(x)
    transpose_kernel<<<dim3(32, 8, 16), tb>>>(x, xT, 262144, 262144, 256, 1024);
    // 2. qkv gemm -> qkv cm + qkT token (mode 2)
    gemm_mma<<<dim3(8,4,16), 256, GEMM_SMEM>>>(qkv_w, 256, xT, 256, (size_t)262144,
        qkv, (size_t)524288, 256, qkv_s, qkv_b, nullptr, qkT, 2, 0);
    // 3. flash attention + PE -> attoT token-major (write-once)
    flash_kernel<<<dim3(8, 64), 256, FA_SMEM>>>(qkT, qkv, pe_w, pe_s, pe_b, attoT);
    // 4. proj gemm -> xnew cm (+x residual) + xnewT token (mode 1)
    gemm_mma<<<dim3(8,2,16), 256, GEMM_SMEM>>>(proj_w, 256, attoT, 256, (size_t)262144,
        xnew, (size_t)262144, 256, proj_s, proj_b, x, xnewT, 1, (size_t)262144);
    // 5. pin gemm -> pin cm
    gemm_mma<<<dim3(8,8,16), 256, GEMM_SMEM>>>(pin_w, 256, xnewT, 256, (size_t)262144,
        pin, (size_t)1048576, 256, nullptr, nullptr, nullptr, nullptr, 0, 0);
    // 6. fused dwconv + gate + transpose -> hidT
    dwgate<<<dim3(8, 16, 16), 256, DG_SMEM>>>(pin, dw_w, hidT);
    // 7. pout gemm -> yout cm
    gemm_mma<<<dim3(8,2,16), 256, GEMM_SMEM>>>(pout_w, 512, hidT, 512, (size_t)524288,
        yout, (size_t)262144, 512, nullptr, nullptr, nullptr, nullptr, 0, 0);
    // 8. fft
    fft_g_kernel<<<C_, 64>>>(ff, gtab);
    fft_apply_kernel<<<NB*C_, 256>>>(yout, gtab, xnew, out);
}

// round 10
// speedup vs baseline: 4.3116x; 1.0116x over previous
#include <cuda_runtime.h>
#include <math.h>
#include <stdint.h>

#define NB 16
#define C_ 256
#define N_ 1024
#define C2 1024
#define HID 512

__device__ float g_qkv  [(size_t)NB*512*1024];
__device__ float g_qkT  [(size_t)64*1024*64];
__device__ float g_xT   [(size_t)NB*1024*256];
__device__ float g_attoT[(size_t)NB*1024*256];
__device__ float g_xnew [(size_t)NB*256*1024];
__device__ float g_xnewT[(size_t)NB*1024*256];
__device__ float g_pin  [(size_t)NB*1024*1024];
__device__ float g_hidT [(size_t)NB*1024*512];
__device__ float g_yout [(size_t)NB*256*1024];
__device__ float g_g    [C_*64];

__device__ __forceinline__ uint32_t smem_u32(const void* p){
    uint32_t a;
    asm("{ .reg .u64 t; cvta.to.shared.u64 t, %1; cvt.u32.u64 %0, t; }" : "=r"(a) : "l"(p));
    return a;
}
__device__ __forceinline__ void cpasync16(uint32_t s, const void* g){
    asm volatile("cp.async.ca.shared.global [%0], [%1], 16;" :: "r"(s), "l"(g));
}
__device__ __forceinline__ void mma8(float* d, const uint32_t* a, uint32_t b0, uint32_t b1){
    asm volatile("mma.sync.aligned.m16n8k8.row.col.f32.tf32.tf32.f32 "
        "{%0,%1,%2,%3}, {%4,%5,%6,%7}, {%8,%9}, {%0,%1,%2,%3};"
        : "+f"(d[0]), "+f"(d[1]), "+f"(d[2]), "+f"(d[3])
        : "r"(a[0]), "r"(a[1]), "r"(a[2]), "r"(a[3]), "r"(b0), "r"(b1));
}

// ============ conv1x1 GEMM, cp.async 2-stage, optional token-major dual write
#define GEMM_SMEM 73728
__global__ void __launch_bounds__(256, 2) gemm_mma(
    const float* __restrict__ A, int lda,
    const float* __restrict__ B, int ldb, size_t bZs,
    float* __restrict__ O, size_t oZs, int K,
    const float* __restrict__ sc, const float* __restrict__ bi,
    const float* __restrict__ res,
    float* __restrict__ tokO, int tokMode, size_t tZs)
{
    extern __shared__ float smem[];
    const int tid = threadIdx.x, wid = tid >> 5, lane = tid & 31;
    const int m0 = blockIdx.y*128, n0 = blockIdx.x*128, z = blockIdx.z;
    const float* Bp = B + (size_t)z * bZs;
    const int wm = (wid & 3) * 32, wn = (wid >> 2) * 64;
    const int grp = lane >> 2, qid = lane & 3;
    const uint32_t sb = smem_u32(smem);

    float acc[2][8][4];
    #pragma unroll
    for (int mt = 0; mt < 2; mt++)
    #pragma unroll
        for (int nt = 0; nt < 8; nt++)
        #pragma unroll
            for (int r = 0; r < 4; r++) acc[mt][nt][r] = 0.f;

    const int nkc = K >> 5;
    auto issue = [&](int i, int st){
        int k0 = i << 5;
        uint32_t abase = sb + st*36864u;
        uint32_t bbase = abase + 18432u;
        #pragma unroll
        for (int idx = tid; idx < 1024; idx += 256) {
            int r = idx >> 3, c4 = (idx & 7) * 4;
            cpasync16(abase + (uint32_t)(r*36 + c4)*4u, A + (size_t)(m0+r)*lda + k0 + c4);
            cpasync16(bbase + (uint32_t)(r*36 + c4)*4u, Bp + (size_t)(n0+r)*ldb + k0 + c4);
        }
        asm volatile("cp.async.commit_group;" ::: "memory");
    };

    issue(0, 0);
    for (int i = 0; i < nkc; i++) {
        if (i + 1 < nkc) { issue(i+1, (i+1)&1); }
        if (i + 1 < nkc) asm volatile("cp.async.wait_group 1;" ::: "memory");
        else             asm volatile("cp.async.wait_group 0;" ::: "memory");
        __syncthreads();
        const uint32_t* As = (const uint32_t*)(smem + (i&1)*9216);
        const uint32_t* Bs = As + 4608;
        #pragma unroll
        for (int ks = 0; ks < 4; ks++) {
            int kk = ks * 8;
            uint32_t a[2][4];
            #pragma unroll
            for (int mt = 0; mt < 2; mt++) {
                int r = wm + mt*16 + grp;
                a[mt][0] = As[r*36 + kk + qid];
                a[mt][1] = As[(r+8)*36 + kk + qid];
                a[mt][2] = As[r*36 + kk + qid + 4];
                a[mt][3] = As[(r+8)*36 + kk + qid + 4];
            }
            #pragma unroll
            for (int nt = 0; nt < 8; nt++) {
                int n = wn + nt*8 + grp;
                uint32_t b0 = Bs[n*36 + kk + qid];
                uint32_t b1 = Bs[n*36 + kk + qid + 4];
                mma8(acc[0][nt], a[0], b0, b1);
                mma8(acc[1][nt], a[1], b0, b1);
            }
        }
        __syncthreads();
    }

    #pragma unroll
    for (int mt = 0; mt < 2; mt++) {
        #pragma unroll
        for (int half = 0; half < 2; half++) {
            int mg = m0 + wm + mt*16 + grp + half*8;
            float s1 = sc ? sc[mg] : 1.f;
            float b1 = sc ? bi[mg] : 0.f;
            const float* rb = res ? res + (size_t)z*oZs + (size_t)mg*1024 + n0 + wn : nullptr;
            #pragma unroll
            for (int nt = 0; nt < 8; nt++) {
                int c = nt*8 + 2*qid;
                float vx = acc[mt][nt][half*2]   * s1 + b1;
                float vy = acc[mt][nt][half*2+1] * s1 + b1;
                if (rb) { float2 rv = *(const float2*)(rb + c); vx += rv.x; vy += rv.y; }
                acc[mt][nt][half*2]   = vx;
                acc[mt][nt][half*2+1] = vy;
            }
        }
    }
    #pragma unroll
    for (int mt = 0; mt < 2; mt++) {
        #pragma unroll
        for (int half = 0; half < 2; half++) {
            int mg = m0 + wm + mt*16 + grp + half*8;
            float* ob = O + (size_t)z*oZs + (size_t)mg*1024 + n0 + wn;
            #pragma unroll
            for (int nt = 0; nt < 8; nt++) {
                int c = nt*8 + 2*qid;
                float2 v; v.x = acc[mt][nt][half*2]; v.y = acc[mt][nt][half*2+1];
                *(float2*)(ob + c) = v;
            }
        }
    }
    if (tokMode) {
        const int tS = (tokMode == 2) ? 68 : 132;
        float* Ts = smem;
        for (int nh = 0; nh < 2; nh++) {
            if ((wid >> 2) == nh && (tokMode == 1 || wm < 64)) {
                #pragma unroll
                for (int mt = 0; mt < 2; mt++)
                #pragma unroll
                    for (int hh = 0; hh < 2; hh++) {
                        int ml = wm + mt*16 + grp + hh*8;
                        #pragma unroll
                        for (int nt = 0; nt < 8; nt++) {
                            int r = nt*8 + 2*qid;
                            Ts[r*tS + ml]     = acc[mt][nt][hh*2];
                            Ts[(r+1)*tS + ml] = acc[mt][nt][hh*2+1];
                        }
                    }
            }
            __syncthreads();
            if (tokMode == 1) {
                float* dst = tokO + (size_t)z*tZs + (size_t)(n0 + nh*64)*256 + m0;
                #pragma unroll
                for (int idx = tid; idx < 2048; idx += 256) {
                    int r = idx >> 5, c4 = (idx & 31) * 4;
                    float4 v = *(float4*)&Ts[r*tS + c4];
                    *(float4*)(dst + (size_t)r*256 + c4) = v;
                }
            } else {
                float* dst = tokO + ((size_t)(z*4 + (m0 >> 7))*1024 + n0 + nh*64)*64;
                #pragma unroll
                for (int idx = tid; idx < 1024; idx += 256) {
                    int r = idx >> 4, c4 = (idx & 15) * 4;
                    float4 v = *(float4*)&Ts[r*tS + c4];
                    *(float4*)(dst + r*64 + c4) = v;
                }
            }
            __syncthreads();
        }
    }
}

// ============ 32x32 tiled transpose (input x only) ============
__global__ void transpose_kernel(const float* __restrict__ src, float* __restrict__ dst,
                                 size_t sStr, size_t dStr, int R, int C)
{
    __shared__ float t[32][33];
    const float* s = src + (size_t)blockIdx.z * sStr;
    float* d = dst + (size_t)blockIdx.z * dStr;
    int c0 = blockIdx.x*32, r0 = blockIdx.y*32;
    int tx = threadIdx.x, ty = threadIdx.y;
    #pragma unroll
    for (int k = 0; k < 32; k += 8)
        t[ty+k][tx] = s[(size_t)(r0+ty+k)*C + c0+tx];
    __syncthreads();
    #pragma unroll
    for (int k = 0; k < 32; k += 8)
        d[(size_t)(c0+ty+k)*R + r0+tx] = t[tx][ty+k];
}

// ============ flash attention v3: cp.async pipelined, raw tf32, fused PE ====
// smem: Qs[128][36] | Ks[128][36] | Vs[2][64][132]  = 104448 bytes
#define FA_SMEM 104448
__global__ void __launch_bounds__(256, 2) flash_kernel(
    const float* __restrict__ qkT, const float* __restrict__ qkv,
    const float* __restrict__ pe_w, const float* __restrict__ pe_s,
    const float* __restrict__ pe_b,
    float* __restrict__ attoT)
{
    extern __shared__ float sm[];
    const int tid = threadIdx.x, wid = tid >> 5, lane = tid & 31;
    const int grp = lane >> 2, qid = lane & 3;
    const int lanebase = lane & ~3, odd = qid & 1;
    const int src1 = lanebase + (qid >> 1), src2 = src1 + 2;
    const int m0 = blockIdx.x * 128, bh = blockIdx.y;
    const int b = bh >> 2, h = bh & 3;
    const int wq = wid * 16;
    const float* qbase = qkT + ((size_t)bh*1024 + m0)*64;
    const float* vbase = qkv + (size_t)b*524288 + (size_t)(h*128+64)*1024;
    const uint32_t sb = smem_u32(sm);
    const uint32_t koff = 4608u*4u, voff = 9216u*4u, vstr = 8448u*4u;

    // prologue: Q + K(0) + V(0), raw fp32 via cp.async
    {
        const float* kb0 = qkT + ((size_t)bh*1024)*64 + 32;
        #pragma unroll
        for (int idx = tid; idx < 1024; idx += 256) {
            int r = idx >> 3, c4 = (idx & 7) * 4;
            cpasync16(sb + (uint32_t)(r*36 + c4)*4u, qbase + r*64 + c4);
            cpasync16(sb + koff + (uint32_t)(r*36 + c4)*4u, kb0 + r*64 + c4);
        }
        #pragma unroll
        for (int idx = tid; idx < 2048; idx += 256) {
            int dd = idx >> 5, c4 = (idx & 31) * 4;
            cpasync16(sb + voff + (uint32_t)(dd*132 + c4)*4u, vbase + (size_t)dd*1024 + c4);
        }
        asm volatile("cp.async.commit_group;" ::: "memory");
    }

    float m_i[2] = {-1e30f, -1e30f};
    float l_i[2] = {0.f, 0.f};
    float ao[8][4];
    #pragma unroll
    for (int dt = 0; dt < 8; dt++) { ao[dt][0]=0; ao[dt][1]=0; ao[dt][2]=0; ao[dt][3]=0; }

    const uint32_t* Qu = (const uint32_t*)sm;
    const uint32_t* Ku = (const uint32_t*)(sm + 4608);
    const float scale = 0.17677669529663687f;

    for (int kc = 0; kc < 8; kc++) {
        asm volatile("cp.async.wait_group 0;" ::: "memory");
        __syncthreads();
        const uint32_t* Vu = (const uint32_t*)(sm + 9216 + (kc & 1)*8448);

        #pragma unroll
        for (int half = 0; half < 2; half++) {
            float sacc[8][4];
            #pragma unroll
            for (int nt = 0; nt < 8; nt++) { sacc[nt][0]=0; sacc[nt][1]=0; sacc[nt][2]=0; sacc[nt][3]=0; }
            #pragma unroll
            for (int ks = 0; ks < 4; ks++) {
                int kk = ks * 8;
                uint32_t a[4];
                a[0] = Qu[(wq+grp)*36 + kk + qid];
                a[1] = Qu[(wq+grp+8)*36 + kk + qid];
                a[2] = Qu[(wq+grp)*36 + kk + qid + 4];
                a[3] = Qu[(wq+grp+8)*36 + kk + qid + 4];
                #pragma unroll
                for (int nt = 0; nt < 8; nt++) {
                    int n = half*64 + nt*8 + grp;
                    uint32_t b0 = Ku[n*36 + kk + qid];
                    uint32_t b1 = Ku[n*36 + kk + qid + 4];
                    mma8(sacc[nt], a, b0, b1);
                }
            }
            // after the LAST K read of this chunk (half==1), prefetch next K+V
            if (half == 1) {
                __syncthreads();
                if (kc < 7) {
                    const float* kbn = qkT + ((size_t)bh*1024 + (kc+1)*128)*64 + 32;
                    const float* vbn = vbase + (kc+1)*128;
                    uint32_t vdst = sb + voff + (uint32_t)((kc+1)&1)*vstr;
                    #pragma unroll
                    for (int idx = tid; idx < 1024; idx += 256) {
                        int r = idx >> 3, c4 = (idx & 7) * 4;
                        cpasync16(sb + koff + (uint32_t)(r*36 + c4)*4u, kbn + r*64 + c4);
                    }
                    #pragma unroll
                    for (int idx = tid; idx < 2048; idx += 256) {
                        int dd = idx >> 5, c4 = (idx & 31) * 4;
                        cpasync16(vdst + (uint32_t)(dd*132 + c4)*4u, vbn + (size_t)dd*1024 + c4);
                    }
                    asm volatile("cp.async.commit_group;" ::: "memory");
                }
            }
            // scale + online softmax
            #pragma unroll
            for (int nt = 0; nt < 8; nt++) {
                sacc[nt][0] *= scale; sacc[nt][1] *= scale;
                sacc[nt][2] *= scale; sacc[nt][3] *= scale;
            }
            float mx0 = -1e30f, mx1 = -1e30f;
            #pragma unroll
            for (int nt = 0; nt < 8; nt++) {
                mx0 = fmaxf(mx0, fmaxf(sacc[nt][0], sacc[nt][1]));
                mx1 = fmaxf(mx1, fmaxf(sacc[nt][2], sacc[nt][3]));
            }
            mx0 = fmaxf(mx0, __shfl_xor_sync(0xffffffffu, mx0, 1));
            mx0 = fmaxf(mx0, __shfl_xor_sync(0xffffffffu, mx0, 2));
            mx1 = fmaxf(mx1, __shfl_xor_sync(0xffffffffu, mx1, 1));
            mx1 = fmaxf(mx1, __shfl_xor_sync(0xffffffffu, mx1, 2));
            float mn0 = fmaxf(m_i[0], mx0), mn1 = fmaxf(m_i[1], mx1);
            float s0 = 0.f, s1 = 0.f;
            #pragma unroll
            for (int nt = 0; nt < 8; nt++) {
                sacc[nt][0] = __expf(sacc[nt][0] - mn0);
                sacc[nt][1] = __expf(sacc[nt][1] - mn0);
                sacc[nt][2] = __expf(sacc[nt][2] - mn1);
                sacc[nt][3] = __expf(sacc[nt][3] - mn1);
                s0 += sacc[nt][0] + sacc[nt][1];
                s1 += sacc[nt][2] + sacc[nt][3];
            }
            s0 += __shfl_xor_sync(0xffffffffu, s0, 1);
            s0 += __shfl_xor_sync(0xffffffffu, s0, 2);
            s1 += __shfl_xor_sync(0xffffffffu, s1, 1);
            s1 += __shfl_xor_sync(0xffffffffu, s1, 2);
            float al0 = __expf(m_i[0] - mn0), al1 = __expf(m_i[1] - mn1);
            l_i[0] = l_i[0]*al0 + s0; l_i[1] = l_i[1]*al1 + s1;
            m_i[0] = mn0; m_i[1] = mn1;
            #pragma unroll
            for (int dt = 0; dt < 8; dt++) {
                ao[dt][0] *= al0; ao[dt][1] *= al0;
                ao[dt][2] *= al1; ao[dt][3] *= al1;
            }
            // PV with in-register P fragment conversion (quad butterfly)
            #pragma unroll
            for (int ks2 = 0; ks2 < 8; ks2++) {
                float p00 = __shfl_sync(0xffffffffu, sacc[ks2][0], src1);
                float p01 = __shfl_sync(0xffffffffu, sacc[ks2][1], src1);
                float p10 = __shfl_sync(0xffffffffu, sacc[ks2][2], src1);
                float p11 = __shfl_sync(0xffffffffu, sacc[ks2][3], src1);
                float q00 = __shfl_sync(0xffffffffu, sacc[ks2][0], src2);
                float q01 = __shfl_sync(0xffffffffu, sacc[ks2][1], src2);
                float q10 = __shfl_sync(0xffffffffu, sacc[ks2][2], src2);
                float q11 = __shfl_sync(0xffffffffu, sacc[ks2][3], src2);
                uint32_t a[4];
                a[0] = __float_as_uint(odd ? p01 : p00);
                a[1] = __float_as_uint(odd ? p11 : p10);
                a[2] = __float_as_uint(odd ? q01 : q00);
                a[3] = __float_as_uint(odd ? q11 : q10);
                int kk = half*64 + ks2*8;
                #pragma unroll
                for (int dt = 0; dt < 8; dt++) {
                    uint32_t b0 = Vu[(dt*8+grp)*132 + kk + qid];
                    uint32_t b1 = Vu[(dt*8+grp)*132 + kk + qid + 4];
                    mma8(ao[dt], a, b0, b1);
                }
            }
        }
    }
    __syncthreads();

    // ---- PE slab: V rows (m0/32 -1 .. +4), 64 channels, padded [64][216] ----
    float* slab = sm;
    const int r0 = m0 >> 5;
    for (int idx = tid; idx < 3072; idx += 256) {
        int c4 = idx & 7;
        int t6 = idx >> 3;
        int srow = t6 % 6, ch = t6 / 6;
        int grow = r0 + srow - 1;
        float4 v = make_float4(0.f, 0.f, 0.f, 0.f);
        if ((unsigned)grow < 32u)
            v = *(const float4*)(vbase + (size_t)ch*1024 + grow*32 + c4*4);
        *(float4*)(slab + ch*216 + srow*36 + c4*4) = v;
    }
    __syncthreads();

    // ---- epilogue: normalize + PE add + token-major store ----
    float inv0 = 1.f / l_i[0], inv1 = 1.f / l_i[1];
    const int tl0 = wq + grp, tl1 = tl0 + 8;
    const int col0 = tl0 & 31, rl0 = tl0 >> 5;
    const int col1 = tl1 & 31, rl1 = tl1 >> 5;
    float* ob0 = attoT + ((size_t)(b*1024 + m0 + tl0))*256 + h*64;
    float* ob1 = attoT + ((size_t)(b*1024 + m0 + tl1))*256 + h*64;
    #pragma unroll
    for (int dt = 0; dt < 8; dt++) {
        int d0 = dt*8 + 2*qid;
        float pe[2][2];
        #pragma unroll
        for (int e = 0; e < 2; e++) {
            int ch = d0 + e, cg = h*64 + ch;
            const float* wp = pe_w + cg*9;
            float w9[9];
            #pragma unroll
            for (int i = 0; i < 9; i++) w9[i] = wp[i];
            float ss = pe_s[cg], bb2 = pe_b[cg];
            const float* sl = slab + ch*216;
            #pragma unroll
            for (int tk = 0; tk < 2; tk++) {
                int col = tk ? col1 : col0;
                int rl  = tk ? rl1  : rl0;
                float acc2 = 0.f;
                #pragma unroll
                for (int rr = 0; rr < 3; rr++) {
                    const float* q = sl + (rl + rr)*36;
                    #pragma unroll
                    for (int dx = -1; dx <= 1; dx++) {
                        int cx = col + dx;
                        if ((unsigned)cx < 32u) acc2 += q[cx] * w9[rr*3 + dx + 1];
                    }
                }
                pe[e][tk] = acc2 * ss + bb2;
            }
        }
        float2 v0, v1;
        v0.x = ao[dt][0]*inv0 + pe[0][0];
        v0.y = ao[dt][1]*inv0 + pe[1][0];
        v1.x = ao[dt][2]*inv1 + pe[0][1];
        v1.y = ao[dt][3]*inv1 + pe[1][1];
        *(float2*)(ob0 + d0) = v0;
        *(float2*)(ob1 + d0) = v1;
    }
}

// ============ fused dwconv3x3 + GELU-gate + transpose ============
#define DG_SMEM 72192
__global__ void __launch_bounds__(256) dwgate(
    const float* __restrict__ pin, const float* __restrict__ w,
    float* __restrict__ hidT)
{
    extern __shared__ float sm[];
    float* s1 = sm;
    float* s2 = sm + 6912;
    float* t  = sm + 13824;
    const int rg = blockIdx.x, ct = blockIdx.y, b = blockIdx.z;
    const int tid = threadIdx.x;

    for (int idx = tid; idx < 3072; idx += 256) {
        int px4 = idx & 7;
        int rowp = idx >> 3;
        int ch = rowp & 31;
        int rp = rowp >> 5;
        int row = rp % 6, plane = rp / 6;
        int grow = rg*4 + row - 1;
        float4 v = make_float4(0.f, 0.f, 0.f, 0.f);
        if ((unsigned)grow < 32u) {
            const float* gp = pin + ((size_t)b*1024 + ct*32 + ch + plane*512)*1024
                            + grow*32 + px4*4;
            v = *(const float4*)gp;
        }
        float* dst = (plane ? s2 : s1) + ch*216 + row*36 + px4*4;
        *(float4*)dst = v;
    }
    __syncthreads();

    const int wl = tid >> 5, lane = tid & 31;
    #pragma unroll
    for (int cc = 0; cc < 4; cc++) {
        int ch = wl*4 + cc;
        int cg = ct*32 + ch;
        float w1[9], w2[9];
        #pragma unroll
        for (int i = 0; i < 9; i++) { w1[i] = w[cg*9 + i]; w2[i] = w[(cg+512)*9 + i]; }
        const float* p1 = s1 + ch*216;
        const float* p2 = s2 + ch*216;
        #pragma unroll
        for (int r = 0; r < 4; r++) {
            float y1 = 0.f, y2 = 0.f;
            #pragma unroll
            for (int rr = 0; rr < 3; rr++) {
                const float* q1 = p1 + (r+rr)*36;
                const float* q2 = p2 + (r+rr)*36;
                #pragma unroll
                for (int dx = -1; dx <= 1; dx++) {
                    int px = lane + dx;
                    if ((unsigned)px < 32u) {
                        float wa = w1[rr*3 + dx + 1], wb = w2[rr*3 + dx + 1];
                        y1 += q1[px] * wa;
                        y2 += q2[px] * wb;
                    }
                }
            }
            float g = 0.5f * y1 * (1.f + erff(y1 * 0.70710678118654752f));
            t[(r*32 + lane)*33 + ch] = g * y2;
        }
    }
    __syncthreads();

    for (int idx = tid; idx < 1024; idx += 256) {
        int tok = idx >> 3, c4 = (idx & 7) * 4;
        const float* tp = &t[tok*33 + c4];
        float4 v; v.x = tp[0]; v.y = tp[1]; v.z = tp[2]; v.w = tp[3];
        *(float4*)(hidT + ((size_t)b*1024 + rg*128 + tok)*512 + ct*32 + c4) = v;
    }
}

// ============ FFT filter -> circular conv ============
__global__ void fft_g_kernel(const float* __restrict__ filt, float* __restrict__ g)
{
    const float ct[8] = {1.f, 0.70710678118654752f, 0.f, -0.70710678118654752f,
                         -1.f, -0.70710678118654752f, 0.f, 0.70710678118654752f};
    int c = blockIdx.x, t = threadIdx.x;
    int a = t >> 3, bb = t & 7;
    float s = 0.f;
    for (int k1 = 0; k1 < 8; k1++)
        for (int k2 = 0; k2 < 8; k2++) {
            float F = (k2 <= 4) ? filt[c*40 + k1*5 + k2]
                                : filt[c*40 + ((8-k1)&7)*5 + (8-k2)];
            s += F * ct[(k1*a + k2*bb) & 7];
        }
    g[c*64 + t] = s * (1.f/64.f);
}

__global__ void fft_apply_kernel(const float* __restrict__ y, const float* __restrict__ g,
                                 const float* __restrict__ xnew, float* __restrict__ out)
{
    __shared__ float ys[1024];
    __shared__ float gs[64];
    int bc = blockIdx.x, c = bc % 256;
    const float* yp = y + (size_t)bc * 1024;
    int tid = threadIdx.x;
    for (int i = tid; i < 1024; i += 256) ys[i] = yp[i];
    if (tid < 64) gs[tid] = g[c*64 + tid];
    __syncthreads();
    for (int i = tid; i < 1024; i += 256) {
        int u = i >> 5, v = i & 31;
        int bu = u & ~7, bv = v & ~7, uu = u & 7, vv = v & 7;
        float s = 0.f;
        #pragma unroll
        for (int a = 0; a < 8; a++) {
            const float* yr = &ys[(bu + a)*32 + bv];
            const float* gr = &gs[((uu - a) & 7) * 8];
            #pragma unroll
            for (int b2 = 0; b2 < 8; b2++)
                s += gr[(vv - b2) & 7] * yr[b2];
        }
        size_t oi = (size_t)bc * 1024 + i;
        out[oi] = xnew[oi] + s;
    }
}

// =========================================================================
extern "C" void kernel_launch(void* const* d_in, const int* in_sizes, int n_in,
                              void* d_out, int out_size)
{
    const float* x      = (const float*)d_in[0];
    const float* qkv_w  = (const float*)d_in[1];
    const float* qkv_s  = (const float*)d_in[2];
    const float* qkv_b  = (const float*)d_in[3];
    const float* pe_w   = (const float*)d_in[4];
    const float* pe_s   = (const float*)d_in[5];
    const float* pe_b   = (const float*)d_in[6];
    const float* proj_w = (const float*)d_in[7];
    const float* proj_s = (const float*)d_in[8];
    const float* proj_b = (const float*)d_in[9];
    const float* pin_w  = (const float*)d_in[10];
    const float* dw_w   = (const float*)d_in[11];
    const float* ff     = (const float*)d_in[12];
    const float* pout_w = (const float*)d_in[13];
    float* out = (float*)d_out;

    float *qkv, *qkT, *xT, *attoT, *xnew, *xnewT, *pin, *hidT, *yout, *gtab;
    cudaGetSymbolAddress((void**)&qkv,   g_qkv);
    cudaGetSymbolAddress((void**)&qkT,   g_qkT);
    cudaGetSymbolAddress((void**)&xT,    g_xT);
    cudaGetSymbolAddress((void**)&attoT, g_attoT);
    cudaGetSymbolAddress((void**)&xnew,  g_xnew);
    cudaGetSymbolAddress((void**)&xnewT, g_xnewT);
    cudaGetSymbolAddress((void**)&pin,   g_pin);
    cudaGetSymbolAddress((void**)&hidT,  g_hidT);
    cudaGetSymbolAddress((void**)&yout,  g_yout);
    cudaGetSymbolAddress((void**)&gtab,  g_g);

    cudaFuncSetAttribute(flash_kernel, cudaFuncAttributeMaxDynamicSharedMemorySize, FA_SMEM);
    cudaFuncSetAttribute(gemm_mma, cudaFuncAttributeMaxDynamicSharedMemorySize, GEMM_SMEM);
    cudaFuncSetAttribute(dwgate, cudaFuncAttributeMaxDynamicSharedMemorySize, DG_SMEM);
    dim3 tb(32, 8);

    // 1. xT = transpose(x)
    transpose_kernel<<<dim3(32, 8, 16), tb>>>(x, xT, 262144, 262144, 256, 1024);
    // 2. qkv gemm -> qkv cm + qkT token (mode 2)
    gemm_mma<<<dim3(8,4,16), 256, GEMM_SMEM>>>(qkv_w, 256, xT, 256, (size_t)262144,
        qkv, (size_t)524288, 256, qkv_s, qkv_b, nullptr, qkT, 2, 0);
    // 3. flash attention + PE -> attoT token-major (write-once)
    flash_kernel<<<dim3(8, 64), 256, FA_SMEM>>>(qkT, qkv, pe_w, pe_s, pe_b, attoT);
    // 4. proj gemm -> xnew cm (+x residual) + xnewT token (mode 1)
    gemm_mma<<<dim3(8,2,16), 256, GEMM_SMEM>>>(proj_w, 256, attoT, 256, (size_t)262144,
        xnew, (size_t)262144, 256, proj_s, proj_b, x, xnewT, 1, (size_t)262144);
    // 5. pin gemm -> pin cm
    gemm_mma<<<dim3(8,8,16), 256, GEMM_SMEM>>>(pin_w, 256, xnewT, 256, (size_t)262144,
        pin, (size_t)1048576, 256, nullptr, nullptr, nullptr, nullptr, 0, 0);
    // 6. fused dwconv + gate + transpose -> hidT
    dwgate<<<dim3(8, 16, 16), 256, DG_SMEM>>>(pin, dw_w, hidT);
    // 7. pout gemm -> yout cm
    gemm_mma<<<dim3(8,2,16), 256, GEMM_SMEM>>>(pout_w, 512, hidT, 512, (size_t)524288,
        yout, (size_t)262144, 512, nullptr, nullptr, nullptr, nullptr, 0, 0);
    // 8. fft
    fft_g_kernel<<<C_, 64>>>(ff, gtab);
    fft_apply_kernel<<<NB*C_, 256>>>(yout, gtab, xnew, out);
}